// round 1
// baseline (speedup 1.0000x reference)
#include <cuda_runtime.h>
#include <cstdint>
#include <cstddef>

#define BB 32
#define NN 1024
#define MM 256
#define DD 512

// -------------------- device scratch (no allocations allowed) --------------------
__device__ float g_S [(size_t)BB * NN * MM];   // raw logits
__device__ float g_A [(size_t)BB * NN * MM];   // row softmax (over m, q-masked)
__device__ float g_Bm[(size_t)BB * NN * MM];   // col softmax (over n, c-masked)
__device__ float g_mid[(size_t)BB * MM * DD];  // Bm^T @ context
__device__ float g_cw[BB * NN];
__device__ float g_qw[BB * MM];
__device__ int   g_clen[BB];
__device__ int   g_qlen[BB];

// -------------------- mask length detection --------------------
// masks are prefix masks (arange < len) with len >= length//4.
// storage dtype unknown; detect by exact value signature.
__device__ __forceinline__ int count_prefix(const unsigned char* p, int length,
                                            int esize, unsigned val) {
    int c = 0;
    for (int i = 0; i < length; i++) {
        unsigned v;
        if (esize == 1)      v = p[i];
        else if (esize == 2) v = ((const unsigned short*)p)[i];
        else                 v = ((const unsigned*)p)[i];
        if (v != val) break;
        c++;
    }
    return c;
}

__device__ void detect_fmt(const unsigned char* p, int length, int minlen,
                           int* esize, unsigned* val) {
    const int es[4]      = {1, 2, 4, 4};
    const unsigned vv[4] = {1u, 0x3F80u, 1u, 0x3F800000u};  // u8/bool, bf16 1.0, i32 1, f32 1.0
    for (int k = 0; k < 4; k++) {
        if (count_prefix(p, length, es[k], vv[k]) >= minlen) {
            *esize = es[k]; *val = vv[k]; return;
        }
    }
    *esize = 4; *val = 1u;  // fallback: int32
}

__global__ void k_lens(const unsigned char* __restrict__ cm,
                       const unsigned char* __restrict__ qm) {
    __shared__ int es_c, es_q;
    __shared__ unsigned v_c, v_q;
    int t = threadIdx.x;
    if (t == 0) detect_fmt(cm, NN, NN / 4, &es_c, &v_c);
    if (t == 1) detect_fmt(qm, MM, MM / 4, &es_q, &v_q);
    __syncthreads();
    if (t < BB) {
        g_clen[t] = count_prefix(cm + (size_t)t * NN * es_c, NN, es_c, v_c);
    } else if (t < 2 * BB) {
        int b = t - BB;
        g_qlen[b] = count_prefix(qm + (size_t)b * MM * es_q, MM, es_q, v_q);
    }
}

// -------------------- cw = ctx @ w_c, qw = query @ w_q --------------------
__global__ void __launch_bounds__(256) k_rowdots(const float* __restrict__ ctx,
                                                 const float* __restrict__ qry,
                                                 const float* __restrict__ w) {
    int warp = threadIdx.x >> 5, lane = threadIdx.x & 31;
    int row = blockIdx.x * 8 + warp;
    const float* src; const float* wp; float* dst;
    if (row < BB * NN) {
        src = ctx + (size_t)row * DD; wp = w + DD;  // w_c = w[D:2D]
        dst = g_cw + row;
    } else {
        int r = row - BB * NN;
        src = qry + (size_t)r * DD; wp = w;          // w_q = w[0:D]
        dst = g_qw + r;
    }
    float s = 0.f;
    #pragma unroll
    for (int d = lane * 4; d < DD; d += 128) {
        float4 v  = *(const float4*)(src + d);
        float4 wv = *(const float4*)(wp + d);
        s += v.x * wv.x + v.y * wv.y + v.z * wv.z + v.w * wv.w;
    }
    #pragma unroll
    for (int o = 16; o; o >>= 1) s += __shfl_xor_sync(0xFFFFFFFFu, s, o);
    if (lane == 0) *dst = s;
}

// -------------------- S GEMM (NT) + row softmax fused --------------------
// block: 64 rows (n) x full M=256 cols. 256 threads: ty in [0,8) owns 8 rows,
// tx in [0,32) owns 8 cols. Warp == one ty => row reductions are warp shuffles.
#define S_BK 16
__global__ void __launch_bounds__(256) k_S(const float* __restrict__ ctx,
                                           const float* __restrict__ qry,
                                           const float* __restrict__ w) {
    __shared__ float As[S_BK][64];     // (ctx * w_m) transposed [k][n]
    __shared__ float Bs[S_BK][MM];     // query transposed       [k][m]
    __shared__ float wm[DD];
    __shared__ float cw_s[64];
    __shared__ float qw_s[MM];

    int b  = blockIdx.y;
    int n0 = blockIdx.x * 64;
    int tid = threadIdx.x;
    int tx = tid & 31, ty = tid >> 5;

    for (int i = tid; i < DD; i += 256) wm[i] = w[2 * DD + i];
    if (tid < 64) cw_s[tid] = g_cw[b * NN + n0 + tid];
    qw_s[tid] = g_qw[b * MM + tid];
    __syncthreads();

    const float* ctxb = ctx + ((size_t)b * NN + n0) * DD;
    const float* qryb = qry + (size_t)b * MM * DD;

    float acc[8][8];
    #pragma unroll
    for (int i = 0; i < 8; i++)
        #pragma unroll
        for (int j = 0; j < 8; j++) acc[i][j] = 0.f;

    for (int k0 = 0; k0 < DD; k0 += S_BK) {
        {   // As: 64 x 16 = 256 float4
            int r = tid >> 2, kq = (tid & 3) * 4;
            float4 v = *(const float4*)(ctxb + (size_t)r * DD + k0 + kq);
            As[kq + 0][r] = v.x * wm[k0 + kq + 0];
            As[kq + 1][r] = v.y * wm[k0 + kq + 1];
            As[kq + 2][r] = v.z * wm[k0 + kq + 2];
            As[kq + 3][r] = v.w * wm[k0 + kq + 3];
        }
        #pragma unroll
        for (int it = 0; it < 4; it++) {  // Bs: 256 x 16 = 1024 float4
            int idx = tid + 256 * it;
            int r = idx >> 2, kq = (idx & 3) * 4;
            float4 v = *(const float4*)(qryb + (size_t)r * DD + k0 + kq);
            Bs[kq + 0][r] = v.x; Bs[kq + 1][r] = v.y;
            Bs[kq + 2][r] = v.z; Bs[kq + 3][r] = v.w;
        }
        __syncthreads();
        #pragma unroll
        for (int k = 0; k < S_BK; k++) {
            float4 a0 = *(float4*)&As[k][ty * 8];
            float4 a1 = *(float4*)&As[k][ty * 8 + 4];
            float4 b0 = *(float4*)&Bs[k][tx * 8];
            float4 b1 = *(float4*)&Bs[k][tx * 8 + 4];
            float a[8] = {a0.x, a0.y, a0.z, a0.w, a1.x, a1.y, a1.z, a1.w};
            float bb[8] = {b0.x, b0.y, b0.z, b0.w, b1.x, b1.y, b1.z, b1.w};
            #pragma unroll
            for (int i = 0; i < 8; i++)
                #pragma unroll
                for (int j = 0; j < 8; j++) acc[i][j] += a[i] * bb[j];
        }
        __syncthreads();
    }

    int qlen = g_qlen[b];
    #pragma unroll
    for (int i = 0; i < 8; i++) {
        int row = ty * 8 + i;
        float cwv = cw_s[row];
        float s[8];
        #pragma unroll
        for (int j = 0; j < 8; j++) s[j] = acc[i][j] + cwv + qw_s[tx * 8 + j];

        float* Srow = g_S + ((size_t)(b * NN + n0 + row)) * MM + tx * 8;
        *(float4*)Srow       = make_float4(s[0], s[1], s[2], s[3]);
        *(float4*)(Srow + 4) = make_float4(s[4], s[5], s[6], s[7]);

        // row softmax over m (mask m >= qlen -> exactly 0, matches -1e9 underflow)
        float mx = -1e30f;
        #pragma unroll
        for (int j = 0; j < 8; j++)
            if (tx * 8 + j < qlen) mx = fmaxf(mx, s[j]);
        #pragma unroll
        for (int o = 16; o; o >>= 1) mx = fmaxf(mx, __shfl_xor_sync(0xFFFFFFFFu, mx, o));

        float e[8]; float sum = 0.f;
        #pragma unroll
        for (int j = 0; j < 8; j++) {
            e[j] = (tx * 8 + j < qlen) ? __expf(s[j] - mx) : 0.f;
            sum += e[j];
        }
        #pragma unroll
        for (int o = 16; o; o >>= 1) sum += __shfl_xor_sync(0xFFFFFFFFu, sum, o);
        float inv = 1.f / sum;

        float* Arow = g_A + ((size_t)(b * NN + n0 + row)) * MM + tx * 8;
        *(float4*)Arow       = make_float4(e[0] * inv, e[1] * inv, e[2] * inv, e[3] * inv);
        *(float4*)(Arow + 4) = make_float4(e[4] * inv, e[5] * inv, e[6] * inv, e[7] * inv);
    }
}

// -------------------- Bm: column softmax over n (c-masked) --------------------
// block: (b, 64-column tile). 256 threads = 64 cols x 4 n-partials, online softmax.
__global__ void __launch_bounds__(256) k_bm() {
    int b  = blockIdx.y;
    int m0 = blockIdx.x * 64;
    int c  = threadIdx.x & 63;
    int p  = threadIdx.x >> 6;
    int m  = m0 + c;
    int clen = g_clen[b];

    const float* Scol = g_S + (size_t)b * NN * MM + m;
    float mx = -1e30f, sum = 0.f;
    for (int n = p; n < clen; n += 4) {
        float s = Scol[(size_t)n * MM];
        if (s > mx) { sum *= __expf(mx - s); mx = s; }
        sum += __expf(s - mx);
    }
    __shared__ float smx[4][64], ssum[4][64];
    smx[p][c] = mx; ssum[p][c] = sum;
    __syncthreads();
    float fm = -1e30f;
    #pragma unroll
    for (int q = 0; q < 4; q++) fm = fmaxf(fm, smx[q][c]);
    float fs = 0.f;
    #pragma unroll
    for (int q = 0; q < 4; q++) fs += ssum[q][c] * __expf(smx[q][c] - fm);
    float inv = 1.f / fs;

    float* Bcol = g_Bm + (size_t)b * NN * MM + m;
    for (int n = p; n < NN; n += 4) {
        float v = 0.f;
        if (n < clen) v = __expf(Scol[(size_t)n * MM] - fm) * inv;
        Bcol[(size_t)n * MM] = v;
    }
}

// -------------------- mid = Bm^T @ ctx  (M x D, K = N) --------------------
__global__ void __launch_bounds__(256) k_mid(const float* __restrict__ ctx) {
    __shared__ float Bs[16][64];  // Bm [k=n][m]
    __shared__ float Cs[16][64];  // ctx [k=n][d]
    int b  = blockIdx.z;
    int m0 = blockIdx.x * 64, d0 = blockIdx.y * 64;
    int tid = threadIdx.x;
    int tx = tid & 15, tyy = tid >> 4;

    const float* Bmb  = g_Bm + (size_t)b * NN * MM;
    const float* ctxb = ctx  + (size_t)b * NN * DD;

    float acc[4][4];
    #pragma unroll
    for (int i = 0; i < 4; i++)
        #pragma unroll
        for (int j = 0; j < 4; j++) acc[i][j] = 0.f;

    int lk = tid >> 4, lq = (tid & 15) * 4;
    for (int n0 = 0; n0 < NN; n0 += 16) {
        *(float4*)&Bs[lk][lq] = *(const float4*)(Bmb  + (size_t)(n0 + lk) * MM + m0 + lq);
        *(float4*)&Cs[lk][lq] = *(const float4*)(ctxb + (size_t)(n0 + lk) * DD + d0 + lq);
        __syncthreads();
        #pragma unroll
        for (int k = 0; k < 16; k++) {
            float4 a = *(float4*)&Bs[k][tyy * 4];
            float4 c = *(float4*)&Cs[k][tx * 4];
            float av[4] = {a.x, a.y, a.z, a.w};
            float cv[4] = {c.x, c.y, c.z, c.w};
            #pragma unroll
            for (int i = 0; i < 4; i++)
                #pragma unroll
                for (int j = 0; j < 4; j++) acc[i][j] += av[i] * cv[j];
        }
        __syncthreads();
    }
    #pragma unroll
    for (int i = 0; i < 4; i++) {
        float* row = g_mid + ((size_t)b * MM + m0 + tyy * 4 + i) * DD + d0 + tx * 4;
        *(float4*)row = make_float4(acc[i][0], acc[i][1], acc[i][2], acc[i][3]);
    }
}

// -------------------- c2q = A@query, q2c = A@mid, fused + output epilogue -------
__global__ void __launch_bounds__(256) k_out(const float* __restrict__ ctx,
                                             const float* __restrict__ qry,
                                             float* __restrict__ out) {
    __shared__ float As [16][64];  // A transposed [k=m][n]
    __shared__ float Bq [16][64];  // query [k=m][d]
    __shared__ float Bmi[16][64];  // mid   [k=m][d]

    int b  = blockIdx.z;
    int n0 = blockIdx.x * 64, d0 = blockIdx.y * 64;
    int tid = threadIdx.x;
    int tx = tid & 15, tyy = tid >> 4;

    const float* Ab   = g_A   + (size_t)b * NN * MM;
    const float* qryb = qry   + (size_t)b * MM * DD;
    const float* midb = g_mid + (size_t)b * MM * DD;

    float accq[4][4], accm[4][4];
    #pragma unroll
    for (int i = 0; i < 4; i++)
        #pragma unroll
        for (int j = 0; j < 4; j++) { accq[i][j] = 0.f; accm[i][j] = 0.f; }

    for (int k0 = 0; k0 < MM; k0 += 16) {
        {   // A tile: 64 n-rows x 16 m, transpose to [k][n]
            int r = tid >> 2, kq = (tid & 3) * 4;
            float4 v = *(const float4*)(Ab + (size_t)(n0 + r) * MM + k0 + kq);
            As[kq + 0][r] = v.x; As[kq + 1][r] = v.y;
            As[kq + 2][r] = v.z; As[kq + 3][r] = v.w;
        }
        {   // query + mid tiles: 16 x 64, direct [k][d]
            int lk = tid >> 4, lq = (tid & 15) * 4;
            *(float4*)&Bq [lk][lq] = *(const float4*)(qryb + (size_t)(k0 + lk) * DD + d0 + lq);
            *(float4*)&Bmi[lk][lq] = *(const float4*)(midb + (size_t)(k0 + lk) * DD + d0 + lq);
        }
        __syncthreads();
        #pragma unroll
        for (int k = 0; k < 16; k++) {
            float4 a = *(float4*)&As [k][tyy * 4];
            float4 q = *(float4*)&Bq [k][tx * 4];
            float4 m = *(float4*)&Bmi[k][tx * 4];
            float av[4] = {a.x, a.y, a.z, a.w};
            float qv[4] = {q.x, q.y, q.z, q.w};
            float mv[4] = {m.x, m.y, m.z, m.w};
            #pragma unroll
            for (int i = 0; i < 4; i++)
                #pragma unroll
                for (int j = 0; j < 4; j++) {
                    accq[i][j] += av[i] * qv[j];
                    accm[i][j] += av[i] * mv[j];
                }
        }
        __syncthreads();
    }

    // epilogue: out = [ctx, c2q, ctx*c2q, ctx*q2c]
    #pragma unroll
    for (int i = 0; i < 4; i++) {
        int n = n0 + tyy * 4 + i;
        int d = d0 + tx * 4;
        float4 cv = *(const float4*)(ctx + ((size_t)b * NN + n) * DD + d);
        float4 c2q = make_float4(accq[i][0], accq[i][1], accq[i][2], accq[i][3]);
        float4 q2c = make_float4(accm[i][0], accm[i][1], accm[i][2], accm[i][3]);
        size_t obase = ((size_t)b * NN + n) * (4 * DD);
        *(float4*)(out + obase + d)          = cv;
        *(float4*)(out + obase + DD + d)     = c2q;
        *(float4*)(out + obase + 2 * DD + d) = make_float4(cv.x * c2q.x, cv.y * c2q.y,
                                                           cv.z * c2q.z, cv.w * c2q.w);
        *(float4*)(out + obase + 3 * DD + d) = make_float4(cv.x * q2c.x, cv.y * q2c.y,
                                                           cv.z * q2c.z, cv.w * q2c.w);
    }
}

// -------------------- launch --------------------
extern "C" void kernel_launch(void* const* d_in, const int* in_sizes, int n_in,
                              void* d_out, int out_size) {
    const float* ctx = (const float*)d_in[0];
    const float* qry = (const float*)d_in[1];
    const unsigned char* cm = (const unsigned char*)d_in[2];
    const unsigned char* qm = (const unsigned char*)d_in[3];
    const float* w = (const float*)d_in[4];
    float* out = (float*)d_out;

    k_lens<<<1, 64>>>(cm, qm);
    k_rowdots<<<(BB * NN + BB * MM) / 8, 256>>>(ctx, qry, w);
    k_S<<<dim3(NN / 64, BB), 256>>>(ctx, qry, w);
    k_bm<<<dim3(MM / 64, BB), 256>>>();
    k_mid<<<dim3(MM / 64, DD / 64, BB), 256>>>(ctx);
    k_out<<<dim3(NN / 64, DD / 64, BB), 256>>>(ctx, qry, out);
}

// round 2
// speedup vs baseline: 2.0252x; 2.0252x over previous
#include <cuda_runtime.h>
#include <cstdint>
#include <cstddef>

#define BB 32
#define NN 1024
#define MM 256
#define DD 512

// -------------------- device scratch --------------------
__device__ float g_S [(size_t)BB * NN * MM];
__device__ float g_A [(size_t)BB * NN * MM];
__device__ float g_Bm[(size_t)BB * NN * MM];
__device__ float g_mid[(size_t)BB * MM * DD];
__device__ float g_cw[BB * NN];
__device__ float g_qw[BB * MM];
__device__ int   g_clen[BB];
__device__ int   g_qlen[BB];

// -------------------- tf32 helpers --------------------
__device__ __forceinline__ uint32_t f2tf32(float x) {
    uint32_t r;
    asm("cvt.rna.tf32.f32 %0, %1;" : "=r"(r) : "f"(x));
    return r;
}

__device__ __forceinline__ void mma8(float* c, const uint32_t* a, const uint32_t* b) {
    asm volatile(
        "mma.sync.aligned.m16n8k8.row.col.f32.tf32.tf32.f32 "
        "{%0,%1,%2,%3}, {%4,%5,%6,%7}, {%8,%9}, {%0,%1,%2,%3};"
        : "+f"(c[0]), "+f"(c[1]), "+f"(c[2]), "+f"(c[3])
        : "r"(a[0]), "r"(a[1]), "r"(a[2]), "r"(a[3]), "r"(b[0]), "r"(b[1]));
}

// -------------------- mask length detection --------------------
__device__ __forceinline__ int count_prefix(const unsigned char* p, int length,
                                            int esize, unsigned val) {
    int c = 0;
    for (int i = 0; i < length; i++) {
        unsigned v;
        if (esize == 1)      v = p[i];
        else if (esize == 2) v = ((const unsigned short*)p)[i];
        else                 v = ((const unsigned*)p)[i];
        if (v != val) break;
        c++;
    }
    return c;
}

__device__ void detect_fmt(const unsigned char* p, int length, int minlen,
                           int* esize, unsigned* val) {
    const int es[4]      = {1, 2, 4, 4};
    const unsigned vv[4] = {1u, 0x3F80u, 1u, 0x3F800000u};
    for (int k = 0; k < 4; k++) {
        if (count_prefix(p, length, es[k], vv[k]) >= minlen) {
            *esize = es[k]; *val = vv[k]; return;
        }
    }
    *esize = 4; *val = 1u;
}

__global__ void k_lens(const unsigned char* __restrict__ cm,
                       const unsigned char* __restrict__ qm) {
    __shared__ int es_c, es_q;
    __shared__ unsigned v_c, v_q;
    int t = threadIdx.x;
    if (t == 0) detect_fmt(cm, NN, NN / 4, &es_c, &v_c);
    if (t == 1) detect_fmt(qm, MM, MM / 4, &es_q, &v_q);
    __syncthreads();
    if (t < BB) {
        g_clen[t] = count_prefix(cm + (size_t)t * NN * es_c, NN, es_c, v_c);
    } else if (t < 2 * BB) {
        int b = t - BB;
        g_qlen[b] = count_prefix(qm + (size_t)b * MM * es_q, MM, es_q, v_q);
    }
}

// -------------------- cw = ctx @ w_c, qw = query @ w_q --------------------
__global__ void __launch_bounds__(256) k_rowdots(const float* __restrict__ ctx,
                                                 const float* __restrict__ qry,
                                                 const float* __restrict__ w) {
    int warp = threadIdx.x >> 5, lane = threadIdx.x & 31;
    int row = blockIdx.x * 8 + warp;
    const float* src; const float* wp; float* dst;
    if (row < BB * NN) {
        src = ctx + (size_t)row * DD; wp = w + DD;
        dst = g_cw + row;
    } else {
        int r = row - BB * NN;
        src = qry + (size_t)r * DD; wp = w;
        dst = g_qw + r;
    }
    float s = 0.f;
    #pragma unroll
    for (int d = lane * 4; d < DD; d += 128) {
        float4 v  = *(const float4*)(src + d);
        float4 wv = *(const float4*)(wp + d);
        s += v.x * wv.x + v.y * wv.y + v.z * wv.z + v.w * wv.w;
    }
    #pragma unroll
    for (int o = 16; o; o >>= 1) s += __shfl_xor_sync(0xFFFFFFFFu, s, o);
    if (lane == 0) *dst = s;
}

// -------------------- S GEMM via tf32 mma: S[n,m] = (ctx*wm)[n,:] . qry[m,:] ----
// block tile 128n x 128m, BK=32, 8 warps (4 n x 2 m), warp tile 32n x 64m.
__global__ void __launch_bounds__(256, 2) k_S_mma(const float* __restrict__ ctx,
                                                  const float* __restrict__ qry,
                                                  const float* __restrict__ w) {
    __shared__ uint32_t As[128][36];   // [n][k], stride 36: banks 4n+k, 144B rows
    __shared__ uint32_t Bs[128][36];   // [m][k]
    __shared__ float wm_s[DD];
    __shared__ float cw_s[128], qw_s[128];

    int b = blockIdx.z, n0 = blockIdx.x * 128, m0 = blockIdx.y * 128;
    int tid = threadIdx.x, lane = tid & 31, warp = tid >> 5;
    int wn = warp & 3, wmw = warp >> 2;

    for (int i = tid; i < DD; i += 256) wm_s[i] = w[2 * DD + i];
    if (tid < 128) cw_s[tid] = g_cw[b * NN + n0 + tid];
    else           qw_s[tid - 128] = g_qw[b * MM + m0 + (tid - 128)];
    __syncthreads();

    const float* ctxb = ctx + ((size_t)b * NN + n0) * DD;
    const float* qryb = qry + ((size_t)b * MM + m0) * DD;

    float acc[2][8][4] = {};

    int lr = tid >> 1;          // row 0..127
    int lf = (tid & 1) * 4;     // f4 base

    for (int k0 = 0; k0 < DD; k0 += 32) {
        #pragma unroll
        for (int i = 0; i < 4; i++) {
            int f4 = lf + i, kk = f4 * 4;
            float4 v = *(const float4*)(ctxb + (size_t)lr * DD + k0 + kk);
            uint4 pa;
            pa.x = f2tf32(v.x * wm_s[k0 + kk + 0]);
            pa.y = f2tf32(v.y * wm_s[k0 + kk + 1]);
            pa.z = f2tf32(v.z * wm_s[k0 + kk + 2]);
            pa.w = f2tf32(v.w * wm_s[k0 + kk + 3]);
            *(uint4*)&As[lr][kk] = pa;
            float4 u = *(const float4*)(qryb + (size_t)lr * DD + k0 + kk);
            uint4 pb;
            pb.x = f2tf32(u.x); pb.y = f2tf32(u.y);
            pb.z = f2tf32(u.z); pb.w = f2tf32(u.w);
            *(uint4*)&Bs[lr][kk] = pb;
        }
        __syncthreads();
        #pragma unroll
        for (int kk = 0; kk < 4; kk++) {
            int kb = kk * 8;
            uint32_t a[2][4];
            #pragma unroll
            for (int i = 0; i < 2; i++) {
                int r = wn * 32 + i * 16 + (lane >> 2);
                a[i][0] = As[r][kb + (lane & 3)];
                a[i][1] = As[r + 8][kb + (lane & 3)];
                a[i][2] = As[r][kb + 4 + (lane & 3)];
                a[i][3] = As[r + 8][kb + 4 + (lane & 3)];
            }
            #pragma unroll
            for (int j = 0; j < 8; j++) {
                int c = wmw * 64 + j * 8 + (lane >> 2);
                uint32_t bf[2];
                bf[0] = Bs[c][kb + (lane & 3)];
                bf[1] = Bs[c][kb + 4 + (lane & 3)];
                mma8(acc[0][j], a[0], bf);
                mma8(acc[1][j], a[1], bf);
            }
        }
        __syncthreads();
    }

    float* Sb = g_S + ((size_t)b * NN + n0) * MM + m0;
    #pragma unroll
    for (int i = 0; i < 2; i++) {
        int r = wn * 32 + i * 16 + (lane >> 2);
        float cw0 = cw_s[r], cw1 = cw_s[r + 8];
        #pragma unroll
        for (int j = 0; j < 8; j++) {
            int c = wmw * 64 + j * 8 + 2 * (lane & 3);
            float q0 = qw_s[c], q1 = qw_s[c + 1];
            float2 v0 = make_float2(acc[i][j][0] + cw0 + q0, acc[i][j][1] + cw0 + q1);
            float2 v1 = make_float2(acc[i][j][2] + cw1 + q0, acc[i][j][3] + cw1 + q1);
            *(float2*)(Sb + (size_t)r * MM + c)       = v0;
            *(float2*)(Sb + (size_t)(r + 8) * MM + c) = v1;
        }
    }
}

// -------------------- row softmax: A = softmax_m(S, q-masked) --------------------
__global__ void __launch_bounds__(256) k_rowsoft() {
    int row  = blockIdx.x * 8 + (threadIdx.x >> 5);   // global row [0, BB*NN)
    int lane = threadIdx.x & 31;
    int b    = row >> 10;                              // NN = 1024
    int qlen = g_qlen[b];
    const float* Sr = g_S + (size_t)row * MM;
    float4 v0 = *(const float4*)(Sr + lane * 4);
    float4 v1 = *(const float4*)(Sr + 128 + lane * 4);
    float s[8] = {v0.x, v0.y, v0.z, v0.w, v1.x, v1.y, v1.z, v1.w};
    int   mi[8];
    #pragma unroll
    for (int j = 0; j < 4; j++) { mi[j] = lane * 4 + j; mi[j + 4] = 128 + lane * 4 + j; }

    float mx = -1e30f;
    #pragma unroll
    for (int j = 0; j < 8; j++) if (mi[j] < qlen) mx = fmaxf(mx, s[j]);
    #pragma unroll
    for (int o = 16; o; o >>= 1) mx = fmaxf(mx, __shfl_xor_sync(0xFFFFFFFFu, mx, o));

    float e[8], sum = 0.f;
    #pragma unroll
    for (int j = 0; j < 8; j++) {
        e[j] = (mi[j] < qlen) ? __expf(s[j] - mx) : 0.f;
        sum += e[j];
    }
    #pragma unroll
    for (int o = 16; o; o >>= 1) sum += __shfl_xor_sync(0xFFFFFFFFu, sum, o);
    float inv = 1.f / sum;

    float* Ar = g_A + (size_t)row * MM;
    *(float4*)(Ar + lane * 4)       = make_float4(e[0] * inv, e[1] * inv, e[2] * inv, e[3] * inv);
    *(float4*)(Ar + 128 + lane * 4) = make_float4(e[4] * inv, e[5] * inv, e[6] * inv, e[7] * inv);
}

// -------------------- column softmax: Bm = softmax_n(S, c-masked) ----------------
// block: 32 m-columns x 8 n-partials (3 passes: max, sum, write).
__global__ void __launch_bounds__(256) k_bm() {
    int b = blockIdx.y;
    int lane = threadIdx.x & 31;
    int p = threadIdx.x >> 5;
    int m = blockIdx.x * 32 + lane;
    int clen = g_clen[b];
    const float* Sc = g_S + (size_t)b * NN * MM + m;

    __shared__ float red[8][32];

    float mx = -1e30f;
    for (int n = p; n < clen; n += 8) mx = fmaxf(mx, Sc[(size_t)n * MM]);
    red[p][lane] = mx;
    __syncthreads();
    float fm = red[0][lane];
    #pragma unroll
    for (int q = 1; q < 8; q++) fm = fmaxf(fm, red[q][lane]);
    __syncthreads();

    float sum = 0.f;
    for (int n = p; n < clen; n += 8) sum += __expf(Sc[(size_t)n * MM] - fm);
    red[p][lane] = sum;
    __syncthreads();
    float ts = 0.f;
    #pragma unroll
    for (int q = 0; q < 8; q++) ts += red[q][lane];
    float inv = 1.f / ts;

    float* Bc = g_Bm + (size_t)b * NN * MM + m;
    for (int n = p; n < NN; n += 8) {
        float v = (n < clen) ? __expf(Sc[(size_t)n * MM] - fm) * inv : 0.f;
        Bc[(size_t)n * MM] = v;
    }
}

// -------------------- mid = Bm^T @ ctx via tf32 mma (k = n) ----------------------
// block tile 128m x 128d, BK=32, warps 4(m) x 2(d), warp 32m x 64d.
__global__ void __launch_bounds__(256, 2) k_mid_mma(const float* __restrict__ ctx) {
    __shared__ uint32_t As[32][136];  // [k][m], stride 136: banks 8k+m, 544B rows
    __shared__ uint32_t Bs[32][136];  // [k][d]

    int b = blockIdx.z, d0 = blockIdx.x * 128, m0 = blockIdx.y * 128;
    int tid = threadIdx.x, lane = tid & 31, warp = tid >> 5;
    int wm = warp & 3, wd = warp >> 2;

    const float* Bmb  = g_Bm + (size_t)b * NN * MM;
    const float* ctxb = ctx  + (size_t)b * NN * DD;

    float acc[2][8][4] = {};

    int kr = tid >> 3;      // k row 0..31
    int f8 = tid & 7;       // f4 base

    for (int k0 = 0; k0 < NN; k0 += 32) {
        #pragma unroll
        for (int i = 0; i < 4; i++) {
            int f4 = f8 + 8 * i, cc = f4 * 4;
            float4 v = *(const float4*)(Bmb + (size_t)(k0 + kr) * MM + m0 + cc);
            uint4 pa;
            pa.x = f2tf32(v.x); pa.y = f2tf32(v.y);
            pa.z = f2tf32(v.z); pa.w = f2tf32(v.w);
            *(uint4*)&As[kr][cc] = pa;
            float4 u = *(const float4*)(ctxb + (size_t)(k0 + kr) * DD + d0 + cc);
            uint4 pb;
            pb.x = f2tf32(u.x); pb.y = f2tf32(u.y);
            pb.z = f2tf32(u.z); pb.w = f2tf32(u.w);
            *(uint4*)&Bs[kr][cc] = pb;
        }
        __syncthreads();
        #pragma unroll
        for (int kk = 0; kk < 4; kk++) {
            int kb = kk * 8;
            uint32_t a[2][4];
            #pragma unroll
            for (int i = 0; i < 2; i++) {
                int r = wm * 32 + i * 16 + (lane >> 2);
                a[i][0] = As[kb + (lane & 3)][r];
                a[i][1] = As[kb + (lane & 3)][r + 8];
                a[i][2] = As[kb + 4 + (lane & 3)][r];
                a[i][3] = As[kb + 4 + (lane & 3)][r + 8];
            }
            #pragma unroll
            for (int j = 0; j < 8; j++) {
                int c = wd * 64 + j * 8 + (lane >> 2);
                uint32_t bf[2];
                bf[0] = Bs[kb + (lane & 3)][c];
                bf[1] = Bs[kb + 4 + (lane & 3)][c];
                mma8(acc[0][j], a[0], bf);
                mma8(acc[1][j], a[1], bf);
            }
        }
        __syncthreads();
    }

    float* midb = g_mid + ((size_t)b * MM + m0) * DD + d0;
    #pragma unroll
    for (int i = 0; i < 2; i++) {
        int r = wm * 32 + i * 16 + (lane >> 2);
        #pragma unroll
        for (int j = 0; j < 8; j++) {
            int c = wd * 64 + j * 8 + 2 * (lane & 3);
            *(float2*)(midb + (size_t)r * DD + c)       = make_float2(acc[i][j][0], acc[i][j][1]);
            *(float2*)(midb + (size_t)(r + 8) * DD + c) = make_float2(acc[i][j][2], acc[i][j][3]);
        }
    }
}

// -------------------- out: c2q = A@qry, q2c = A@mid (k = m), fused epilogue ------
// block tile 128n x 64d, BK=32, warps 4(n) x 2(d), warp 32n x 32d, dual accum.
__global__ void __launch_bounds__(256, 2) k_out_mma(const float* __restrict__ ctx,
                                                    const float* __restrict__ qry,
                                                    float* __restrict__ out) {
    __shared__ uint32_t As [128][36];  // [n][k=m]
    __shared__ uint32_t Bq [32][72];   // [k][d], stride 72: banks 8k+d
    __shared__ uint32_t Bm2[32][72];

    int b = blockIdx.z, d0 = blockIdx.x * 64, n0 = blockIdx.y * 128;
    int tid = threadIdx.x, lane = tid & 31, warp = tid >> 5;
    int wn = warp & 3, wd = warp >> 2;

    const float* Ab   = g_A   + ((size_t)b * NN + n0) * MM;
    const float* qryb = qry   + (size_t)b * MM * DD;
    const float* midb = g_mid + (size_t)b * MM * DD;

    float accq[2][4][4] = {};
    float accm[2][4][4] = {};

    int lr = tid >> 1, lf = (tid & 1) * 4;  // A loads
    int kr = tid >> 3, f8 = tid & 7;        // B loads

    for (int k0 = 0; k0 < MM; k0 += 32) {
        #pragma unroll
        for (int i = 0; i < 4; i++) {
            int f4 = lf + i, cc = f4 * 4;
            float4 v = *(const float4*)(Ab + (size_t)lr * MM + k0 + cc);
            uint4 pa;
            pa.x = f2tf32(v.x); pa.y = f2tf32(v.y);
            pa.z = f2tf32(v.z); pa.w = f2tf32(v.w);
            *(uint4*)&As[lr][cc] = pa;
        }
        #pragma unroll
        for (int i = 0; i < 2; i++) {
            int f4 = f8 + 8 * i, cc = f4 * 4;
            float4 u = *(const float4*)(qryb + (size_t)(k0 + kr) * DD + d0 + cc);
            uint4 pb;
            pb.x = f2tf32(u.x); pb.y = f2tf32(u.y);
            pb.z = f2tf32(u.z); pb.w = f2tf32(u.w);
            *(uint4*)&Bq[kr][cc] = pb;
            float4 t = *(const float4*)(midb + (size_t)(k0 + kr) * DD + d0 + cc);
            uint4 pc;
            pc.x = f2tf32(t.x); pc.y = f2tf32(t.y);
            pc.z = f2tf32(t.z); pc.w = f2tf32(t.w);
            *(uint4*)&Bm2[kr][cc] = pc;
        }
        __syncthreads();
        #pragma unroll
        for (int kk = 0; kk < 4; kk++) {
            int kb = kk * 8;
            uint32_t a[2][4];
            #pragma unroll
            for (int i = 0; i < 2; i++) {
                int r = wn * 32 + i * 16 + (lane >> 2);
                a[i][0] = As[r][kb + (lane & 3)];
                a[i][1] = As[r + 8][kb + (lane & 3)];
                a[i][2] = As[r][kb + 4 + (lane & 3)];
                a[i][3] = As[r + 8][kb + 4 + (lane & 3)];
            }
            #pragma unroll
            for (int j = 0; j < 4; j++) {
                int c = wd * 32 + j * 8 + (lane >> 2);
                uint32_t bq[2], bm[2];
                bq[0] = Bq [kb + (lane & 3)][c];
                bq[1] = Bq [kb + 4 + (lane & 3)][c];
                bm[0] = Bm2[kb + (lane & 3)][c];
                bm[1] = Bm2[kb + 4 + (lane & 3)][c];
                mma8(accq[0][j], a[0], bq);
                mma8(accq[1][j], a[1], bq);
                mma8(accm[0][j], a[0], bm);
                mma8(accm[1][j], a[1], bm);
            }
        }
        __syncthreads();
    }

    // epilogue: out = [ctx, c2q, ctx*c2q, ctx*q2c]
    #pragma unroll
    for (int i = 0; i < 2; i++) {
        #pragma unroll
        for (int half = 0; half < 2; half++) {
            int n = n0 + wn * 32 + i * 16 + (lane >> 2) + half * 8;
            const float* crow = ctx + ((size_t)b * NN + n) * DD;
            float* orow = out + ((size_t)b * NN + n) * (4 * DD);
            #pragma unroll
            for (int j = 0; j < 4; j++) {
                int d = d0 + wd * 32 + j * 8 + 2 * (lane & 3);
                float2 cv = *(const float2*)(crow + d);
                float c2q0 = accq[i][j][half * 2], c2q1 = accq[i][j][half * 2 + 1];
                float q2c0 = accm[i][j][half * 2], q2c1 = accm[i][j][half * 2 + 1];
                *(float2*)(orow + d)            = cv;
                *(float2*)(orow + DD + d)       = make_float2(c2q0, c2q1);
                *(float2*)(orow + 2 * DD + d)   = make_float2(cv.x * c2q0, cv.y * c2q1);
                *(float2*)(orow + 3 * DD + d)   = make_float2(cv.x * q2c0, cv.y * q2c1);
            }
        }
    }
}

// -------------------- launch --------------------
extern "C" void kernel_launch(void* const* d_in, const int* in_sizes, int n_in,
                              void* d_out, int out_size) {
    const float* ctx = (const float*)d_in[0];
    const float* qry = (const float*)d_in[1];
    const unsigned char* cm = (const unsigned char*)d_in[2];
    const unsigned char* qm = (const unsigned char*)d_in[3];
    const float* w = (const float*)d_in[4];
    float* out = (float*)d_out;

    k_lens<<<1, 64>>>(cm, qm);
    k_rowdots<<<(BB * NN + BB * MM) / 8, 256>>>(ctx, qry, w);
    k_S_mma<<<dim3(NN / 128, MM / 128, BB), 256>>>(ctx, qry, w);
    k_rowsoft<<<BB * NN / 8, 256>>>();
    k_bm<<<dim3(MM / 32, BB), 256>>>();
    k_mid_mma<<<dim3(DD / 128, MM / 128, BB), 256>>>(ctx);
    k_out_mma<<<dim3(DD / 64, NN / 128, BB), 256>>>(ctx, qry, out);
}

// round 3
// speedup vs baseline: 2.1373x; 1.0554x over previous
#include <cuda_runtime.h>
#include <cstdint>
#include <cstddef>

#define BB 32
#define NN 1024
#define MM 256
#define DD 512

// -------------------- device scratch --------------------
__device__ __align__(128) float g_S [(size_t)BB * NN * MM];
__device__ __align__(128) float g_A [(size_t)BB * NN * MM];
__device__ __align__(128) float g_Bm[(size_t)BB * NN * MM];
__device__ __align__(128) float g_mid[(size_t)BB * MM * DD];
__device__ __align__(128) float g_qs [(size_t)BB * MM * DD];   // query * w_m
__device__ float g_cw[BB * NN];
__device__ float g_qw[BB * MM];
__device__ int   g_clen[BB];
__device__ int   g_qlen[BB];

// -------------------- helpers --------------------
__device__ __forceinline__ void mma8(float* c, const uint32_t* a, const uint32_t* b) {
    asm volatile(
        "mma.sync.aligned.m16n8k8.row.col.f32.tf32.tf32.f32 "
        "{%0,%1,%2,%3}, {%4,%5,%6,%7}, {%8,%9}, {%0,%1,%2,%3};"
        : "+f"(c[0]), "+f"(c[1]), "+f"(c[2]), "+f"(c[3])
        : "r"(a[0]), "r"(a[1]), "r"(a[2]), "r"(a[3]), "r"(b[0]), "r"(b[1]));
}

__device__ __forceinline__ uint32_t s2u(const void* p) {
    return (uint32_t)__cvta_generic_to_shared(p);
}

__device__ __forceinline__ void cp16(uint32_t dst, const void* src) {
    asm volatile("cp.async.cg.shared.global [%0], [%1], 16;" :: "r"(dst), "l"(src));
}
__device__ __forceinline__ void cp_commit() {
    asm volatile("cp.async.commit_group;");
}

// -------------------- mask length detection --------------------
__device__ __forceinline__ int count_prefix(const unsigned char* p, int length,
                                            int esize, unsigned val) {
    int c = 0;
    for (int i = 0; i < length; i++) {
        unsigned v;
        if (esize == 1)      v = p[i];
        else if (esize == 2) v = ((const unsigned short*)p)[i];
        else                 v = ((const unsigned*)p)[i];
        if (v != val) break;
        c++;
    }
    return c;
}

__device__ void detect_fmt(const unsigned char* p, int length, int minlen,
                           int* esize, unsigned* val) {
    const int es[4]      = {1, 2, 4, 4};
    const unsigned vv[4] = {1u, 0x3F80u, 1u, 0x3F800000u};
    for (int k = 0; k < 4; k++) {
        if (count_prefix(p, length, es[k], vv[k]) >= minlen) {
            *esize = es[k]; *val = vv[k]; return;
        }
    }
    *esize = 4; *val = 1u;
}

__global__ void k_lens(const unsigned char* __restrict__ cm,
                       const unsigned char* __restrict__ qm) {
    __shared__ int es_c, es_q;
    __shared__ unsigned v_c, v_q;
    int t = threadIdx.x;
    if (t == 0) detect_fmt(cm, NN, NN / 4, &es_c, &v_c);
    if (t == 1) detect_fmt(qm, MM, MM / 4, &es_q, &v_q);
    __syncthreads();
    if (t < BB) {
        g_clen[t] = count_prefix(cm + (size_t)t * NN * es_c, NN, es_c, v_c);
    } else if (t < 2 * BB) {
        int b = t - BB;
        g_qlen[b] = count_prefix(qm + (size_t)b * MM * es_q, MM, es_q, v_q);
    }
}

// -------------------- cw = ctx @ w_c, qw = query @ w_q --------------------
__global__ void __launch_bounds__(256) k_rowdots(const float* __restrict__ ctx,
                                                 const float* __restrict__ qry,
                                                 const float* __restrict__ w) {
    int warp = threadIdx.x >> 5, lane = threadIdx.x & 31;
    int row = blockIdx.x * 8 + warp;
    const float* src; const float* wp; float* dst;
    if (row < BB * NN) {
        src = ctx + (size_t)row * DD; wp = w + DD;
        dst = g_cw + row;
    } else {
        int r = row - BB * NN;
        src = qry + (size_t)r * DD; wp = w;
        dst = g_qw + r;
    }
    float s = 0.f;
    #pragma unroll
    for (int d = lane * 4; d < DD; d += 128) {
        float4 v  = *(const float4*)(src + d);
        float4 wv = *(const float4*)(wp + d);
        s += v.x * wv.x + v.y * wv.y + v.z * wv.z + v.w * wv.w;
    }
    #pragma unroll
    for (int o = 16; o; o >>= 1) s += __shfl_xor_sync(0xFFFFFFFFu, s, o);
    if (lane == 0) *dst = s;
}

// -------------------- qs = query * w_m --------------------
__global__ void __launch_bounds__(256) k_scale(const float* __restrict__ qry,
                                               const float* __restrict__ w) {
    int i4 = blockIdx.x * 256 + threadIdx.x;   // float4 index
    int d4 = i4 & (DD / 4 - 1);
    float4 v  = *(const float4*)(qry + (size_t)i4 * 4);
    float4 wm = *(const float4*)(w + 2 * DD + d4 * 4);
    v.x *= wm.x; v.y *= wm.y; v.z *= wm.z; v.w *= wm.w;
    *(float4*)(g_qs + (size_t)i4 * 4) = v;
}

// -------------------- S = ctx . qs^T via tf32 mma, cp.async 2-stage --------------
// block 128n x 128m, BK=32, warps 4(n) x 2(m), warp tile 32n x 64m.
__global__ void __launch_bounds__(256, 2) k_S_mma(const float* __restrict__ ctx) {
    extern __shared__ float sm[];
    float (*As)[128][36] = (float(*)[128][36])sm;                 // [stage][n][k]
    float (*Bs)[128][36] = (float(*)[128][36])(sm + 2 * 128 * 36);// [stage][m][k]
    __shared__ float cw_s[128], qw_s[128];

    int b = blockIdx.z, n0 = blockIdx.x * 128, m0 = blockIdx.y * 128;
    int tid = threadIdx.x, lane = tid & 31, warp = tid >> 5;
    int wn = warp & 3, wmw = warp >> 2;

    if (tid < 128) cw_s[tid] = g_cw[b * NN + n0 + tid];
    else           qw_s[tid - 128] = g_qw[b * MM + m0 + (tid - 128)];

    const float* ctxb = ctx  + ((size_t)b * NN + n0) * DD;
    const float* qsb  = g_qs + ((size_t)b * MM + m0) * DD;

    int lr = tid >> 1, lf = (tid & 1) * 16;   // row, float col base
    uint32_t aB[2] = { s2u(&As[0][lr][lf]), s2u(&As[1][lr][lf]) };
    uint32_t bB[2] = { s2u(&Bs[0][lr][lf]), s2u(&Bs[1][lr][lf]) };

    float acc[2][8][4] = {};
    const int KT = DD / 32;

    // prologue
    {
        const float* a = ctxb + (size_t)lr * DD + lf;
        const float* q = qsb  + (size_t)lr * DD + lf;
        #pragma unroll
        for (int i = 0; i < 4; i++) { cp16(aB[0] + i * 16, a + i * 4); cp16(bB[0] + i * 16, q + i * 4); }
        cp_commit();
    }

    for (int kt = 0; kt < KT; kt++) {
        int buf = kt & 1;
        if (kt + 1 < KT) {
            int k0 = (kt + 1) * 32;
            const float* a = ctxb + (size_t)lr * DD + k0 + lf;
            const float* q = qsb  + (size_t)lr * DD + k0 + lf;
            #pragma unroll
            for (int i = 0; i < 4; i++) { cp16(aB[buf ^ 1] + i * 16, a + i * 4); cp16(bB[buf ^ 1] + i * 16, q + i * 4); }
            cp_commit();
            asm volatile("cp.async.wait_group 1;");
        } else {
            asm volatile("cp.async.wait_group 0;");
        }
        __syncthreads();
        #pragma unroll
        for (int kk = 0; kk < 4; kk++) {
            int kb = kk * 8;
            uint32_t a[2][4];
            #pragma unroll
            for (int i = 0; i < 2; i++) {
                int r = wn * 32 + i * 16 + (lane >> 2);
                a[i][0] = __float_as_uint(As[buf][r][kb + (lane & 3)]);
                a[i][1] = __float_as_uint(As[buf][r + 8][kb + (lane & 3)]);
                a[i][2] = __float_as_uint(As[buf][r][kb + 4 + (lane & 3)]);
                a[i][3] = __float_as_uint(As[buf][r + 8][kb + 4 + (lane & 3)]);
            }
            #pragma unroll
            for (int j = 0; j < 8; j++) {
                int c = wmw * 64 + j * 8 + (lane >> 2);
                uint32_t bf[2];
                bf[0] = __float_as_uint(Bs[buf][c][kb + (lane & 3)]);
                bf[1] = __float_as_uint(Bs[buf][c][kb + 4 + (lane & 3)]);
                mma8(acc[0][j], a[0], bf);
                mma8(acc[1][j], a[1], bf);
            }
        }
        __syncthreads();
    }

    float* Sb = g_S + ((size_t)b * NN + n0) * MM + m0;
    #pragma unroll
    for (int i = 0; i < 2; i++) {
        int r = wn * 32 + i * 16 + (lane >> 2);
        float cw0 = cw_s[r], cw1 = cw_s[r + 8];
        #pragma unroll
        for (int j = 0; j < 8; j++) {
            int c = wmw * 64 + j * 8 + 2 * (lane & 3);
            float q0 = qw_s[c], q1 = qw_s[c + 1];
            *(float2*)(Sb + (size_t)r * MM + c)       = make_float2(acc[i][j][0] + cw0 + q0, acc[i][j][1] + cw0 + q1);
            *(float2*)(Sb + (size_t)(r + 8) * MM + c) = make_float2(acc[i][j][2] + cw1 + q0, acc[i][j][3] + cw1 + q1);
        }
    }
}

// -------------------- row softmax: A = softmax_m(S, q-masked) --------------------
__global__ void __launch_bounds__(256) k_rowsoft() {
    int row  = blockIdx.x * 8 + (threadIdx.x >> 5);
    int lane = threadIdx.x & 31;
    int b    = row >> 10;
    int qlen = g_qlen[b];
    const float* Sr = g_S + (size_t)row * MM;
    float4 v0 = *(const float4*)(Sr + lane * 4);
    float4 v1 = *(const float4*)(Sr + 128 + lane * 4);
    float s[8] = {v0.x, v0.y, v0.z, v0.w, v1.x, v1.y, v1.z, v1.w};
    int   mi[8];
    #pragma unroll
    for (int j = 0; j < 4; j++) { mi[j] = lane * 4 + j; mi[j + 4] = 128 + lane * 4 + j; }

    float mx = -1e30f;
    #pragma unroll
    for (int j = 0; j < 8; j++) if (mi[j] < qlen) mx = fmaxf(mx, s[j]);
    #pragma unroll
    for (int o = 16; o; o >>= 1) mx = fmaxf(mx, __shfl_xor_sync(0xFFFFFFFFu, mx, o));

    float e[8], sum = 0.f;
    #pragma unroll
    for (int j = 0; j < 8; j++) {
        e[j] = (mi[j] < qlen) ? __expf(s[j] - mx) : 0.f;
        sum += e[j];
    }
    #pragma unroll
    for (int o = 16; o; o >>= 1) sum += __shfl_xor_sync(0xFFFFFFFFu, sum, o);
    float inv = 1.f / sum;

    float* Ar = g_A + (size_t)row * MM;
    *(float4*)(Ar + lane * 4)       = make_float4(e[0] * inv, e[1] * inv, e[2] * inv, e[3] * inv);
    *(float4*)(Ar + 128 + lane * 4) = make_float4(e[4] * inv, e[5] * inv, e[6] * inv, e[7] * inv);
}

// -------------------- column softmax: Bm = softmax_n(S, c-masked) ----------------
__global__ void __launch_bounds__(256) k_bm() {
    int b = blockIdx.y;
    int lane = threadIdx.x & 31;
    int p = threadIdx.x >> 5;
    int m = blockIdx.x * 32 + lane;
    int clen = g_clen[b];
    const float* Sc = g_S + (size_t)b * NN * MM + m;

    __shared__ float red[8][32];

    float mx = -1e30f;
    for (int n = p; n < clen; n += 8) mx = fmaxf(mx, Sc[(size_t)n * MM]);
    red[p][lane] = mx;
    __syncthreads();
    float fm = red[0][lane];
    #pragma unroll
    for (int q = 1; q < 8; q++) fm = fmaxf(fm, red[q][lane]);
    __syncthreads();

    float sum = 0.f;
    for (int n = p; n < clen; n += 8) sum += __expf(Sc[(size_t)n * MM] - fm);
    red[p][lane] = sum;
    __syncthreads();
    float ts = 0.f;
    #pragma unroll
    for (int q = 0; q < 8; q++) ts += red[q][lane];
    float inv = 1.f / ts;

    float* Bc = g_Bm + (size_t)b * NN * MM + m;
    for (int n = p; n < NN; n += 8) {
        float v = (n < clen) ? __expf(Sc[(size_t)n * MM] - fm) * inv : 0.f;
        Bc[(size_t)n * MM] = v;
    }
}

// -------------------- mid = Bm^T @ ctx via tf32 mma, cp.async 2-stage ------------
// block 128m x 128d, BK=32(n), warps 4(m) x 2(d).
__global__ void __launch_bounds__(256, 2) k_mid_mma(const float* __restrict__ ctx) {
    extern __shared__ float sm[];
    float (*As)[32][136] = (float(*)[32][136])sm;                  // [stage][k][m]
    float (*Bs)[32][136] = (float(*)[32][136])(sm + 2 * 32 * 136); // [stage][k][d]

    int b = blockIdx.z, d0 = blockIdx.x * 128, m0 = blockIdx.y * 128;
    int tid = threadIdx.x, lane = tid & 31, warp = tid >> 5;
    int wm = warp & 3, wd = warp >> 2;

    const float* Bmb  = g_Bm + (size_t)b * NN * MM;
    const float* ctxb = ctx  + (size_t)b * NN * DD;

    int kr = tid >> 3, f8 = (tid & 7) * 4;   // k row, float col base (stride 32)
    uint32_t aB[2] = { s2u(&As[0][kr][f8]), s2u(&As[1][kr][f8]) };
    uint32_t bB[2] = { s2u(&Bs[0][kr][f8]), s2u(&Bs[1][kr][f8]) };

    float acc[2][8][4] = {};
    const int KT = NN / 32;

    {
        const float* a = Bmb  + (size_t)kr * MM + m0 + f8;
        const float* c = ctxb + (size_t)kr * DD + d0 + f8;
        #pragma unroll
        for (int i = 0; i < 4; i++) {
            cp16(aB[0] + i * 128, a + i * 32);
            cp16(bB[0] + i * 128, c + i * 32);
        }
        cp_commit();
    }

    for (int kt = 0; kt < KT; kt++) {
        int buf = kt & 1;
        if (kt + 1 < KT) {
            int k0 = (kt + 1) * 32;
            const float* a = Bmb  + (size_t)(k0 + kr) * MM + m0 + f8;
            const float* c = ctxb + (size_t)(k0 + kr) * DD + d0 + f8;
            #pragma unroll
            for (int i = 0; i < 4; i++) {
                cp16(aB[buf ^ 1] + i * 128, a + i * 32);
                cp16(bB[buf ^ 1] + i * 128, c + i * 32);
            }
            cp_commit();
            asm volatile("cp.async.wait_group 1;");
        } else {
            asm volatile("cp.async.wait_group 0;");
        }
        __syncthreads();
        #pragma unroll
        for (int kk = 0; kk < 4; kk++) {
            int kb = kk * 8;
            uint32_t a[2][4];
            #pragma unroll
            for (int i = 0; i < 2; i++) {
                int r = wm * 32 + i * 16 + (lane >> 2);
                a[i][0] = __float_as_uint(As[buf][kb + (lane & 3)][r]);
                a[i][1] = __float_as_uint(As[buf][kb + (lane & 3)][r + 8]);
                a[i][2] = __float_as_uint(As[buf][kb + 4 + (lane & 3)][r]);
                a[i][3] = __float_as_uint(As[buf][kb + 4 + (lane & 3)][r + 8]);
            }
            #pragma unroll
            for (int j = 0; j < 8; j++) {
                int c = wd * 64 + j * 8 + (lane >> 2);
                uint32_t bf[2];
                bf[0] = __float_as_uint(Bs[buf][kb + (lane & 3)][c]);
                bf[1] = __float_as_uint(Bs[buf][kb + 4 + (lane & 3)][c]);
                mma8(acc[0][j], a[0], bf);
                mma8(acc[1][j], a[1], bf);
            }
        }
        __syncthreads();
    }

    float* midb = g_mid + ((size_t)b * MM + m0) * DD + d0;
    #pragma unroll
    for (int i = 0; i < 2; i++) {
        int r = wm * 32 + i * 16 + (lane >> 2);
        #pragma unroll
        for (int j = 0; j < 8; j++) {
            int c = wd * 64 + j * 8 + 2 * (lane & 3);
            *(float2*)(midb + (size_t)r * DD + c)       = make_float2(acc[i][j][0], acc[i][j][1]);
            *(float2*)(midb + (size_t)(r + 8) * DD + c) = make_float2(acc[i][j][2], acc[i][j][3]);
        }
    }
}

// -------------------- out: c2q = A@qry, q2c = A@mid, cp.async 2-stage ------------
// block 128n x 64d, BK=32(m), warps 4(n) x 2(d), dual accumulators.
__global__ void __launch_bounds__(256, 2) k_out_mma(const float* __restrict__ ctx,
                                                    const float* __restrict__ qry,
                                                    float* __restrict__ out) {
    extern __shared__ float sm[];
    float (*As)[128][36] = (float(*)[128][36])sm;                        // [stage][n][k]
    float (*Bq)[32][72]  = (float(*)[32][72])(sm + 2 * 128 * 36);        // [stage][k][d]
    float (*Bm2)[32][72] = (float(*)[32][72])(sm + 2 * 128 * 36 + 2 * 32 * 72);

    int b = blockIdx.z, d0 = blockIdx.x * 64, n0 = blockIdx.y * 128;
    int tid = threadIdx.x, lane = tid & 31, warp = tid >> 5;
    int wn = warp & 3, wd = warp >> 2;

    const float* Ab   = g_A   + ((size_t)b * NN + n0) * MM;
    const float* qryb = qry   + (size_t)b * MM * DD;
    const float* midb = g_mid + (size_t)b * MM * DD;

    float accq[2][4][4] = {};
    float accm[2][4][4] = {};

    int lr = tid >> 1, lf = (tid & 1) * 16;   // A loads
    int kr = tid >> 3, f8 = (tid & 7) * 4;    // B loads
    uint32_t aB[2]  = { s2u(&As[0][lr][lf]),  s2u(&As[1][lr][lf]) };
    uint32_t qB[2]  = { s2u(&Bq[0][kr][f8]),  s2u(&Bq[1][kr][f8]) };
    uint32_t mB[2]  = { s2u(&Bm2[0][kr][f8]), s2u(&Bm2[1][kr][f8]) };

    const int KT = MM / 32;

    {
        const float* a = Ab + (size_t)lr * MM + lf;
        const float* q = qryb + (size_t)kr * DD + d0 + f8;
        const float* m = midb + (size_t)kr * DD + d0 + f8;
        #pragma unroll
        for (int i = 0; i < 4; i++) cp16(aB[0] + i * 16, a + i * 4);
        #pragma unroll
        for (int i = 0; i < 2; i++) { cp16(qB[0] + i * 128, q + i * 32); cp16(mB[0] + i * 128, m + i * 32); }
        cp_commit();
    }

    for (int kt = 0; kt < KT; kt++) {
        int buf = kt & 1;
        if (kt + 1 < KT) {
            int k0 = (kt + 1) * 32;
            const float* a = Ab + (size_t)lr * MM + k0 + lf;
            const float* q = qryb + (size_t)(k0 + kr) * DD + d0 + f8;
            const float* m = midb + (size_t)(k0 + kr) * DD + d0 + f8;
            #pragma unroll
            for (int i = 0; i < 4; i++) cp16(aB[buf ^ 1] + i * 16, a + i * 4);
            #pragma unroll
            for (int i = 0; i < 2; i++) { cp16(qB[buf ^ 1] + i * 128, q + i * 32); cp16(mB[buf ^ 1] + i * 128, m + i * 32); }
            cp_commit();
            asm volatile("cp.async.wait_group 1;");
        } else {
            asm volatile("cp.async.wait_group 0;");
        }
        __syncthreads();
        #pragma unroll
        for (int kk = 0; kk < 4; kk++) {
            int kb = kk * 8;
            uint32_t a[2][4];
            #pragma unroll
            for (int i = 0; i < 2; i++) {
                int r = wn * 32 + i * 16 + (lane >> 2);
                a[i][0] = __float_as_uint(As[buf][r][kb + (lane & 3)]);
                a[i][1] = __float_as_uint(As[buf][r + 8][kb + (lane & 3)]);
                a[i][2] = __float_as_uint(As[buf][r][kb + 4 + (lane & 3)]);
                a[i][3] = __float_as_uint(As[buf][r + 8][kb + 4 + (lane & 3)]);
            }
            #pragma unroll
            for (int j = 0; j < 4; j++) {
                int c = wd * 32 + j * 8 + (lane >> 2);
                uint32_t bq[2], bm[2];
                bq[0] = __float_as_uint(Bq[buf][kb + (lane & 3)][c]);
                bq[1] = __float_as_uint(Bq[buf][kb + 4 + (lane & 3)][c]);
                bm[0] = __float_as_uint(Bm2[buf][kb + (lane & 3)][c]);
                bm[1] = __float_as_uint(Bm2[buf][kb + 4 + (lane & 3)][c]);
                mma8(accq[0][j], a[0], bq);
                mma8(accq[1][j], a[1], bq);
                mma8(accm[0][j], a[0], bm);
                mma8(accm[1][j], a[1], bm);
            }
        }
        __syncthreads();
    }

    #pragma unroll
    for (int i = 0; i < 2; i++) {
        #pragma unroll
        for (int half = 0; half < 2; half++) {
            int n = n0 + wn * 32 + i * 16 + (lane >> 2) + half * 8;
            const float* crow = ctx + ((size_t)b * NN + n) * DD;
            float* orow = out + ((size_t)b * NN + n) * (4 * DD);
            #pragma unroll
            for (int j = 0; j < 4; j++) {
                int d = d0 + wd * 32 + j * 8 + 2 * (lane & 3);
                float2 cv = *(const float2*)(crow + d);
                float c2q0 = accq[i][j][half * 2], c2q1 = accq[i][j][half * 2 + 1];
                float q2c0 = accm[i][j][half * 2], q2c1 = accm[i][j][half * 2 + 1];
                *(float2*)(orow + d)          = cv;
                *(float2*)(orow + DD + d)     = make_float2(c2q0, c2q1);
                *(float2*)(orow + 2 * DD + d) = make_float2(cv.x * c2q0, cv.y * c2q1);
                *(float2*)(orow + 3 * DD + d) = make_float2(cv.x * q2c0, cv.y * q2c1);
            }
        }
    }
}

// -------------------- launch --------------------
extern "C" void kernel_launch(void* const* d_in, const int* in_sizes, int n_in,
                              void* d_out, int out_size) {
    const float* ctx = (const float*)d_in[0];
    const float* qry = (const float*)d_in[1];
    const unsigned char* cm = (const unsigned char*)d_in[2];
    const unsigned char* qm = (const unsigned char*)d_in[3];
    const float* w = (const float*)d_in[4];
    float* out = (float*)d_out;

    const int SMEM_S   = 2 * 128 * 36 * 4 * 2;                 // 73728
    const int SMEM_MID = 2 * 32 * 136 * 4 * 2;                 // 69632
    const int SMEM_OUT = (2 * 128 * 36 + 4 * 32 * 72) * 4;     // 73728

    cudaFuncSetAttribute(k_S_mma,   cudaFuncAttributeMaxDynamicSharedMemorySize, SMEM_S);
    cudaFuncSetAttribute(k_mid_mma, cudaFuncAttributeMaxDynamicSharedMemorySize, SMEM_MID);
    cudaFuncSetAttribute(k_out_mma, cudaFuncAttributeMaxDynamicSharedMemorySize, SMEM_OUT);

    k_lens<<<1, 64>>>(cm, qm);
    k_rowdots<<<(BB * NN + BB * MM) / 8, 256>>>(ctx, qry, w);
    k_scale<<<(BB * MM * DD) / (4 * 256), 256>>>(qry, w);
    k_S_mma<<<dim3(NN / 128, MM / 128, BB), 256, SMEM_S>>>(ctx);
    k_rowsoft<<<BB * NN / 8, 256>>>();
    k_bm<<<dim3(MM / 32, BB), 256>>>();
    k_mid_mma<<<dim3(DD / 128, MM / 128, BB), 256, SMEM_MID>>>(ctx);
    k_out_mma<<<dim3(DD / 64, NN / 128, BB), 256, SMEM_OUT>>>(ctx, qry, out);
}

// round 4
// speedup vs baseline: 2.2052x; 1.0318x over previous
#include <cuda_runtime.h>
#include <cstdint>
#include <cstddef>

#define BB 32
#define NN 1024
#define MM 256
#define DD 512

// -------------------- device scratch --------------------
__device__ __align__(128) float g_S  [(size_t)BB * NN * MM];
__device__ __align__(128) float g_A  [(size_t)BB * NN * MM];
__device__ __align__(128) float g_Bm [(size_t)BB * NN * MM];
__device__ __align__(128) float g_midT[(size_t)BB * DD * MM];  // mid transposed [d][m]
__device__ __align__(128) float g_qs [(size_t)BB * MM * DD];   // query * w_m
__device__ __align__(128) float g_qT [(size_t)BB * DD * MM];   // query transposed [d][m]
__device__ float g_cw[BB * NN];
__device__ float g_qw[BB * MM];
__device__ int   g_clen[BB];
__device__ int   g_qlen[BB];

// -------------------- helpers --------------------
__device__ __forceinline__ void mma8(float* c, const uint32_t* a, const uint32_t* b) {
    asm volatile(
        "mma.sync.aligned.m16n8k8.row.col.f32.tf32.tf32.f32 "
        "{%0,%1,%2,%3}, {%4,%5,%6,%7}, {%8,%9}, {%0,%1,%2,%3};"
        : "+f"(c[0]), "+f"(c[1]), "+f"(c[2]), "+f"(c[3])
        : "r"(a[0]), "r"(a[1]), "r"(a[2]), "r"(a[3]), "r"(b[0]), "r"(b[1]));
}

__device__ __forceinline__ void ldsm4(uint32_t* r, uint32_t addr) {
    asm volatile("ldmatrix.sync.aligned.m8n8.x4.shared.b16 {%0,%1,%2,%3}, [%4];"
                 : "=r"(r[0]), "=r"(r[1]), "=r"(r[2]), "=r"(r[3]) : "r"(addr));
}

__device__ __forceinline__ uint32_t s2u(const void* p) {
    return (uint32_t)__cvta_generic_to_shared(p);
}

__device__ __forceinline__ void cp16(uint32_t dst, const void* src) {
    asm volatile("cp.async.cg.shared.global [%0], [%1], 16;" :: "r"(dst), "l"(src));
}
__device__ __forceinline__ void cp_commit() {
    asm volatile("cp.async.commit_group;");
}
__device__ __forceinline__ void cp_wait0() {
    asm volatile("cp.async.wait_group 0;");
}

// -------------------- mask length detection --------------------
__device__ __forceinline__ int count_prefix(const unsigned char* p, int length,
                                            int esize, unsigned val) {
    int c = 0;
    for (int i = 0; i < length; i++) {
        unsigned v;
        if (esize == 1)      v = p[i];
        else if (esize == 2) v = ((const unsigned short*)p)[i];
        else                 v = ((const unsigned*)p)[i];
        if (v != val) break;
        c++;
    }
    return c;
}

__device__ void detect_fmt(const unsigned char* p, int length, int minlen,
                           int* esize, unsigned* val) {
    const int es[4]      = {1, 2, 4, 4};
    const unsigned vv[4] = {1u, 0x3F80u, 1u, 0x3F800000u};
    for (int k = 0; k < 4; k++) {
        if (count_prefix(p, length, es[k], vv[k]) >= minlen) {
            *esize = es[k]; *val = vv[k]; return;
        }
    }
    *esize = 4; *val = 1u;
}

__global__ void k_lens(const unsigned char* __restrict__ cm,
                       const unsigned char* __restrict__ qm) {
    __shared__ int es_c, es_q;
    __shared__ unsigned v_c, v_q;
    int t = threadIdx.x;
    if (t == 0) detect_fmt(cm, NN, NN / 4, &es_c, &v_c);
    if (t == 1) detect_fmt(qm, MM, MM / 4, &es_q, &v_q);
    __syncthreads();
    if (t < BB) {
        g_clen[t] = count_prefix(cm + (size_t)t * NN * es_c, NN, es_c, v_c);
    } else if (t < 2 * BB) {
        int b = t - BB;
        g_qlen[b] = count_prefix(qm + (size_t)b * MM * es_q, MM, es_q, v_q);
    }
}

// -------------------- cw = ctx @ w_c, qw = query @ w_q --------------------
__global__ void __launch_bounds__(256) k_rowdots(const float* __restrict__ ctx,
                                                 const float* __restrict__ qry,
                                                 const float* __restrict__ w) {
    int warp = threadIdx.x >> 5, lane = threadIdx.x & 31;
    int row = blockIdx.x * 8 + warp;
    const float* src; const float* wp; float* dst;
    if (row < BB * NN) {
        src = ctx + (size_t)row * DD; wp = w + DD;
        dst = g_cw + row;
    } else {
        int r = row - BB * NN;
        src = qry + (size_t)r * DD; wp = w;
        dst = g_qw + r;
    }
    float s = 0.f;
    #pragma unroll
    for (int d = lane * 4; d < DD; d += 128) {
        float4 v  = *(const float4*)(src + d);
        float4 wv = *(const float4*)(wp + d);
        s += v.x * wv.x + v.y * wv.y + v.z * wv.z + v.w * wv.w;
    }
    #pragma unroll
    for (int o = 16; o; o >>= 1) s += __shfl_xor_sync(0xFFFFFFFFu, s, o);
    if (lane == 0) *dst = s;
}

// -------------------- qs = query * w_m --------------------
__global__ void __launch_bounds__(256) k_scale(const float* __restrict__ qry,
                                               const float* __restrict__ w) {
    int i4 = blockIdx.x * 256 + threadIdx.x;
    int d4 = i4 & (DD / 4 - 1);
    float4 v  = *(const float4*)(qry + (size_t)i4 * 4);
    float4 wm = *(const float4*)(w + 2 * DD + d4 * 4);
    v.x *= wm.x; v.y *= wm.y; v.z *= wm.z; v.w *= wm.w;
    *(float4*)(g_qs + (size_t)i4 * 4) = v;
}

// -------------------- qT[b][d][m] = qry[b][m][d] --------------------
__global__ void k_tq(const float* __restrict__ qry) {
    __shared__ float t[32][33];
    int b = blockIdx.z, m0 = blockIdx.x * 32, d0 = blockIdx.y * 32;
    int tx = threadIdx.x, ty = threadIdx.y;
    const float* src = qry + ((size_t)b * MM + m0) * DD + d0;
    #pragma unroll
    for (int i = 0; i < 4; i++) t[ty + 8 * i][tx] = src[(size_t)(ty + 8 * i) * DD + tx];
    __syncthreads();
    float* dst = g_qT + ((size_t)b * DD + d0) * MM + m0;
    #pragma unroll
    for (int i = 0; i < 4; i++) dst[(size_t)(ty + 8 * i) * MM + tx] = t[tx][ty + 8 * i];
}

// -------------------- S = ctx . qs^T, tf32 mma + ldmatrix, 1-barrier pipeline ----
__global__ void __launch_bounds__(256, 2) k_S_mma(const float* __restrict__ ctx) {
    extern __shared__ float sm[];
    float (*As)[128][36] = (float(*)[128][36])sm;
    float (*Bs)[128][36] = (float(*)[128][36])(sm + 2 * 128 * 36);
    __shared__ float cw_s[128], qw_s[128];
    const uint32_t STG = 128 * 36 * 4;

    int b = blockIdx.z, n0 = blockIdx.x * 128, m0 = blockIdx.y * 128;
    int tid = threadIdx.x, lane = tid & 31, warp = tid >> 5;
    int wn = warp & 3, wmw = warp >> 2;

    if (tid < 128) cw_s[tid] = g_cw[b * NN + n0 + tid];
    else           qw_s[tid - 128] = g_qw[b * MM + m0 + (tid - 128)];

    const float* ctxb = ctx  + ((size_t)b * NN + n0) * DD;
    const float* qsb  = g_qs + ((size_t)b * MM + m0) * DD;

    int lr = tid >> 1, lf = (tid & 1) * 16;
    uint32_t aCp = s2u(&As[0][lr][lf]);
    uint32_t bCp = s2u(&Bs[0][lr][lf]);

    int g = lane >> 3, lr8 = lane & 7;
    uint32_t aLd[2], bLd[4];
    #pragma unroll
    for (int i = 0; i < 2; i++)
        aLd[i] = s2u(&As[0][wn * 32 + i * 16 + (g & 1) * 8 + lr8][(g >> 1) * 4]);
    #pragma unroll
    for (int jj = 0; jj < 4; jj++)
        bLd[jj] = s2u(&Bs[0][wmw * 64 + jj * 16 + (g >> 1) * 8 + lr8][(g & 1) * 4]);

    float acc[2][8][4] = {};
    const int KT = DD / 32;

    {
        const float* a = ctxb + (size_t)lr * DD + lf;
        const float* q = qsb  + (size_t)lr * DD + lf;
        #pragma unroll
        for (int i = 0; i < 4; i++) { cp16(aCp + i * 16, a + i * 4); cp16(bCp + i * 16, q + i * 4); }
        cp_commit();
    }

    for (int kt = 0; kt < KT; kt++) {
        uint32_t boff = (kt & 1) ? STG : 0;
        cp_wait0();
        __syncthreads();
        if (kt + 1 < KT) {
            uint32_t poff = (kt & 1) ? 0 : STG;
            int k0 = (kt + 1) * 32;
            const float* a = ctxb + (size_t)lr * DD + k0 + lf;
            const float* q = qsb  + (size_t)lr * DD + k0 + lf;
            #pragma unroll
            for (int i = 0; i < 4; i++) { cp16(aCp + poff + i * 16, a + i * 4); cp16(bCp + poff + i * 16, q + i * 4); }
            cp_commit();
        }
        #pragma unroll
        for (int kk = 0; kk < 4; kk++) {
            uint32_t ko = boff + kk * 32;
            uint32_t a0[4], a1[4];
            ldsm4(a0, aLd[0] + ko);
            ldsm4(a1, aLd[1] + ko);
            #pragma unroll
            for (int jj = 0; jj < 4; jj++) {
                uint32_t bb[4];
                ldsm4(bb, bLd[jj] + ko);
                mma8(acc[0][2 * jj],     a0, bb);
                mma8(acc[0][2 * jj + 1], a0, bb + 2);
                mma8(acc[1][2 * jj],     a1, bb);
                mma8(acc[1][2 * jj + 1], a1, bb + 2);
            }
        }
    }

    float* Sb = g_S + ((size_t)b * NN + n0) * MM + m0;
    #pragma unroll
    for (int i = 0; i < 2; i++) {
        int r = wn * 32 + i * 16 + (lane >> 2);
        float cw0 = cw_s[r], cw1 = cw_s[r + 8];
        #pragma unroll
        for (int j = 0; j < 8; j++) {
            int c = wmw * 64 + j * 8 + 2 * (lane & 3);
            float q0 = qw_s[c], q1 = qw_s[c + 1];
            *(float2*)(Sb + (size_t)r * MM + c)       = make_float2(acc[i][j][0] + cw0 + q0, acc[i][j][1] + cw0 + q1);
            *(float2*)(Sb + (size_t)(r + 8) * MM + c) = make_float2(acc[i][j][2] + cw1 + q0, acc[i][j][3] + cw1 + q1);
        }
    }
}

// -------------------- row softmax: A = softmax_m(S, q-masked) --------------------
__global__ void __launch_bounds__(256) k_rowsoft() {
    int row  = blockIdx.x * 8 + (threadIdx.x >> 5);
    int lane = threadIdx.x & 31;
    int b    = row >> 10;
    int qlen = g_qlen[b];
    const float* Sr = g_S + (size_t)row * MM;
    float4 v0 = *(const float4*)(Sr + lane * 4);
    float4 v1 = *(const float4*)(Sr + 128 + lane * 4);
    float s[8] = {v0.x, v0.y, v0.z, v0.w, v1.x, v1.y, v1.z, v1.w};
    int   mi[8];
    #pragma unroll
    for (int j = 0; j < 4; j++) { mi[j] = lane * 4 + j; mi[j + 4] = 128 + lane * 4 + j; }

    float mx = -1e30f;
    #pragma unroll
    for (int j = 0; j < 8; j++) if (mi[j] < qlen) mx = fmaxf(mx, s[j]);
    #pragma unroll
    for (int o = 16; o; o >>= 1) mx = fmaxf(mx, __shfl_xor_sync(0xFFFFFFFFu, mx, o));

    float e[8], sum = 0.f;
    #pragma unroll
    for (int j = 0; j < 8; j++) {
        e[j] = (mi[j] < qlen) ? __expf(s[j] - mx) : 0.f;
        sum += e[j];
    }
    #pragma unroll
    for (int o = 16; o; o >>= 1) sum += __shfl_xor_sync(0xFFFFFFFFu, sum, o);
    float inv = 1.f / sum;

    float* Ar = g_A + (size_t)row * MM;
    *(float4*)(Ar + lane * 4)       = make_float4(e[0] * inv, e[1] * inv, e[2] * inv, e[3] * inv);
    *(float4*)(Ar + 128 + lane * 4) = make_float4(e[4] * inv, e[5] * inv, e[6] * inv, e[7] * inv);
}

// -------------------- column softmax: Bm = softmax_n(S, c-masked) ----------------
__global__ void __launch_bounds__(256) k_bm() {
    int b = blockIdx.y;
    int lane = threadIdx.x & 31;
    int p = threadIdx.x >> 5;
    int m = blockIdx.x * 32 + lane;
    int clen = g_clen[b];
    const float* Sc = g_S + (size_t)b * NN * MM + m;

    __shared__ float red[8][32];

    float mx = -1e30f;
    for (int n = p; n < clen; n += 8) mx = fmaxf(mx, Sc[(size_t)n * MM]);
    red[p][lane] = mx;
    __syncthreads();
    float fm = red[0][lane];
    #pragma unroll
    for (int q = 1; q < 8; q++) fm = fmaxf(fm, red[q][lane]);
    __syncthreads();

    float sum = 0.f;
    for (int n = p; n < clen; n += 8) sum += __expf(Sc[(size_t)n * MM] - fm);
    red[p][lane] = sum;
    __syncthreads();
    float ts = 0.f;
    #pragma unroll
    for (int q = 0; q < 8; q++) ts += red[q][lane];
    float inv = 1.f / ts;

    float* Bc = g_Bm + (size_t)b * NN * MM + m;
    for (int n = p; n < NN; n += 8) {
        float v = (n < clen) ? __expf(Sc[(size_t)n * MM] - fm) * inv : 0.f;
        Bc[(size_t)n * MM] = v;
    }
}

// -------------------- midT[d][m] = (Bm^T @ ctx)^T, tf32 mma, 1-barrier -----------
__global__ void __launch_bounds__(256, 2) k_mid_mma(const float* __restrict__ ctx) {
    extern __shared__ float sm[];
    float (*As)[32][136] = (float(*)[32][136])sm;                  // [stage][k][m]
    float (*Bs)[32][136] = (float(*)[32][136])(sm + 2 * 32 * 136); // [stage][k][d]

    int b = blockIdx.z, d0 = blockIdx.x * 128, m0 = blockIdx.y * 128;
    int tid = threadIdx.x, lane = tid & 31, warp = tid >> 5;
    int wm = warp & 3, wd = warp >> 2;

    const float* Bmb  = g_Bm + (size_t)b * NN * MM;
    const float* ctxb = ctx  + (size_t)b * NN * DD;

    int kr = tid >> 3, f8 = (tid & 7) * 4;
    uint32_t aCp = s2u(&As[0][kr][f8]);
    uint32_t bCp = s2u(&Bs[0][kr][f8]);
    const uint32_t STG = 32 * 136 * 4;

    float acc[2][8][4] = {};
    const int KT = NN / 32;

    {
        const float* a = Bmb  + (size_t)kr * MM + m0 + f8;
        const float* c = ctxb + (size_t)kr * DD + d0 + f8;
        #pragma unroll
        for (int i = 0; i < 4; i++) { cp16(aCp + i * 128, a + i * 32); cp16(bCp + i * 128, c + i * 32); }
        cp_commit();
    }

    for (int kt = 0; kt < KT; kt++) {
        int buf = kt & 1;
        cp_wait0();
        __syncthreads();
        if (kt + 1 < KT) {
            uint32_t poff = buf ? 0 : STG;
            int k0 = (kt + 1) * 32;
            const float* a = Bmb  + (size_t)(k0 + kr) * MM + m0 + f8;
            const float* c = ctxb + (size_t)(k0 + kr) * DD + d0 + f8;
            #pragma unroll
            for (int i = 0; i < 4; i++) { cp16(aCp + poff + i * 128, a + i * 32); cp16(bCp + poff + i * 128, c + i * 32); }
            cp_commit();
        }
        #pragma unroll
        for (int kk = 0; kk < 4; kk++) {
            int kb = kk * 8;
            uint32_t a[2][4];
            #pragma unroll
            for (int i = 0; i < 2; i++) {
                int r = wm * 32 + i * 16 + (lane >> 2);
                a[i][0] = __float_as_uint(As[buf][kb + (lane & 3)][r]);
                a[i][1] = __float_as_uint(As[buf][kb + (lane & 3)][r + 8]);
                a[i][2] = __float_as_uint(As[buf][kb + 4 + (lane & 3)][r]);
                a[i][3] = __float_as_uint(As[buf][kb + 4 + (lane & 3)][r + 8]);
            }
            #pragma unroll
            for (int j = 0; j < 8; j++) {
                int c = wd * 64 + j * 8 + (lane >> 2);
                uint32_t bf[2];
                bf[0] = __float_as_uint(Bs[buf][kb + (lane & 3)][c]);
                bf[1] = __float_as_uint(Bs[buf][kb + 4 + (lane & 3)][c]);
                mma8(acc[0][j], a[0], bf);
                mma8(acc[1][j], a[1], bf);
            }
        }
    }

    // write transposed: midT[d][m]
    #pragma unroll
    for (int i = 0; i < 2; i++) {
        int r = wm * 32 + i * 16 + (lane >> 2);     // m-local
        #pragma unroll
        for (int j = 0; j < 8; j++) {
            int c = wd * 64 + j * 8 + 2 * (lane & 3);  // d-local
            float* p0 = g_midT + ((size_t)b * DD + d0 + c) * MM + m0 + r;
            float* p1 = g_midT + ((size_t)b * DD + d0 + c + 1) * MM + m0 + r;
            p0[0] = acc[i][j][0]; p1[0] = acc[i][j][1];
            p0[8] = acc[i][j][2]; p1[8] = acc[i][j][3];
        }
    }
}

// -------------------- out: c2q = A@qry, q2c = A@mid, ldmatrix, 1-barrier ---------
__global__ void __launch_bounds__(256, 2) k_out_mma(const float* __restrict__ ctx,
                                                    float* __restrict__ out) {
    extern __shared__ float sm[];
    float (*As)[128][36] = (float(*)[128][36])sm;                        // [stage][n][k]
    float (*Bq)[64][36]  = (float(*)[64][36])(sm + 2 * 128 * 36);        // [stage][d][k]
    float (*Bm2)[64][36] = (float(*)[64][36])(sm + 2 * 128 * 36 + 2 * 64 * 36);
    const uint32_t STG_A = 128 * 36 * 4, STG_B = 64 * 36 * 4;

    int b = blockIdx.z, d0 = blockIdx.x * 64, n0 = blockIdx.y * 128;
    int tid = threadIdx.x, lane = tid & 31, warp = tid >> 5;
    int wn = warp & 3, wd = warp >> 2;

    const float* Ab  = g_A    + ((size_t)b * NN + n0) * MM;
    const float* qTb = g_qT   + (size_t)b * DD * MM;
    const float* mTb = g_midT + (size_t)b * DD * MM;

    float accq[2][4][4] = {};
    float accm[2][4][4] = {};

    int lr = tid >> 1, lf = (tid & 1) * 16;       // A loads (128 rows x 32k)
    int lr2 = tid >> 2, lc2 = (tid & 3) * 4;      // B loads (64 rows x 32k)
    uint32_t aCp = s2u(&As[0][lr][lf]);
    uint32_t qCp = s2u(&Bq[0][lr2][lc2]);
    uint32_t mCp = s2u(&Bm2[0][lr2][lc2]);

    int g = lane >> 3, lr8 = lane & 7;
    uint32_t aLd[2], bqLd[2], bmLd[2];
    #pragma unroll
    for (int i = 0; i < 2; i++)
        aLd[i] = s2u(&As[0][wn * 32 + i * 16 + (g & 1) * 8 + lr8][(g >> 1) * 4]);
    #pragma unroll
    for (int j2 = 0; j2 < 2; j2++) {
        bqLd[j2] = s2u(&Bq[0][wd * 32 + j2 * 16 + (g >> 1) * 8 + lr8][(g & 1) * 4]);
        bmLd[j2] = s2u(&Bm2[0][wd * 32 + j2 * 16 + (g >> 1) * 8 + lr8][(g & 1) * 4]);
    }

    const int KT = MM / 32;

    {
        const float* a = Ab + (size_t)lr * MM + lf;
        const float* q = qTb + (size_t)(d0 + lr2) * MM + lc2;
        const float* m = mTb + (size_t)(d0 + lr2) * MM + lc2;
        #pragma unroll
        for (int i = 0; i < 4; i++) cp16(aCp + i * 16, a + i * 4);
        cp16(qCp, q);           cp16(qCp + 64, q + 16);
        cp16(mCp, m);           cp16(mCp + 64, m + 16);
        cp_commit();
    }

    for (int kt = 0; kt < KT; kt++) {
        uint32_t boffA = (kt & 1) ? STG_A : 0;
        uint32_t boffB = (kt & 1) ? STG_B : 0;
        cp_wait0();
        __syncthreads();
        if (kt + 1 < KT) {
            uint32_t poffA = (kt & 1) ? 0 : STG_A;
            uint32_t poffB = (kt & 1) ? 0 : STG_B;
            int k0 = (kt + 1) * 32;
            const float* a = Ab + (size_t)lr * MM + k0 + lf;
            const float* q = qTb + (size_t)(d0 + lr2) * MM + k0 + lc2;
            const float* m = mTb + (size_t)(d0 + lr2) * MM + k0 + lc2;
            #pragma unroll
            for (int i = 0; i < 4; i++) cp16(aCp + poffA + i * 16, a + i * 4);
            cp16(qCp + poffB, q);      cp16(qCp + poffB + 64, q + 16);
            cp16(mCp + poffB, m);      cp16(mCp + poffB + 64, m + 16);
            cp_commit();
        }
        #pragma unroll
        for (int kk = 0; kk < 4; kk++) {
            uint32_t koA = boffA + kk * 32;
            uint32_t koB = boffB + kk * 32;
            uint32_t a0[4], a1[4];
            ldsm4(a0, aLd[0] + koA);
            ldsm4(a1, aLd[1] + koA);
            #pragma unroll
            for (int j2 = 0; j2 < 2; j2++) {
                uint32_t bq[4], bm[4];
                ldsm4(bq, bqLd[j2] + koB);
                mma8(accq[0][2 * j2],     a0, bq);
                mma8(accq[0][2 * j2 + 1], a0, bq + 2);
                mma8(accq[1][2 * j2],     a1, bq);
                mma8(accq[1][2 * j2 + 1], a1, bq + 2);
                ldsm4(bm, bmLd[j2] + koB);
                mma8(accm[0][2 * j2],     a0, bm);
                mma8(accm[0][2 * j2 + 1], a0, bm + 2);
                mma8(accm[1][2 * j2],     a1, bm);
                mma8(accm[1][2 * j2 + 1], a1, bm + 2);
            }
        }
    }

    // epilogue: out = [ctx, c2q, ctx*c2q, ctx*q2c]
    #pragma unroll
    for (int i = 0; i < 2; i++) {
        #pragma unroll
        for (int half = 0; half < 2; half++) {
            int n = n0 + wn * 32 + i * 16 + (lane >> 2) + half * 8;
            const float* crow = ctx + ((size_t)b * NN + n) * DD;
            float* orow = out + ((size_t)b * NN + n) * (4 * DD);
            #pragma unroll
            for (int j = 0; j < 4; j++) {
                int d = d0 + wd * 32 + j * 8 + 2 * (lane & 3);
                float2 cv = *(const float2*)(crow + d);
                float c2q0 = accq[i][j][half * 2], c2q1 = accq[i][j][half * 2 + 1];
                float q2c0 = accm[i][j][half * 2], q2c1 = accm[i][j][half * 2 + 1];
                *(float2*)(orow + d)          = cv;
                *(float2*)(orow + DD + d)     = make_float2(c2q0, c2q1);
                *(float2*)(orow + 2 * DD + d) = make_float2(cv.x * c2q0, cv.y * c2q1);
                *(float2*)(orow + 3 * DD + d) = make_float2(cv.x * q2c0, cv.y * q2c1);
            }
        }
    }
}

// -------------------- launch --------------------
extern "C" void kernel_launch(void* const* d_in, const int* in_sizes, int n_in,
                              void* d_out, int out_size) {
    const float* ctx = (const float*)d_in[0];
    const float* qry = (const float*)d_in[1];
    const unsigned char* cm = (const unsigned char*)d_in[2];
    const unsigned char* qm = (const unsigned char*)d_in[3];
    const float* w = (const float*)d_in[4];
    float* out = (float*)d_out;

    const int SMEM_S   = 2 * 128 * 36 * 4 * 2;                 // 73728
    const int SMEM_MID = 2 * 32 * 136 * 4 * 2;                 // 69632
    const int SMEM_OUT = (2 * 128 * 36 + 4 * 64 * 36) * 4;     // 73728

    cudaFuncSetAttribute(k_S_mma,   cudaFuncAttributeMaxDynamicSharedMemorySize, SMEM_S);
    cudaFuncSetAttribute(k_mid_mma, cudaFuncAttributeMaxDynamicSharedMemorySize, SMEM_MID);
    cudaFuncSetAttribute(k_out_mma, cudaFuncAttributeMaxDynamicSharedMemorySize, SMEM_OUT);

    k_lens<<<1, 64>>>(cm, qm);
    k_rowdots<<<(BB * NN + BB * MM) / 8, 256>>>(ctx, qry, w);
    k_scale<<<(BB * MM * DD) / (4 * 256), 256>>>(qry, w);
    k_tq<<<dim3(MM / 32, DD / 32, BB), dim3(32, 8)>>>(qry);
    k_S_mma<<<dim3(NN / 128, MM / 128, BB), 256, SMEM_S>>>(ctx);
    k_rowsoft<<<BB * NN / 8, 256>>>();
    k_bm<<<dim3(MM / 32, BB), 256>>>();
    k_mid_mma<<<dim3(DD / 128, MM / 128, BB), 256, SMEM_MID>>>(ctx);
    k_out_mma<<<dim3(DD / 64, NN / 128, BB), 256, SMEM_OUT>>>(ctx, out);
}

// round 5
// speedup vs baseline: 2.2779x; 1.0330x over previous
#include <cuda_runtime.h>
#include <cstdint>
#include <cstddef>

#define BB 32
#define NN 1024
#define MM 256
#define DD 512
#define NSPLIT 8

// -------------------- device scratch --------------------
__device__ __align__(128) float g_S  [(size_t)BB * NN * MM];
__device__ __align__(128) float g_A  [(size_t)BB * NN * MM];
__device__ __align__(128) float g_Bm [(size_t)BB * NN * MM];
__device__ __align__(128) float g_midT[(size_t)BB * DD * MM];  // mid transposed [d][m]
__device__ __align__(128) float g_qs [(size_t)BB * MM * DD];   // query * w_m
__device__ __align__(128) float g_qT [(size_t)BB * DD * MM];   // query transposed [d][m]
__device__ float g_pmax[BB][NSPLIT][MM];
__device__ float g_psum[BB][NSPLIT][MM];
__device__ float g_cw[BB * NN];
__device__ float g_qw[BB * MM];
__device__ int   g_clen[BB];
__device__ int   g_qlen[BB];

// -------------------- helpers --------------------
__device__ __forceinline__ void mma8(float* c, const uint32_t* a, const uint32_t* b) {
    asm volatile(
        "mma.sync.aligned.m16n8k8.row.col.f32.tf32.tf32.f32 "
        "{%0,%1,%2,%3}, {%4,%5,%6,%7}, {%8,%9}, {%0,%1,%2,%3};"
        : "+f"(c[0]), "+f"(c[1]), "+f"(c[2]), "+f"(c[3])
        : "r"(a[0]), "r"(a[1]), "r"(a[2]), "r"(a[3]), "r"(b[0]), "r"(b[1]));
}

__device__ __forceinline__ void ldsm4(uint32_t* r, uint32_t addr) {
    asm volatile("ldmatrix.sync.aligned.m8n8.x4.shared.b16 {%0,%1,%2,%3}, [%4];"
                 : "=r"(r[0]), "=r"(r[1]), "=r"(r[2]), "=r"(r[3]) : "r"(addr));
}

__device__ __forceinline__ uint32_t s2u(const void* p) {
    return (uint32_t)__cvta_generic_to_shared(p);
}

__device__ __forceinline__ void cp16(uint32_t dst, const void* src) {
    asm volatile("cp.async.cg.shared.global [%0], [%1], 16;" :: "r"(dst), "l"(src));
}
__device__ __forceinline__ void cp_commit() {
    asm volatile("cp.async.commit_group;");
}
__device__ __forceinline__ void cp_wait1() {
    asm volatile("cp.async.wait_group 1;");
}

// -------------------- mask length detection --------------------
__device__ __forceinline__ int count_prefix(const unsigned char* p, int length,
                                            int esize, unsigned val) {
    int c = 0;
    for (int i = 0; i < length; i++) {
        unsigned v;
        if (esize == 1)      v = p[i];
        else if (esize == 2) v = ((const unsigned short*)p)[i];
        else                 v = ((const unsigned*)p)[i];
        if (v != val) break;
        c++;
    }
    return c;
}

__device__ void detect_fmt(const unsigned char* p, int length, int minlen,
                           int* esize, unsigned* val) {
    const int es[4]      = {1, 2, 4, 4};
    const unsigned vv[4] = {1u, 0x3F80u, 1u, 0x3F800000u};
    for (int k = 0; k < 4; k++) {
        if (count_prefix(p, length, es[k], vv[k]) >= minlen) {
            *esize = es[k]; *val = vv[k]; return;
        }
    }
    *esize = 4; *val = 1u;
}

__global__ void k_lens(const unsigned char* __restrict__ cm,
                       const unsigned char* __restrict__ qm) {
    __shared__ int es_c, es_q;
    __shared__ unsigned v_c, v_q;
    int t = threadIdx.x;
    if (t == 0) detect_fmt(cm, NN, NN / 4, &es_c, &v_c);
    if (t == 1) detect_fmt(qm, MM, MM / 4, &es_q, &v_q);
    __syncthreads();
    if (t < BB) {
        g_clen[t] = count_prefix(cm + (size_t)t * NN * es_c, NN, es_c, v_c);
    } else if (t < 2 * BB) {
        int b = t - BB;
        g_qlen[b] = count_prefix(qm + (size_t)b * MM * es_q, MM, es_q, v_q);
    }
}

// -------------------- cw = ctx @ w_c, qw = query @ w_q --------------------
__global__ void __launch_bounds__(256) k_rowdots(const float* __restrict__ ctx,
                                                 const float* __restrict__ qry,
                                                 const float* __restrict__ w) {
    int warp = threadIdx.x >> 5, lane = threadIdx.x & 31;
    int row = blockIdx.x * 8 + warp;
    const float* src; const float* wp; float* dst;
    if (row < BB * NN) {
        src = ctx + (size_t)row * DD; wp = w + DD;
        dst = g_cw + row;
    } else {
        int r = row - BB * NN;
        src = qry + (size_t)r * DD; wp = w;
        dst = g_qw + r;
    }
    float s = 0.f;
    #pragma unroll
    for (int d = lane * 4; d < DD; d += 128) {
        float4 v  = *(const float4*)(src + d);
        float4 wv = *(const float4*)(wp + d);
        s += v.x * wv.x + v.y * wv.y + v.z * wv.z + v.w * wv.w;
    }
    #pragma unroll
    for (int o = 16; o; o >>= 1) s += __shfl_xor_sync(0xFFFFFFFFu, s, o);
    if (lane == 0) *dst = s;
}

// -------------------- qs = query * w_m --------------------
__global__ void __launch_bounds__(256) k_scale(const float* __restrict__ qry,
                                               const float* __restrict__ w) {
    int i4 = blockIdx.x * 256 + threadIdx.x;
    int d4 = i4 & (DD / 4 - 1);
    float4 v  = *(const float4*)(qry + (size_t)i4 * 4);
    float4 wm = *(const float4*)(w + 2 * DD + d4 * 4);
    v.x *= wm.x; v.y *= wm.y; v.z *= wm.z; v.w *= wm.w;
    *(float4*)(g_qs + (size_t)i4 * 4) = v;
}

// -------------------- qT[b][d][m] = qry[b][m][d] --------------------
__global__ void k_tq(const float* __restrict__ qry) {
    __shared__ float t[32][33];
    int b = blockIdx.z, m0 = blockIdx.x * 32, d0 = blockIdx.y * 32;
    int tx = threadIdx.x, ty = threadIdx.y;
    const float* src = qry + ((size_t)b * MM + m0) * DD + d0;
    #pragma unroll
    for (int i = 0; i < 4; i++) t[ty + 8 * i][tx] = src[(size_t)(ty + 8 * i) * DD + tx];
    __syncthreads();
    float* dst = g_qT + ((size_t)b * DD + d0) * MM + m0;
    #pragma unroll
    for (int i = 0; i < 4; i++) dst[(size_t)(ty + 8 * i) * MM + tx] = t[tx][ty + 8 * i];
}

// -------------------- S = ctx . qs^T, tf32 mma + ldmatrix, 3-stage ---------------
// block 128n x 128m, BK=32, warps 4(n) x 2(m).
__global__ void __launch_bounds__(256, 2) k_S_mma(const float* __restrict__ ctx) {
    extern __shared__ float sm[];
    // stage s: A at sm + s*9216 (128x36), B at +4608 (128x36)
    __shared__ float cw_s[128], qw_s[128];
    const uint32_t STGB = 9216 * 4;

    int b = blockIdx.z, n0 = blockIdx.x * 128, m0 = blockIdx.y * 128;
    int tid = threadIdx.x, lane = tid & 31, warp = tid >> 5;
    int wn = warp & 3, wmw = warp >> 2;

    if (tid < 128) cw_s[tid] = g_cw[b * NN + n0 + tid];
    else           qw_s[tid - 128] = g_qw[b * MM + m0 + (tid - 128)];

    const float* ctxb = ctx  + ((size_t)b * NN + n0) * DD;
    const float* qsb  = g_qs + ((size_t)b * MM + m0) * DD;

    int lr = tid >> 1, lf = (tid & 1) * 16;
    uint32_t aCp = s2u(sm) + (lr * 36 + lf) * 4;
    uint32_t bCp = s2u(sm) + (4608 + lr * 36 + lf) * 4;

    int g = lane >> 3, lr8 = lane & 7;
    uint32_t aLd[2], bLd[4];
    #pragma unroll
    for (int i = 0; i < 2; i++)
        aLd[i] = s2u(sm) + ((wn * 32 + i * 16 + (g & 1) * 8 + lr8) * 36 + (g >> 1) * 4) * 4;
    #pragma unroll
    for (int jj = 0; jj < 4; jj++)
        bLd[jj] = s2u(sm) + (4608 + (wmw * 64 + jj * 16 + (g >> 1) * 8 + lr8) * 36 + (g & 1) * 4) * 4;

    float acc[2][8][4] = {};
    const int KT = DD / 32;

    #pragma unroll
    for (int s = 0; s < 2; s++) {
        const float* a = ctxb + (size_t)lr * DD + s * 32 + lf;
        const float* q = qsb  + (size_t)lr * DD + s * 32 + lf;
        #pragma unroll
        for (int i = 0; i < 4; i++) { cp16(aCp + s * STGB + i * 16, a + i * 4); cp16(bCp + s * STGB + i * 16, q + i * 4); }
        cp_commit();
    }

    int st = 0, pst = 2;
    for (int kt = 0; kt < KT; kt++) {
        cp_wait1();
        __syncthreads();
        if (kt + 2 < KT) {
            int k0 = (kt + 2) * 32;
            const float* a = ctxb + (size_t)lr * DD + k0 + lf;
            const float* q = qsb  + (size_t)lr * DD + k0 + lf;
            uint32_t poff = pst * STGB;
            #pragma unroll
            for (int i = 0; i < 4; i++) { cp16(aCp + poff + i * 16, a + i * 4); cp16(bCp + poff + i * 16, q + i * 4); }
        }
        cp_commit();
        uint32_t boff = st * STGB;
        #pragma unroll
        for (int kk = 0; kk < 4; kk++) {
            uint32_t ko = boff + kk * 32;
            uint32_t a0[4], a1[4];
            ldsm4(a0, aLd[0] + ko);
            ldsm4(a1, aLd[1] + ko);
            #pragma unroll
            for (int jj = 0; jj < 4; jj++) {
                uint32_t bb[4];
                ldsm4(bb, bLd[jj] + ko);
                mma8(acc[0][2 * jj],     a0, bb);
                mma8(acc[0][2 * jj + 1], a0, bb + 2);
                mma8(acc[1][2 * jj],     a1, bb);
                mma8(acc[1][2 * jj + 1], a1, bb + 2);
            }
        }
        st  = (st  + 1 == 3) ? 0 : st  + 1;
        pst = (pst + 1 == 3) ? 0 : pst + 1;
    }

    float* Sb = g_S + ((size_t)b * NN + n0) * MM + m0;
    #pragma unroll
    for (int i = 0; i < 2; i++) {
        int r = wn * 32 + i * 16 + (lane >> 2);
        float cw0 = cw_s[r], cw1 = cw_s[r + 8];
        #pragma unroll
        for (int j = 0; j < 8; j++) {
            int c = wmw * 64 + j * 8 + 2 * (lane & 3);
            float q0 = qw_s[c], q1 = qw_s[c + 1];
            *(float2*)(Sb + (size_t)r * MM + c)       = make_float2(acc[i][j][0] + cw0 + q0, acc[i][j][1] + cw0 + q1);
            *(float2*)(Sb + (size_t)(r + 8) * MM + c) = make_float2(acc[i][j][2] + cw1 + q0, acc[i][j][3] + cw1 + q1);
        }
    }
}

// -------------------- row softmax: A = softmax_m(S, q-masked) --------------------
__global__ void __launch_bounds__(256) k_rowsoft() {
    int row  = blockIdx.x * 8 + (threadIdx.x >> 5);
    int lane = threadIdx.x & 31;
    int b    = row >> 10;
    int qlen = g_qlen[b];
    const float* Sr = g_S + (size_t)row * MM;
    float4 v0 = *(const float4*)(Sr + lane * 4);
    float4 v1 = *(const float4*)(Sr + 128 + lane * 4);
    float s[8] = {v0.x, v0.y, v0.z, v0.w, v1.x, v1.y, v1.z, v1.w};
    int   mi[8];
    #pragma unroll
    for (int j = 0; j < 4; j++) { mi[j] = lane * 4 + j; mi[j + 4] = 128 + lane * 4 + j; }

    float mx = -1e30f;
    #pragma unroll
    for (int j = 0; j < 8; j++) if (mi[j] < qlen) mx = fmaxf(mx, s[j]);
    #pragma unroll
    for (int o = 16; o; o >>= 1) mx = fmaxf(mx, __shfl_xor_sync(0xFFFFFFFFu, mx, o));

    float e[8], sum = 0.f;
    #pragma unroll
    for (int j = 0; j < 8; j++) {
        e[j] = (mi[j] < qlen) ? __expf(s[j] - mx) : 0.f;
        sum += e[j];
    }
    #pragma unroll
    for (int o = 16; o; o >>= 1) sum += __shfl_xor_sync(0xFFFFFFFFu, sum, o);
    float inv = 1.f / sum;

    float* Ar = g_A + (size_t)row * MM;
    *(float4*)(Ar + lane * 4)       = make_float4(e[0] * inv, e[1] * inv, e[2] * inv, e[3] * inv);
    *(float4*)(Ar + 128 + lane * 4) = make_float4(e[4] * inv, e[5] * inv, e[6] * inv, e[7] * inv);
}

// -------------------- k_bm1: per-(b, nsplit, m) partial max/sum ------------------
// grid (MM/32, NSPLIT, BB), 256 thr: warp p handles rows nsplit*128 + p + 8*it.
__global__ void __launch_bounds__(256) k_bm1() {
    int b = blockIdx.z, ns = blockIdx.y;
    int lane = threadIdx.x & 31, p = threadIdx.x >> 5;
    int m = blockIdx.x * 32 + lane;
    int clen = g_clen[b];
    const float* Sc = g_S + (size_t)b * NN * MM + m;

    float vals[16];
    #pragma unroll
    for (int it = 0; it < 16; it++) {
        int n = ns * 128 + p + it * 8;
        vals[it] = (n < clen) ? Sc[(size_t)n * MM] : -1e30f;
    }
    float mx = -1e30f;
    #pragma unroll
    for (int it = 0; it < 16; it++) mx = fmaxf(mx, vals[it]);

    __shared__ float red[8][32];
    red[p][lane] = mx;
    __syncthreads();
    float bmax = red[0][lane];
    #pragma unroll
    for (int q = 1; q < 8; q++) bmax = fmaxf(bmax, red[q][lane]);
    __syncthreads();

    float sum = 0.f;
    #pragma unroll
    for (int it = 0; it < 16; it++)
        if (vals[it] > -1e29f) sum += __expf(vals[it] - bmax);
    red[p][lane] = sum;
    __syncthreads();
    if (p == 0) {
        float ts = 0.f;
        #pragma unroll
        for (int q = 0; q < 8; q++) ts += red[q][lane];
        g_pmax[b][ns][m] = bmax;
        g_psum[b][ns][m] = ts;
    }
}

// -------------------- k_bm2: combine partials, write Bm --------------------------
// grid (MM/32, NSPLIT, BB), 256 thr.
__global__ void __launch_bounds__(256) k_bm2() {
    int b = blockIdx.z, ns = blockIdx.y;
    int lane = threadIdx.x & 31, p = threadIdx.x >> 5;
    int m = blockIdx.x * 32 + lane;
    int clen = g_clen[b];

    __shared__ float fmv[32], invv[32];
    if (threadIdx.x < 32) {
        float fm = -1e30f;
        #pragma unroll
        for (int q = 0; q < NSPLIT; q++) fm = fmaxf(fm, g_pmax[b][q][m]);
        float fs = 0.f;
        #pragma unroll
        for (int q = 0; q < NSPLIT; q++) {
            float pm = g_pmax[b][q][m];
            if (pm > -1e29f) fs += g_psum[b][q][m] * __expf(pm - fm);
        }
        fmv[threadIdx.x] = fm;
        invv[threadIdx.x] = 1.f / fs;
    }
    __syncthreads();

    float fm = fmv[lane], inv = invv[lane];
    const float* Sc = g_S  + (size_t)b * NN * MM + m;
    float*       Bc = g_Bm + (size_t)b * NN * MM + m;
    #pragma unroll
    for (int it = 0; it < 16; it++) {
        int n = ns * 128 + p + it * 8;
        float v = (n < clen) ? __expf(Sc[(size_t)n * MM] - fm) * inv : 0.f;
        Bc[(size_t)n * MM] = v;
    }
}

// -------------------- midT[d][m] = (Bm^T @ ctx)^T, tf32 mma, 3-stage -------------
__global__ void __launch_bounds__(256, 2) k_mid_mma(const float* __restrict__ ctx) {
    extern __shared__ float sm[];
    // stage s: As (32x136) at sm + s*8704, Bs at +4352
    const uint32_t STGB = 8704 * 4;

    int b = blockIdx.z, d0 = blockIdx.x * 128, m0 = blockIdx.y * 128;
    int tid = threadIdx.x, lane = tid & 31, warp = tid >> 5;
    int wm = warp & 3, wd = warp >> 2;

    const float* Bmb  = g_Bm + (size_t)b * NN * MM;
    const float* ctxb = ctx  + (size_t)b * NN * DD;

    int kr = tid >> 3, f8 = (tid & 7) * 4;
    uint32_t aCp = s2u(sm) + (kr * 136 + f8) * 4;
    uint32_t bCp = s2u(sm) + (4352 + kr * 136 + f8) * 4;

    float acc[2][8][4] = {};
    const int KT = NN / 32;

    #pragma unroll
    for (int s = 0; s < 2; s++) {
        const float* a = Bmb  + (size_t)(s * 32 + kr) * MM + m0 + f8;
        const float* c = ctxb + (size_t)(s * 32 + kr) * DD + d0 + f8;
        #pragma unroll
        for (int i = 0; i < 4; i++) { cp16(aCp + s * STGB + i * 128, a + i * 32); cp16(bCp + s * STGB + i * 128, c + i * 32); }
        cp_commit();
    }

    int st = 0, pst = 2;
    for (int kt = 0; kt < KT; kt++) {
        cp_wait1();
        __syncthreads();
        if (kt + 2 < KT) {
            int k0 = (kt + 2) * 32;
            const float* a = Bmb  + (size_t)(k0 + kr) * MM + m0 + f8;
            const float* c = ctxb + (size_t)(k0 + kr) * DD + d0 + f8;
            uint32_t poff = pst * STGB;
            #pragma unroll
            for (int i = 0; i < 4; i++) { cp16(aCp + poff + i * 128, a + i * 32); cp16(bCp + poff + i * 128, c + i * 32); }
        }
        cp_commit();
        const float* As = sm + st * 8704;
        const float* Bs = sm + st * 8704 + 4352;
        #pragma unroll
        for (int kk = 0; kk < 4; kk++) {
            int kb = kk * 8;
            uint32_t a[2][4];
            #pragma unroll
            for (int i = 0; i < 2; i++) {
                int r = wm * 32 + i * 16 + (lane >> 2);
                a[i][0] = __float_as_uint(As[(kb + (lane & 3)) * 136 + r]);
                a[i][1] = __float_as_uint(As[(kb + (lane & 3)) * 136 + r + 8]);
                a[i][2] = __float_as_uint(As[(kb + 4 + (lane & 3)) * 136 + r]);
                a[i][3] = __float_as_uint(As[(kb + 4 + (lane & 3)) * 136 + r + 8]);
            }
            #pragma unroll
            for (int j = 0; j < 8; j++) {
                int c = wd * 64 + j * 8 + (lane >> 2);
                uint32_t bf[2];
                bf[0] = __float_as_uint(Bs[(kb + (lane & 3)) * 136 + c]);
                bf[1] = __float_as_uint(Bs[(kb + 4 + (lane & 3)) * 136 + c]);
                mma8(acc[0][j], a[0], bf);
                mma8(acc[1][j], a[1], bf);
            }
        }
        st  = (st  + 1 == 3) ? 0 : st  + 1;
        pst = (pst + 1 == 3) ? 0 : pst + 1;
    }

    #pragma unroll
    for (int i = 0; i < 2; i++) {
        int r = wm * 32 + i * 16 + (lane >> 2);
        #pragma unroll
        for (int j = 0; j < 8; j++) {
            int c = wd * 64 + j * 8 + 2 * (lane & 3);
            float* p0 = g_midT + ((size_t)b * DD + d0 + c) * MM + m0 + r;
            float* p1 = g_midT + ((size_t)b * DD + d0 + c + 1) * MM + m0 + r;
            p0[0] = acc[i][j][0]; p1[0] = acc[i][j][1];
            p0[8] = acc[i][j][2]; p1[8] = acc[i][j][3];
        }
    }
}

// -------------------- out: c2q = A@qry, q2c = A@mid, 64x64 tiles, 3-stage --------
// block 64n x 64d, BK=32(m), 8 warps: wn=warp&1 (32n), wd=warp>>1 (16d).
__global__ void __launch_bounds__(256, 2) k_out_mma(const float* __restrict__ ctx,
                                                    float* __restrict__ out) {
    extern __shared__ float sm[];
    // stage s (6912 floats): A (64x36) at +0, Bq at +2304, Bm at +4608
    const uint32_t STGB = 6912 * 4;

    int b = blockIdx.z, d0 = blockIdx.x * 64, n0 = blockIdx.y * 64;
    int tid = threadIdx.x, lane = tid & 31, warp = tid >> 5;
    int wn = warp & 1, wd = warp >> 1;

    const float* Ab  = g_A    + ((size_t)b * NN + n0) * MM;
    const float* qTb = g_qT   + ((size_t)b * DD + d0) * MM;
    const float* mTb = g_midT + ((size_t)b * DD + d0) * MM;

    float accq[2][2][4] = {};
    float accm[2][2][4] = {};

    int lr = tid >> 2, lc = (tid & 3) * 4;   // row 0..63, float col {lc, lc+16}
    uint32_t aCp = s2u(sm) + (lr * 36 + lc) * 4;
    uint32_t qCp = s2u(sm) + (2304 + lr * 36 + lc) * 4;
    uint32_t mCp = s2u(sm) + (4608 + lr * 36 + lc) * 4;

    int g = lane >> 3, lr8 = lane & 7;
    uint32_t aLd[2], bqLd, bmLd;
    #pragma unroll
    for (int i = 0; i < 2; i++)
        aLd[i] = s2u(sm) + ((wn * 32 + i * 16 + (g & 1) * 8 + lr8) * 36 + (g >> 1) * 4) * 4;
    bqLd = s2u(sm) + (2304 + (wd * 16 + (g >> 1) * 8 + lr8) * 36 + (g & 1) * 4) * 4;
    bmLd = s2u(sm) + (4608 + (wd * 16 + (g >> 1) * 8 + lr8) * 36 + (g & 1) * 4) * 4;

    const int KT = MM / 32;

    #pragma unroll
    for (int s = 0; s < 2; s++) {
        int k0 = s * 32;
        const float* a = Ab  + (size_t)lr * MM + k0 + lc;
        const float* q = qTb + (size_t)lr * MM + k0 + lc;
        const float* m = mTb + (size_t)lr * MM + k0 + lc;
        uint32_t o = s * STGB;
        cp16(aCp + o, a);  cp16(aCp + o + 64, a + 16);
        cp16(qCp + o, q);  cp16(qCp + o + 64, q + 16);
        cp16(mCp + o, m);  cp16(mCp + o + 64, m + 16);
        cp_commit();
    }

    int st = 0, pst = 2;
    for (int kt = 0; kt < KT; kt++) {
        cp_wait1();
        __syncthreads();
        if (kt + 2 < KT) {
            int k0 = (kt + 2) * 32;
            const float* a = Ab  + (size_t)lr * MM + k0 + lc;
            const float* q = qTb + (size_t)lr * MM + k0 + lc;
            const float* m = mTb + (size_t)lr * MM + k0 + lc;
            uint32_t o = pst * STGB;
            cp16(aCp + o, a);  cp16(aCp + o + 64, a + 16);
            cp16(qCp + o, q);  cp16(qCp + o + 64, q + 16);
            cp16(mCp + o, m);  cp16(mCp + o + 64, m + 16);
        }
        cp_commit();
        uint32_t boff = st * STGB;
        #pragma unroll
        for (int kk = 0; kk < 4; kk++) {
            uint32_t ko = boff + kk * 32;
            uint32_t a0[4], a1[4], bq[4], bm[4];
            ldsm4(a0, aLd[0] + ko);
            ldsm4(a1, aLd[1] + ko);
            ldsm4(bq, bqLd + ko);
            ldsm4(bm, bmLd + ko);
            mma8(accq[0][0], a0, bq);
            mma8(accq[0][1], a0, bq + 2);
            mma8(accq[1][0], a1, bq);
            mma8(accq[1][1], a1, bq + 2);
            mma8(accm[0][0], a0, bm);
            mma8(accm[0][1], a0, bm + 2);
            mma8(accm[1][0], a1, bm);
            mma8(accm[1][1], a1, bm + 2);
        }
        st  = (st  + 1 == 3) ? 0 : st  + 1;
        pst = (pst + 1 == 3) ? 0 : pst + 1;
    }

    // epilogue: out = [ctx, c2q, ctx*c2q, ctx*q2c]
    #pragma unroll
    for (int i = 0; i < 2; i++) {
        #pragma unroll
        for (int half = 0; half < 2; half++) {
            int n = n0 + wn * 32 + i * 16 + (lane >> 2) + half * 8;
            const float* crow = ctx + ((size_t)b * NN + n) * DD;
            float* orow = out + ((size_t)b * NN + n) * (4 * DD);
            #pragma unroll
            for (int jh = 0; jh < 2; jh++) {
                int d = d0 + wd * 16 + jh * 8 + 2 * (lane & 3);
                float2 cv = *(const float2*)(crow + d);
                float c2q0 = accq[i][jh][half * 2], c2q1 = accq[i][jh][half * 2 + 1];
                float q2c0 = accm[i][jh][half * 2], q2c1 = accm[i][jh][half * 2 + 1];
                *(float2*)(orow + d)          = cv;
                *(float2*)(orow + DD + d)     = make_float2(c2q0, c2q1);
                *(float2*)(orow + 2 * DD + d) = make_float2(cv.x * c2q0, cv.y * c2q1);
                *(float2*)(orow + 3 * DD + d) = make_float2(cv.x * q2c0, cv.y * q2c1);
            }
        }
    }
}

// -------------------- launch --------------------
extern "C" void kernel_launch(void* const* d_in, const int* in_sizes, int n_in,
                              void* d_out, int out_size) {
    const float* ctx = (const float*)d_in[0];
    const float* qry = (const float*)d_in[1];
    const unsigned char* cm = (const unsigned char*)d_in[2];
    const unsigned char* qm = (const unsigned char*)d_in[3];
    const float* w = (const float*)d_in[4];
    float* out = (float*)d_out;

    const int SMEM_S   = 3 * 9216 * 4;   // 110592
    const int SMEM_MID = 3 * 8704 * 4;   // 104448
    const int SMEM_OUT = 3 * 6912 * 4;   // 82944

    cudaFuncSetAttribute(k_S_mma,   cudaFuncAttributeMaxDynamicSharedMemorySize, SMEM_S);
    cudaFuncSetAttribute(k_mid_mma, cudaFuncAttributeMaxDynamicSharedMemorySize, SMEM_MID);
    cudaFuncSetAttribute(k_out_mma, cudaFuncAttributeMaxDynamicSharedMemorySize, SMEM_OUT);

    k_lens<<<1, 64>>>(cm, qm);
    k_rowdots<<<(BB * NN + BB * MM) / 8, 256>>>(ctx, qry, w);
    k_scale<<<(BB * MM * DD) / (4 * 256), 256>>>(qry, w);
    k_tq<<<dim3(MM / 32, DD / 32, BB), dim3(32, 8)>>>(qry);
    k_S_mma<<<dim3(NN / 128, MM / 128, BB), 256, SMEM_S>>>(ctx);
    k_rowsoft<<<BB * NN / 8, 256>>>();
    k_bm1<<<dim3(MM / 32, NSPLIT, BB), 256>>>();
    k_bm2<<<dim3(MM / 32, NSPLIT, BB), 256>>>();
    k_mid_mma<<<dim3(DD / 128, MM / 128, BB), 256, SMEM_MID>>>(ctx);
    k_out_mma<<<dim3(DD / 64, NN / 64, BB), 256, SMEM_OUT>>>(ctx, out);
}

// round 7
// speedup vs baseline: 2.3689x; 1.0400x over previous
#include <cuda_runtime.h>
#include <cstdint>
#include <cstddef>

#define BB 32
#define NN 1024
#define MM 256
#define DD 512
#define NSPLIT 8

// -------------------- device scratch --------------------
__device__ __align__(128) float g_S  [(size_t)BB * NN * MM];
__device__ __align__(128) float g_A  [(size_t)BB * NN * MM];
__device__ __align__(128) float g_Bm [(size_t)BB * NN * MM];
__device__ __align__(128) float g_midT[(size_t)BB * DD * MM];  // mid transposed [d][m]
__device__ __align__(128) float g_qs [(size_t)BB * MM * DD];   // query * w_m
__device__ __align__(128) float g_qT [(size_t)BB * DD * MM];   // query transposed [d][m]
__device__ float g_pmax[BB][NSPLIT][MM];
__device__ float g_psum[BB][NSPLIT][MM];
__device__ float g_cw[BB * NN];
__device__ float g_qw[BB * MM];
__device__ int   g_clen[BB];
__device__ int   g_qlen[BB];

// -------------------- helpers --------------------
__device__ __forceinline__ void mma8(float* c, const uint32_t* a, const uint32_t* b) {
    asm volatile(
        "mma.sync.aligned.m16n8k8.row.col.f32.tf32.tf32.f32 "
        "{%0,%1,%2,%3}, {%4,%5,%6,%7}, {%8,%9}, {%0,%1,%2,%3};"
        : "+f"(c[0]), "+f"(c[1]), "+f"(c[2]), "+f"(c[3])
        : "r"(a[0]), "r"(a[1]), "r"(a[2]), "r"(a[3]), "r"(b[0]), "r"(b[1]));
}

__device__ __forceinline__ void ldsm4(uint32_t* r, uint32_t addr) {
    asm volatile("ldmatrix.sync.aligned.m8n8.x4.shared.b16 {%0,%1,%2,%3}, [%4];"
                 : "=r"(r[0]), "=r"(r[1]), "=r"(r[2]), "=r"(r[3]) : "r"(addr));
}

__device__ __forceinline__ uint32_t s2u(const void* p) {
    return (uint32_t)__cvta_generic_to_shared(p);
}
__device__ __forceinline__ void cp16(uint32_t dst, const void* src) {
    asm volatile("cp.async.cg.shared.global [%0], [%1], 16;" :: "r"(dst), "l"(src));
}
__device__ __forceinline__ void cp_commit() { asm volatile("cp.async.commit_group;"); }
__device__ __forceinline__ void cp_wait1()  { asm volatile("cp.async.wait_group 1;"); }

// -------------------- mask length detection --------------------
__device__ __forceinline__ int count_prefix(const unsigned char* p, int length,
                                            int esize, unsigned val) {
    int c = 0;
    for (int i = 0; i < length; i++) {
        unsigned v;
        if (esize == 1)      v = p[i];
        else if (esize == 2) v = ((const unsigned short*)p)[i];
        else                 v = ((const unsigned*)p)[i];
        if (v != val) break;
        c++;
    }
    return c;
}

__device__ void detect_fmt(const unsigned char* p, int length, int minlen,
                           int* esize, unsigned* val) {
    const int es[4]      = {1, 2, 4, 4};
    const unsigned vv[4] = {1u, 0x3F80u, 1u, 0x3F800000u};
    for (int k = 0; k < 4; k++) {
        if (count_prefix(p, length, es[k], vv[k]) >= minlen) {
            *esize = es[k]; *val = vv[k]; return;
        }
    }
    *esize = 4; *val = 1u;
}

__global__ void k_lens(const unsigned char* __restrict__ cm,
                       const unsigned char* __restrict__ qm) {
    __shared__ int es_c, es_q;
    __shared__ unsigned v_c, v_q;
    int t = threadIdx.x;
    if (t == 0) detect_fmt(cm, NN, NN / 4, &es_c, &v_c);
    if (t == 1) detect_fmt(qm, MM, MM / 4, &es_q, &v_q);
    __syncthreads();
    if (t < BB) {
        g_clen[t] = count_prefix(cm + (size_t)t * NN * es_c, NN, es_c, v_c);
    } else if (t < 2 * BB) {
        int b = t - BB;
        g_qlen[b] = count_prefix(qm + (size_t)b * MM * es_q, MM, es_q, v_q);
    }
}

// -------------------- cw = ctx @ w_c, qw = query @ w_q --------------------
__global__ void __launch_bounds__(256) k_rowdots(const float* __restrict__ ctx,
                                                 const float* __restrict__ qry,
                                                 const float* __restrict__ w) {
    int warp = threadIdx.x >> 5, lane = threadIdx.x & 31;
    int row = blockIdx.x * 8 + warp;
    const float* src; const float* wp; float* dst;
    if (row < BB * NN) {
        src = ctx + (size_t)row * DD; wp = w + DD;
        dst = g_cw + row;
    } else {
        int r = row - BB * NN;
        src = qry + (size_t)r * DD; wp = w;
        dst = g_qw + r;
    }
    float s = 0.f;
    #pragma unroll
    for (int d = lane * 4; d < DD; d += 128) {
        float4 v  = *(const float4*)(src + d);
        float4 wv = *(const float4*)(wp + d);
        s += v.x * wv.x + v.y * wv.y + v.z * wv.z + v.w * wv.w;
    }
    #pragma unroll
    for (int o = 16; o; o >>= 1) s += __shfl_xor_sync(0xFFFFFFFFu, s, o);
    if (lane == 0) *dst = s;
}

// -------------------- qs = query * w_m --------------------
__global__ void __launch_bounds__(256) k_scale(const float* __restrict__ qry,
                                               const float* __restrict__ w) {
    int i4 = blockIdx.x * 256 + threadIdx.x;
    int d4 = i4 & (DD / 4 - 1);
    float4 v  = *(const float4*)(qry + (size_t)i4 * 4);
    float4 wm = *(const float4*)(w + 2 * DD + d4 * 4);
    v.x *= wm.x; v.y *= wm.y; v.z *= wm.z; v.w *= wm.w;
    *(float4*)(g_qs + (size_t)i4 * 4) = v;
}

// -------------------- qT[b][d][m] = qry[b][m][d] --------------------
__global__ void k_tq(const float* __restrict__ qry) {
    __shared__ float t[32][33];
    int b = blockIdx.z, m0 = blockIdx.x * 32, d0 = blockIdx.y * 32;
    int tx = threadIdx.x, ty = threadIdx.y;
    const float* src = qry + ((size_t)b * MM + m0) * DD + d0;
    #pragma unroll
    for (int i = 0; i < 4; i++) t[ty + 8 * i][tx] = src[(size_t)(ty + 8 * i) * DD + tx];
    __syncthreads();
    float* dst = g_qT + ((size_t)b * DD + d0) * MM + m0;
    #pragma unroll
    for (int i = 0; i < 4; i++) dst[(size_t)(ty + 8 * i) * MM + tx] = t[tx][ty + 8 * i];
}

// ============ k_S_f: S = ctx.qs^T (128n x 256m), fused row softmax + col partials
// 512 thr, 16 warps (wn=warp&3 over n, wm=warp>>2 over m), warp 32n x 64m, BK=32.
#define S_STGF 13824                      // floats per stage: A 128x36 + B 256x36
#define S_STGB (S_STGF * 4)
#define S_BOFF (128 * 36)                 // B offset in floats
#define S_RED  (3 * S_STGF)               // reduction area offset (floats)
__global__ void __launch_bounds__(512, 1) k_S_f(const float* __restrict__ ctx) {
    extern __shared__ float sm[];
    float* rowred  = sm + S_RED;           // [4][128]
    float* colred  = rowred + 512;         // [4][256]
    float* colred2 = colred + 1024;        // [4][256]
    float* cw_s    = colred2 + 1024;       // [128]
    float* qw_s    = cw_s + 128;           // [256]

    int b = blockIdx.y, n0 = blockIdx.x * 128;
    int tid = threadIdx.x, lane = tid & 31, warp = tid >> 5;
    int wn = warp & 3, wm = warp >> 2;
    uint32_t smb = s2u(sm);

    if (tid < 128) cw_s[tid] = g_cw[b * NN + n0 + tid];
    else if (tid < 384) qw_s[tid - 128] = g_qw[b * MM + (tid - 128)];

    const float* ctxb = ctx  + ((size_t)b * NN + n0) * DD;
    const float* qsb  = g_qs + (size_t)b * MM * DD;

    int g = lane >> 3, lr8 = lane & 7;
    uint32_t aLd[2], bLd[4];
    #pragma unroll
    for (int i = 0; i < 2; i++)
        aLd[i] = smb + ((wn * 32 + i * 16 + (g & 1) * 8 + lr8) * 36 + (g >> 1) * 4) * 4;
    #pragma unroll
    for (int jj = 0; jj < 4; jj++)
        bLd[jj] = smb + (S_BOFF + (wm * 64 + jj * 16 + (g >> 1) * 8 + lr8) * 36 + (g & 1) * 4) * 4;

    float acc[2][8][4] = {};
    const int KT = DD / 32;  // 16

    #define SF_LOAD(kt, s) do { \
        uint32_t base = smb + (s) * S_STGB; \
        _Pragma("unroll") \
        for (int r2 = 0; r2 < 2; r2++) { \
            int idx = tid + 512 * r2; int row = idx >> 3, c4 = idx & 7; \
            cp16(base + (row * 36 + c4 * 4) * 4, ctxb + (size_t)row * DD + (kt) * 32 + c4 * 4); \
        } \
        _Pragma("unroll") \
        for (int r2 = 0; r2 < 4; r2++) { \
            int idx = tid + 512 * r2; int row = idx >> 3, c4 = idx & 7; \
            cp16(base + (S_BOFF + row * 36 + c4 * 4) * 4, qsb + (size_t)row * DD + (kt) * 32 + c4 * 4); \
        } \
    } while (0)

    SF_LOAD(0, 0); cp_commit();
    SF_LOAD(1, 1); cp_commit();

    for (int kt = 0; kt < KT; kt++) {
        cp_wait1();
        __syncthreads();
        if (kt + 2 < KT) { SF_LOAD(kt + 2, (kt + 2) % 3); }
        cp_commit();
        uint32_t boff = (kt % 3) * S_STGB;
        #pragma unroll
        for (int kk = 0; kk < 4; kk++) {
            uint32_t ko = boff + kk * 32;
            uint32_t a0[4], a1[4];
            ldsm4(a0, aLd[0] + ko);
            ldsm4(a1, aLd[1] + ko);
            #pragma unroll
            for (int jj = 0; jj < 4; jj++) {
                uint32_t bb[4];
                ldsm4(bb, bLd[jj] + ko);
                mma8(acc[0][2 * jj],     a0, bb);
                mma8(acc[0][2 * jj + 1], a0, bb + 2);
                mma8(acc[1][2 * jj],     a1, bb);
                mma8(acc[1][2 * jj + 1], a1, bb + 2);
            }
        }
    }
    #undef SF_LOAD

    // ======== fused epilogue ========
    int qlen = g_qlen[b], clen = g_clen[b];
    int rbase = wn * 32 + (lane >> 2);
    int cbase = wm * 64 + 2 * (lane & 3);

    // -- pass 1: write S, row maxes --
    float rmax[2][2] = {{-1e30f, -1e30f}, {-1e30f, -1e30f}};
    #pragma unroll
    for (int i = 0; i < 2; i++) {
        #pragma unroll
        for (int h = 0; h < 2; h++) {
            int r = rbase + i * 16 + h * 8;
            float cwv = cw_s[r];
            float* Srow = g_S + ((size_t)b * NN + n0 + r) * MM;
            #pragma unroll
            for (int j = 0; j < 8; j++) {
                int c = cbase + j * 8;
                float s0 = acc[i][j][h * 2]     + cwv + qw_s[c];
                float s1 = acc[i][j][h * 2 + 1] + cwv + qw_s[c + 1];
                *(float2*)(Srow + c) = make_float2(s0, s1);
                if (c < qlen)     rmax[i][h] = fmaxf(rmax[i][h], s0);
                if (c + 1 < qlen) rmax[i][h] = fmaxf(rmax[i][h], s1);
            }
        }
    }
    #pragma unroll
    for (int i = 0; i < 2; i++)
        #pragma unroll
        for (int h = 0; h < 2; h++) {
            #pragma unroll
            for (int o = 1; o <= 2; o <<= 1)
                rmax[i][h] = fmaxf(rmax[i][h], __shfl_xor_sync(0xFFFFFFFFu, rmax[i][h], o));
        }
    if ((lane & 3) == 0) {
        #pragma unroll
        for (int i = 0; i < 2; i++)
            #pragma unroll
            for (int h = 0; h < 2; h++)
                rowred[wm * 128 + rbase + i * 16 + h * 8] = rmax[i][h];
    }
    __syncthreads();
    float frmax[2][2];
    #pragma unroll
    for (int i = 0; i < 2; i++)
        #pragma unroll
        for (int h = 0; h < 2; h++) {
            int r = rbase + i * 16 + h * 8;
            float m = rowred[r];
            #pragma unroll
            for (int q = 1; q < 4; q++) m = fmaxf(m, rowred[q * 128 + r]);
            frmax[i][h] = m;
        }
    __syncthreads();

    // -- pass 2: row sums --
    float rsum[2][2] = {};
    #pragma unroll
    for (int i = 0; i < 2; i++)
        #pragma unroll
        for (int h = 0; h < 2; h++) {
            int r = rbase + i * 16 + h * 8;
            float cwv = cw_s[r];
            #pragma unroll
            for (int j = 0; j < 8; j++) {
                int c = cbase + j * 8;
                if (c < qlen)     rsum[i][h] += __expf(acc[i][j][h * 2]     + cwv + qw_s[c]     - frmax[i][h]);
                if (c + 1 < qlen) rsum[i][h] += __expf(acc[i][j][h * 2 + 1] + cwv + qw_s[c + 1] - frmax[i][h]);
            }
            #pragma unroll
            for (int o = 1; o <= 2; o <<= 1)
                rsum[i][h] += __shfl_xor_sync(0xFFFFFFFFu, rsum[i][h], o);
        }
    if ((lane & 3) == 0) {
        #pragma unroll
        for (int i = 0; i < 2; i++)
            #pragma unroll
            for (int h = 0; h < 2; h++)
                rowred[wm * 128 + rbase + i * 16 + h * 8] = rsum[i][h];
    }
    __syncthreads();
    float rinv[2][2];
    #pragma unroll
    for (int i = 0; i < 2; i++)
        #pragma unroll
        for (int h = 0; h < 2; h++) {
            int r = rbase + i * 16 + h * 8;
            float t = 0.f;
            #pragma unroll
            for (int q = 0; q < 4; q++) t += rowred[q * 128 + r];
            rinv[i][h] = 1.f / t;
        }

    // -- pass 3: write A --
    #pragma unroll
    for (int i = 0; i < 2; i++)
        #pragma unroll
        for (int h = 0; h < 2; h++) {
            int r = rbase + i * 16 + h * 8;
            float cwv = cw_s[r];
            float* Arow = g_A + ((size_t)b * NN + n0 + r) * MM;
            #pragma unroll
            for (int j = 0; j < 8; j++) {
                int c = cbase + j * 8;
                float e0 = (c < qlen)
                    ? __expf(acc[i][j][h * 2] + cwv + qw_s[c] - frmax[i][h]) * rinv[i][h] : 0.f;
                float e1 = (c + 1 < qlen)
                    ? __expf(acc[i][j][h * 2 + 1] + cwv + qw_s[c + 1] - frmax[i][h]) * rinv[i][h] : 0.f;
                *(float2*)(Arow + c) = make_float2(e0, e1);
            }
        }

    // -- pass 4: column max partials over this block's 128 rows --
    #pragma unroll
    for (int j = 0; j < 8; j++) {
        #pragma unroll
        for (int e2 = 0; e2 < 2; e2++) {
            int c = cbase + j * 8 + e2;
            float cm = -1e30f;
            #pragma unroll
            for (int i = 0; i < 2; i++)
                #pragma unroll
                for (int h = 0; h < 2; h++) {
                    int r = rbase + i * 16 + h * 8;
                    if (n0 + r < clen)
                        cm = fmaxf(cm, acc[i][j][h * 2 + e2] + cw_s[r] + qw_s[c]);
                }
            #pragma unroll
            for (int o = 4; o <= 16; o <<= 1)
                cm = fmaxf(cm, __shfl_xor_sync(0xFFFFFFFFu, cm, o));
            if ((lane >> 2) == 0) colred[wn * 256 + c] = cm;
        }
    }
    __syncthreads();

    // -- pass 5: column sum partials (using final block colmax) --
    #pragma unroll
    for (int j = 0; j < 8; j++) {
        #pragma unroll
        for (int e2 = 0; e2 < 2; e2++) {
            int c = cbase + j * 8 + e2;
            float fc = colred[c];
            #pragma unroll
            for (int q = 1; q < 4; q++) fc = fmaxf(fc, colred[q * 256 + c]);
            float cs = 0.f;
            #pragma unroll
            for (int i = 0; i < 2; i++)
                #pragma unroll
                for (int h = 0; h < 2; h++) {
                    int r = rbase + i * 16 + h * 8;
                    if (n0 + r < clen)
                        cs += __expf(acc[i][j][h * 2 + e2] + cw_s[r] + qw_s[c] - fc);
                }
            #pragma unroll
            for (int o = 4; o <= 16; o <<= 1)
                cs += __shfl_xor_sync(0xFFFFFFFFu, cs, o);
            if ((lane >> 2) == 0) colred2[wn * 256 + c] = cs;
        }
    }
    __syncthreads();

    // -- final: write per-block column partials (ns = blockIdx.x) --
    if (wn == 0 && (lane >> 2) == 0) {
        #pragma unroll
        for (int j = 0; j < 8; j++)
            #pragma unroll
            for (int e2 = 0; e2 < 2; e2++) {
                int c = cbase + j * 8 + e2;
                float fm2 = colred[c], ps = colred2[c];
                #pragma unroll
                for (int q = 1; q < 4; q++) {
                    fm2 = fmaxf(fm2, colred[q * 256 + c]);
                    ps += colred2[q * 256 + c];
                }
                g_pmax[b][blockIdx.x][c] = fm2;
                g_psum[b][blockIdx.x][c] = ps;
            }
    }
}

// -------------------- k_bm2: combine partials, write Bm --------------------------
__global__ void __launch_bounds__(256) k_bm2() {
    int b = blockIdx.z, ns = blockIdx.y;
    int lane = threadIdx.x & 31, p = threadIdx.x >> 5;
    int m = blockIdx.x * 32 + lane;
    int clen = g_clen[b];

    __shared__ float fmv[32], invv[32];
    if (threadIdx.x < 32) {
        float fm = -1e30f;
        #pragma unroll
        for (int q = 0; q < NSPLIT; q++) fm = fmaxf(fm, g_pmax[b][q][m]);
        float fs = 0.f;
        #pragma unroll
        for (int q = 0; q < NSPLIT; q++) {
            float pm = g_pmax[b][q][m];
            if (pm > -1e29f) fs += g_psum[b][q][m] * __expf(pm - fm);
        }
        fmv[threadIdx.x] = fm;
        invv[threadIdx.x] = 1.f / fs;
    }
    __syncthreads();

    float fm = fmv[lane], inv = invv[lane];
    const float* Sc = g_S  + (size_t)b * NN * MM + m;
    float*       Bc = g_Bm + (size_t)b * NN * MM + m;
    #pragma unroll
    for (int it = 0; it < 16; it++) {
        int n = ns * 128 + p + it * 8;
        float v = (n < clen) ? __expf(Sc[(size_t)n * MM] - fm) * inv : 0.f;
        Bc[(size_t)n * MM] = v;
    }
}

// ============ k_mid_f: midT[d][m] = (Bm^T @ ctx)^T, 256m x 128d tiles ============
// 512 thr, 16 warps (wm=warp&3 over 64m, wd=warp>>2 over 32d), BK=32, 3 stages.
#define M_STGF 12800                       // A 32x264 + B 32x136
#define M_STGB (M_STGF * 4)
#define M_BOFF (32 * 264)
__global__ void __launch_bounds__(512, 1) k_mid_f(const float* __restrict__ ctx) {
    extern __shared__ float sm[];
    int b = blockIdx.y, d0 = blockIdx.x * 128;
    int tid = threadIdx.x, lane = tid & 31, warp = tid >> 5;
    int wm = warp & 3, wd = warp >> 2;
    uint32_t smb = s2u(sm);

    const float* Bmb  = g_Bm + (size_t)b * NN * MM;
    const float* ctxb = ctx  + (size_t)b * NN * DD;

    float acc[4][4][4] = {};
    const int KT = NN / 32;  // 32

    #define MF_LOAD(kt, s) do { \
        uint32_t base = smb + (s) * M_STGB; \
        _Pragma("unroll") \
        for (int r2 = 0; r2 < 4; r2++) { \
            int idx = tid + 512 * r2; int kr = idx >> 6, c4 = idx & 63; \
            cp16(base + (kr * 264 + c4 * 4) * 4, Bmb + (size_t)((kt) * 32 + kr) * MM + c4 * 4); \
        } \
        _Pragma("unroll") \
        for (int r2 = 0; r2 < 2; r2++) { \
            int idx = tid + 512 * r2; int kr = idx >> 5, c4 = idx & 31; \
            cp16(base + (M_BOFF + kr * 136 + c4 * 4) * 4, ctxb + (size_t)((kt) * 32 + kr) * DD + d0 + c4 * 4); \
        } \
    } while (0)

    MF_LOAD(0, 0); cp_commit();
    MF_LOAD(1, 1); cp_commit();

    for (int kt = 0; kt < KT; kt++) {
        cp_wait1();
        __syncthreads();
        if (kt + 2 < KT) { MF_LOAD(kt + 2, (kt + 2) % 3); }
        cp_commit();
        const float* As = sm + (kt % 3) * M_STGF;
        const float* Bs = As + M_BOFF;
        #pragma unroll
        for (int kk = 0; kk < 4; kk++) {
            int kb = kk * 8;
            uint32_t a[4][4];
            #pragma unroll
            for (int i = 0; i < 4; i++) {
                int r = wm * 64 + i * 16 + (lane >> 2);
                a[i][0] = __float_as_uint(As[(kb + (lane & 3)) * 264 + r]);
                a[i][1] = __float_as_uint(As[(kb + (lane & 3)) * 264 + r + 8]);
                a[i][2] = __float_as_uint(As[(kb + 4 + (lane & 3)) * 264 + r]);
                a[i][3] = __float_as_uint(As[(kb + 4 + (lane & 3)) * 264 + r + 8]);
            }
            #pragma unroll
            for (int j = 0; j < 4; j++) {
                int c = wd * 32 + j * 8 + (lane >> 2);
                uint32_t bf[2];
                bf[0] = __float_as_uint(Bs[(kb + (lane & 3)) * 136 + c]);
                bf[1] = __float_as_uint(Bs[(kb + 4 + (lane & 3)) * 136 + c]);
                #pragma unroll
                for (int i = 0; i < 4; i++) mma8(acc[i][j], a[i], bf);
            }
        }
    }
    #undef MF_LOAD

    // epilogue: stage [d][m] in smem (stride 260), then coalesced store
    __syncthreads();
    float* ot = sm;
    #pragma unroll
    for (int i = 0; i < 4; i++) {
        int m_r = wm * 64 + i * 16 + (lane >> 2);
        #pragma unroll
        for (int j = 0; j < 4; j++) {
            int c = wd * 32 + j * 8 + 2 * (lane & 3);
            ot[(size_t)c * 260 + m_r]           = acc[i][j][0];
            ot[(size_t)(c + 1) * 260 + m_r]     = acc[i][j][1];
            ot[(size_t)c * 260 + m_r + 8]       = acc[i][j][2];
            ot[(size_t)(c + 1) * 260 + m_r + 8] = acc[i][j][3];
        }
    }
    __syncthreads();
    #pragma unroll
    for (int rep = 0; rep < 16; rep++) {
        int idx = tid + rep * 512;
        int d = idx >> 6, m4 = (idx & 63) * 4;
        float4 v = *(float4*)(ot + (size_t)d * 260 + m4);
        *(float4*)(g_midT + ((size_t)b * DD + d0 + d) * MM + m4) = v;
    }
}

// ============ k_out_f: c2q = A@qT^T, q2c = A@midT^T, 128n x 128d dual ============
// 512 thr, 16 warps (wn=warp&3 over 32n, wd=warp>>2 over 32d), BK=32, 3 stages.
#define O_STGF 13824                        // 3 arrays of 128x36
#define O_STGB (O_STGF * 4)
#define O_QOFF (128 * 36)
#define O_MOFF (2 * 128 * 36)
__global__ void __launch_bounds__(512, 1) k_out_f(const float* __restrict__ ctx,
                                                  float* __restrict__ out) {
    extern __shared__ float sm[];
    int b = blockIdx.z, d0 = blockIdx.x * 128, n0 = blockIdx.y * 128;
    int tid = threadIdx.x, lane = tid & 31, warp = tid >> 5;
    int wn = warp & 3, wd = warp >> 2;
    uint32_t smb = s2u(sm);

    const float* Ab  = g_A    + ((size_t)b * NN + n0) * MM;
    const float* qTb = g_qT   + ((size_t)b * DD + d0) * MM;
    const float* mTb = g_midT + ((size_t)b * DD + d0) * MM;

    int g = lane >> 3, lr8 = lane & 7;
    uint32_t aLd[2], bqLd[2], bmLd[2];
    #pragma unroll
    for (int i = 0; i < 2; i++)
        aLd[i] = smb + ((wn * 32 + i * 16 + (g & 1) * 8 + lr8) * 36 + (g >> 1) * 4) * 4;
    #pragma unroll
    for (int jj = 0; jj < 2; jj++) {
        bqLd[jj] = smb + (O_QOFF + (wd * 32 + jj * 16 + (g >> 1) * 8 + lr8) * 36 + (g & 1) * 4) * 4;
        bmLd[jj] = smb + (O_MOFF + (wd * 32 + jj * 16 + (g >> 1) * 8 + lr8) * 36 + (g & 1) * 4) * 4;
    }

    float accq[2][4][4] = {};
    float accm[2][4][4] = {};
    const int KT = MM / 32;  // 8

    #define OF_LOAD(kt, s) do { \
        uint32_t base = smb + (s) * O_STGB; \
        _Pragma("unroll") \
        for (int r2 = 0; r2 < 2; r2++) { \
            int idx = tid + 512 * r2; int row = idx >> 3, c4 = idx & 7; \
            uint32_t o = (row * 36 + c4 * 4) * 4; \
            const float* gsrc = Ab  + (size_t)row * MM + (kt) * 32 + c4 * 4; \
            cp16(base + o, gsrc); \
            cp16(base + O_QOFF * 4 + o, qTb + (size_t)row * MM + (kt) * 32 + c4 * 4); \
            cp16(base + O_MOFF * 4 + o, mTb + (size_t)row * MM + (kt) * 32 + c4 * 4); \
        } \
    } while (0)

    OF_LOAD(0, 0); cp_commit();
    OF_LOAD(1, 1); cp_commit();

    for (int kt = 0; kt < KT; kt++) {
        cp_wait1();
        __syncthreads();
        if (kt + 2 < KT) { OF_LOAD(kt + 2, (kt + 2) % 3); }
        cp_commit();
        uint32_t boff = (kt % 3) * O_STGB;
        #pragma unroll
        for (int kk = 0; kk < 4; kk++) {
            uint32_t ko = boff + kk * 32;
            uint32_t a0[4], a1[4];
            ldsm4(a0, aLd[0] + ko);
            ldsm4(a1, aLd[1] + ko);
            #pragma unroll
            for (int jj = 0; jj < 2; jj++) {
                uint32_t bq[4], bm[4];
                ldsm4(bq, bqLd[jj] + ko);
                mma8(accq[0][jj * 2],     a0, bq);
                mma8(accq[0][jj * 2 + 1], a0, bq + 2);
                mma8(accq[1][jj * 2],     a1, bq);
                mma8(accq[1][jj * 2 + 1], a1, bq + 2);
                ldsm4(bm, bmLd[jj] + ko);
                mma8(accm[0][jj * 2],     a0, bm);
                mma8(accm[0][jj * 2 + 1], a0, bm + 2);
                mma8(accm[1][jj * 2],     a1, bm);
                mma8(accm[1][jj * 2 + 1], a1, bm + 2);
            }
        }
    }
    #undef OF_LOAD

    // epilogue: out = [ctx, c2q, ctx*c2q, ctx*q2c]
    #pragma unroll
    for (int i = 0; i < 2; i++) {
        #pragma unroll
        for (int half = 0; half < 2; half++) {
            int n = n0 + wn * 32 + i * 16 + (lane >> 2) + half * 8;
            const float* crow = ctx + ((size_t)b * NN + n) * DD;
            float* orow = out + ((size_t)b * NN + n) * (4 * DD);
            #pragma unroll
            for (int jj = 0; jj < 2; jj++) {
                #pragma unroll
                for (int hc = 0; hc < 2; hc++) {
                    int d = d0 + wd * 32 + jj * 16 + hc * 8 + 2 * (lane & 3);
                    int ai = jj * 2 + hc;
                    float2 cv = *(const float2*)(crow + d);
                    float c2q0 = accq[i][ai][half * 2], c2q1 = accq[i][ai][half * 2 + 1];
                    float q2c0 = accm[i][ai][half * 2], q2c1 = accm[i][ai][half * 2 + 1];
                    *(float2*)(orow + d)          = cv;
                    *(float2*)(orow + DD + d)     = make_float2(c2q0, c2q1);
                    *(float2*)(orow + 2 * DD + d) = make_float2(cv.x * c2q0, cv.y * c2q1);
                    *(float2*)(orow + 3 * DD + d) = make_float2(cv.x * q2c0, cv.y * q2c1);
                }
            }
        }
    }
}

// -------------------- launch --------------------
extern "C" void kernel_launch(void* const* d_in, const int* in_sizes, int n_in,
                              void* d_out, int out_size) {
    const float* ctx = (const float*)d_in[0];
    const float* qry = (const float*)d_in[1];
    const unsigned char* cm = (const unsigned char*)d_in[2];
    const unsigned char* qm = (const unsigned char*)d_in[3];
    const float* w = (const float*)d_in[4];
    float* out = (float*)d_out;

    const int SMEM_S   = (3 * S_STGF + 2944) * 4;  // 177664
    const int SMEM_MID = 3 * M_STGF * 4;           // 153600
    const int SMEM_OUT = 3 * O_STGF * 4;           // 165888

    cudaFuncSetAttribute(k_S_f,   cudaFuncAttributeMaxDynamicSharedMemorySize, SMEM_S);
    cudaFuncSetAttribute(k_mid_f, cudaFuncAttributeMaxDynamicSharedMemorySize, SMEM_MID);
    cudaFuncSetAttribute(k_out_f, cudaFuncAttributeMaxDynamicSharedMemorySize, SMEM_OUT);

    k_lens<<<1, 64>>>(cm, qm);
    k_rowdots<<<(BB * NN + BB * MM) / 8, 256>>>(ctx, qry, w);
    k_scale<<<(BB * MM * DD) / (4 * 256), 256>>>(qry, w);
    k_tq<<<dim3(MM / 32, DD / 32, BB), dim3(32, 8)>>>(qry);
    k_S_f<<<dim3(NN / 128, BB), 512, SMEM_S>>>(ctx);
    k_bm2<<<dim3(MM / 32, NSPLIT, BB), 256>>>();
    k_mid_f<<<dim3(DD / 128, BB), 512, SMEM_MID>>>(ctx);
    k_out_f<<<dim3(DD / 128, NN / 128, BB), 512, SMEM_OUT>>>(ctx, out);
}

// round 8
// speedup vs baseline: 2.6287x; 1.1097x over previous
#include <cuda_runtime.h>
#include <cuda_fp16.h>
#include <cstdint>
#include <cstddef>

#define BB 32
#define NN 1024
#define MM 256
#define DD 512
#define NSPLIT 8

// -------------------- device scratch --------------------
__device__ __align__(128) float  g_S  [(size_t)BB * NN * MM];
__device__ __align__(128) __half g_A  [(size_t)BB * NN * MM];
__device__ __align__(128) float  g_Bm [(size_t)BB * NN * MM];
__device__ __align__(128) __half g_midT[(size_t)BB * DD * MM];  // mid^T [d][m] fp16
__device__ __align__(128) __half g_qs [(size_t)BB * MM * DD];   // (query*w_m) fp16
__device__ __align__(128) __half g_qT [(size_t)BB * DD * MM];   // query^T [d][m] fp16
__device__ __align__(128) __half g_ctxh[(size_t)BB * NN * DD];  // ctx fp16
__device__ float g_pmax[BB][NSPLIT][MM];
__device__ float g_psum[BB][NSPLIT][MM];
__device__ float g_cw[BB * NN];
__device__ float g_qw[BB * MM];
__device__ int   g_clen[BB];
__device__ int   g_qlen[BB];

// -------------------- helpers --------------------
__device__ __forceinline__ void mma8(float* c, const uint32_t* a, const uint32_t* b) {
    asm volatile(
        "mma.sync.aligned.m16n8k8.row.col.f32.tf32.tf32.f32 "
        "{%0,%1,%2,%3}, {%4,%5,%6,%7}, {%8,%9}, {%0,%1,%2,%3};"
        : "+f"(c[0]), "+f"(c[1]), "+f"(c[2]), "+f"(c[3])
        : "r"(a[0]), "r"(a[1]), "r"(a[2]), "r"(a[3]), "r"(b[0]), "r"(b[1]));
}

__device__ __forceinline__ void mma16(float* c, const uint32_t* a, uint32_t b0, uint32_t b1) {
    asm volatile(
        "mma.sync.aligned.m16n8k16.row.col.f32.f16.f16.f32 "
        "{%0,%1,%2,%3}, {%4,%5,%6,%7}, {%8,%9}, {%0,%1,%2,%3};"
        : "+f"(c[0]), "+f"(c[1]), "+f"(c[2]), "+f"(c[3])
        : "r"(a[0]), "r"(a[1]), "r"(a[2]), "r"(a[3]), "r"(b0), "r"(b1));
}

__device__ __forceinline__ void ldsm4(uint32_t* r, uint32_t addr) {
    asm volatile("ldmatrix.sync.aligned.m8n8.x4.shared.b16 {%0,%1,%2,%3}, [%4];"
                 : "=r"(r[0]), "=r"(r[1]), "=r"(r[2]), "=r"(r[3]) : "r"(addr));
}

__device__ __forceinline__ uint32_t s2u(const void* p) {
    return (uint32_t)__cvta_generic_to_shared(p);
}
__device__ __forceinline__ void cp16(uint32_t dst, const void* src) {
    asm volatile("cp.async.cg.shared.global [%0], [%1], 16;" :: "r"(dst), "l"(src));
}
__device__ __forceinline__ void cp_commit() { asm volatile("cp.async.commit_group;"); }
__device__ __forceinline__ void cp_wait1()  { asm volatile("cp.async.wait_group 1;"); }

// -------------------- mask length detection --------------------
__device__ __forceinline__ int count_prefix(const unsigned char* p, int length,
                                            int esize, unsigned val) {
    int c = 0;
    for (int i = 0; i < length; i++) {
        unsigned v;
        if (esize == 1)      v = p[i];
        else if (esize == 2) v = ((const unsigned short*)p)[i];
        else                 v = ((const unsigned*)p)[i];
        if (v != val) break;
        c++;
    }
    return c;
}

__device__ void detect_fmt(const unsigned char* p, int length, int minlen,
                           int* esize, unsigned* val) {
    const int es[4]      = {1, 2, 4, 4};
    const unsigned vv[4] = {1u, 0x3F80u, 1u, 0x3F800000u};
    for (int k = 0; k < 4; k++) {
        if (count_prefix(p, length, es[k], vv[k]) >= minlen) {
            *esize = es[k]; *val = vv[k]; return;
        }
    }
    *esize = 4; *val = 1u;
}

__global__ void k_lens(const unsigned char* __restrict__ cm,
                       const unsigned char* __restrict__ qm) {
    __shared__ int es_c, es_q;
    __shared__ unsigned v_c, v_q;
    int t = threadIdx.x;
    if (t == 0) detect_fmt(cm, NN, NN / 4, &es_c, &v_c);
    if (t == 1) detect_fmt(qm, MM, MM / 4, &es_q, &v_q);
    __syncthreads();
    if (t < BB) {
        g_clen[t] = count_prefix(cm + (size_t)t * NN * es_c, NN, es_c, v_c);
    } else if (t < 2 * BB) {
        int b = t - BB;
        g_qlen[b] = count_prefix(qm + (size_t)b * MM * es_q, MM, es_q, v_q);
    }
}

// -------------------- cw = ctx @ w_c, qw = query @ w_q --------------------
__global__ void __launch_bounds__(256) k_rowdots(const float* __restrict__ ctx,
                                                 const float* __restrict__ qry,
                                                 const float* __restrict__ w) {
    int warp = threadIdx.x >> 5, lane = threadIdx.x & 31;
    int row = blockIdx.x * 8 + warp;
    const float* src; const float* wp; float* dst;
    if (row < BB * NN) {
        src = ctx + (size_t)row * DD; wp = w + DD;
        dst = g_cw + row;
    } else {
        int r = row - BB * NN;
        src = qry + (size_t)r * DD; wp = w;
        dst = g_qw + r;
    }
    float s = 0.f;
    #pragma unroll
    for (int d = lane * 4; d < DD; d += 128) {
        float4 v  = *(const float4*)(src + d);
        float4 wv = *(const float4*)(wp + d);
        s += v.x * wv.x + v.y * wv.y + v.z * wv.z + v.w * wv.w;
    }
    #pragma unroll
    for (int o = 16; o; o >>= 1) s += __shfl_xor_sync(0xFFFFFFFFu, s, o);
    if (lane == 0) *dst = s;
}

// -------------------- qs = (query * w_m) fp16 --------------------
__global__ void __launch_bounds__(256) k_scale(const float* __restrict__ qry,
                                               const float* __restrict__ w) {
    int i4 = blockIdx.x * 256 + threadIdx.x;
    int d4 = i4 & (DD / 4 - 1);
    float4 v  = *(const float4*)(qry + (size_t)i4 * 4);
    float4 wm = *(const float4*)(w + 2 * DD + d4 * 4);
    __half2* dst = (__half2*)(g_qs + (size_t)i4 * 4);
    dst[0] = __floats2half2_rn(v.x * wm.x, v.y * wm.y);
    dst[1] = __floats2half2_rn(v.z * wm.z, v.w * wm.w);
}

// -------------------- ctx_h = fp16(ctx) --------------------
__global__ void __launch_bounds__(512) k_cvtctx(const float* __restrict__ ctx) {
    size_t i4 = (size_t)blockIdx.x * 512 + threadIdx.x;
    float4 v = *(const float4*)(ctx + i4 * 4);
    __half2* dst = (__half2*)(g_ctxh + i4 * 4);
    dst[0] = __floats2half2_rn(v.x, v.y);
    dst[1] = __floats2half2_rn(v.z, v.w);
}

// -------------------- qT[b][d][m] = fp16(qry[b][m][d]) --------------------
__global__ void k_tq(const float* __restrict__ qry) {
    __shared__ float t[32][33];
    int b = blockIdx.z, m0 = blockIdx.x * 32, d0 = blockIdx.y * 32;
    int tx = threadIdx.x, ty = threadIdx.y;
    const float* src = qry + ((size_t)b * MM + m0) * DD + d0;
    #pragma unroll
    for (int i = 0; i < 4; i++) t[ty + 8 * i][tx] = src[(size_t)(ty + 8 * i) * DD + tx];
    __syncthreads();
    __half* dst = g_qT + ((size_t)b * DD + d0) * MM + m0;
    #pragma unroll
    for (int i = 0; i < 4; i++)
        dst[(size_t)(ty + 8 * i) * MM + tx] = __float2half_rn(t[tx][ty + 8 * i]);
}

// ============ k_S_f: S = ctx.qs^T (128n x 256m) fp16 MMA, fused softmax ==========
// 512 thr, 16 warps (wn over 4x32n, wm over 4x64m), BK=64 halfs, 3 stages.
// tile rows: 64 halfs + 8 pad = 144 B. A 128 rows (18432 B), B 256 rows (36864 B).
#define S_STGB 55296
#define S_BOFFB 18432
#define S_REDF (3 * S_STGB / 4)
__global__ void __launch_bounds__(512, 1) k_S_f(const float* __restrict__ ctx) {
    extern __shared__ float sm[];
    float* rowred  = sm + S_REDF;          // [4][128]
    float* colred  = rowred + 512;         // [4][256]
    float* colred2 = colred + 1024;        // [4][256]
    float* cw_s    = colred2 + 1024;       // [128]
    float* qw_s    = cw_s + 128;           // [256]

    int b = blockIdx.y, n0 = blockIdx.x * 128;
    int tid = threadIdx.x, lane = tid & 31, warp = tid >> 5;
    int wn = warp & 3, wm = warp >> 2;
    uint32_t smb = s2u(sm);

    if (tid < 128) cw_s[tid] = g_cw[b * NN + n0 + tid];
    else if (tid < 384) qw_s[tid - 128] = g_qw[b * MM + (tid - 128)];

    const __half* ctxb = g_ctxh + ((size_t)b * NN + n0) * DD;
    const __half* qsb  = g_qs   + (size_t)b * MM * DD;

    // ldmatrix bases: A block i (m16), B pair jj (two n8)
    uint32_t aLd[2], bLd[4];
    #pragma unroll
    for (int i = 0; i < 2; i++)
        aLd[i] = smb + (wn * 32 + i * 16 + (lane & 15)) * 144 + (lane >> 4) * 16;
    #pragma unroll
    for (int jj = 0; jj < 4; jj++)
        bLd[jj] = smb + S_BOFFB + (wm * 64 + jj * 16 + (lane & 15)) * 144 + (lane >> 4) * 16;

    float acc[2][8][4] = {};
    const int KT = DD / 64;  // 8

    #define SF_LOAD(kt, s) do { \
        uint32_t base = smb + (s) * S_STGB; \
        _Pragma("unroll") \
        for (int r2 = 0; r2 < 2; r2++) { \
            int idx = tid + 512 * r2; int row = idx >> 3, c = idx & 7; \
            cp16(base + row * 144 + c * 16, ctxb + (size_t)row * DD + (kt) * 64 + c * 8); \
        } \
        _Pragma("unroll") \
        for (int r2 = 0; r2 < 4; r2++) { \
            int idx = tid + 512 * r2; int row = idx >> 3, c = idx & 7; \
            cp16(base + S_BOFFB + row * 144 + c * 16, qsb + (size_t)row * DD + (kt) * 64 + c * 8); \
        } \
    } while (0)

    SF_LOAD(0, 0); cp_commit();
    SF_LOAD(1, 1); cp_commit();

    for (int kt = 0; kt < KT; kt++) {
        cp_wait1();
        __syncthreads();
        if (kt + 2 < KT) { SF_LOAD(kt + 2, (kt + 2) % 3); }
        cp_commit();
        uint32_t boff = (kt % 3) * S_STGB;
        #pragma unroll
        for (int kk = 0; kk < 4; kk++) {
            uint32_t ko = boff + kk * 32;
            uint32_t a0[4], a1[4];
            ldsm4(a0, aLd[0] + ko);
            ldsm4(a1, aLd[1] + ko);
            #pragma unroll
            for (int jj = 0; jj < 4; jj++) {
                uint32_t bb[4];
                ldsm4(bb, bLd[jj] + ko);
                mma16(acc[0][2 * jj],     a0, bb[0], bb[2]);
                mma16(acc[0][2 * jj + 1], a0, bb[1], bb[3]);
                mma16(acc[1][2 * jj],     a1, bb[0], bb[2]);
                mma16(acc[1][2 * jj + 1], a1, bb[1], bb[3]);
            }
        }
    }
    #undef SF_LOAD

    // ======== fused epilogue ========
    int qlen = g_qlen[b], clen = g_clen[b];
    int rbase = wn * 32 + (lane >> 2);
    int cbase = wm * 64 + 2 * (lane & 3);

    // -- pass 1: write S (fp32), row maxes --
    float rmax[2][2] = {{-1e30f, -1e30f}, {-1e30f, -1e30f}};
    #pragma unroll
    for (int i = 0; i < 2; i++) {
        #pragma unroll
        for (int h = 0; h < 2; h++) {
            int r = rbase + i * 16 + h * 8;
            float cwv = cw_s[r];
            float* Srow = g_S + ((size_t)b * NN + n0 + r) * MM;
            #pragma unroll
            for (int j = 0; j < 8; j++) {
                int c = cbase + j * 8;
                float s0 = acc[i][j][h * 2]     + cwv + qw_s[c];
                float s1 = acc[i][j][h * 2 + 1] + cwv + qw_s[c + 1];
                *(float2*)(Srow + c) = make_float2(s0, s1);
                if (c < qlen)     rmax[i][h] = fmaxf(rmax[i][h], s0);
                if (c + 1 < qlen) rmax[i][h] = fmaxf(rmax[i][h], s1);
            }
        }
    }
    #pragma unroll
    for (int i = 0; i < 2; i++)
        #pragma unroll
        for (int h = 0; h < 2; h++) {
            #pragma unroll
            for (int o = 1; o <= 2; o <<= 1)
                rmax[i][h] = fmaxf(rmax[i][h], __shfl_xor_sync(0xFFFFFFFFu, rmax[i][h], o));
        }
    if ((lane & 3) == 0) {
        #pragma unroll
        for (int i = 0; i < 2; i++)
            #pragma unroll
            for (int h = 0; h < 2; h++)
                rowred[wm * 128 + rbase + i * 16 + h * 8] = rmax[i][h];
    }
    __syncthreads();
    float frmax[2][2];
    #pragma unroll
    for (int i = 0; i < 2; i++)
        #pragma unroll
        for (int h = 0; h < 2; h++) {
            int r = rbase + i * 16 + h * 8;
            float m = rowred[r];
            #pragma unroll
            for (int q = 1; q < 4; q++) m = fmaxf(m, rowred[q * 128 + r]);
            frmax[i][h] = m;
        }
    __syncthreads();

    // -- pass 2: row sums --
    float rsum[2][2] = {};
    #pragma unroll
    for (int i = 0; i < 2; i++)
        #pragma unroll
        for (int h = 0; h < 2; h++) {
            int r = rbase + i * 16 + h * 8;
            float cwv = cw_s[r];
            #pragma unroll
            for (int j = 0; j < 8; j++) {
                int c = cbase + j * 8;
                if (c < qlen)     rsum[i][h] += __expf(acc[i][j][h * 2]     + cwv + qw_s[c]     - frmax[i][h]);
                if (c + 1 < qlen) rsum[i][h] += __expf(acc[i][j][h * 2 + 1] + cwv + qw_s[c + 1] - frmax[i][h]);
            }
            #pragma unroll
            for (int o = 1; o <= 2; o <<= 1)
                rsum[i][h] += __shfl_xor_sync(0xFFFFFFFFu, rsum[i][h], o);
        }
    if ((lane & 3) == 0) {
        #pragma unroll
        for (int i = 0; i < 2; i++)
            #pragma unroll
            for (int h = 0; h < 2; h++)
                rowred[wm * 128 + rbase + i * 16 + h * 8] = rsum[i][h];
    }
    __syncthreads();
    float rinv[2][2];
    #pragma unroll
    for (int i = 0; i < 2; i++)
        #pragma unroll
        for (int h = 0; h < 2; h++) {
            int r = rbase + i * 16 + h * 8;
            float t = 0.f;
            #pragma unroll
            for (int q = 0; q < 4; q++) t += rowred[q * 128 + r];
            rinv[i][h] = 1.f / t;
        }

    // -- pass 3: write A (fp16) --
    #pragma unroll
    for (int i = 0; i < 2; i++)
        #pragma unroll
        for (int h = 0; h < 2; h++) {
            int r = rbase + i * 16 + h * 8;
            float cwv = cw_s[r];
            __half* Arow = g_A + ((size_t)b * NN + n0 + r) * MM;
            #pragma unroll
            for (int j = 0; j < 8; j++) {
                int c = cbase + j * 8;
                float e0 = (c < qlen)
                    ? __expf(acc[i][j][h * 2] + cwv + qw_s[c] - frmax[i][h]) * rinv[i][h] : 0.f;
                float e1 = (c + 1 < qlen)
                    ? __expf(acc[i][j][h * 2 + 1] + cwv + qw_s[c + 1] - frmax[i][h]) * rinv[i][h] : 0.f;
                *(__half2*)(Arow + c) = __floats2half2_rn(e0, e1);
            }
        }

    // -- pass 4: column max partials over this block's 128 rows --
    #pragma unroll
    for (int j = 0; j < 8; j++) {
        #pragma unroll
        for (int e2 = 0; e2 < 2; e2++) {
            int c = cbase + j * 8 + e2;
            float cm = -1e30f;
            #pragma unroll
            for (int i = 0; i < 2; i++)
                #pragma unroll
                for (int h = 0; h < 2; h++) {
                    int r = rbase + i * 16 + h * 8;
                    if (n0 + r < clen)
                        cm = fmaxf(cm, acc[i][j][h * 2 + e2] + cw_s[r] + qw_s[c]);
                }
            #pragma unroll
            for (int o = 4; o <= 16; o <<= 1)
                cm = fmaxf(cm, __shfl_xor_sync(0xFFFFFFFFu, cm, o));
            if ((lane >> 2) == 0) colred[wn * 256 + c] = cm;
        }
    }
    __syncthreads();

    // -- pass 5: column sum partials --
    #pragma unroll
    for (int j = 0; j < 8; j++) {
        #pragma unroll
        for (int e2 = 0; e2 < 2; e2++) {
            int c = cbase + j * 8 + e2;
            float fc = colred[c];
            #pragma unroll
            for (int q = 1; q < 4; q++) fc = fmaxf(fc, colred[q * 256 + c]);
            float cs = 0.f;
            #pragma unroll
            for (int i = 0; i < 2; i++)
                #pragma unroll
                for (int h = 0; h < 2; h++) {
                    int r = rbase + i * 16 + h * 8;
                    if (n0 + r < clen)
                        cs += __expf(acc[i][j][h * 2 + e2] + cw_s[r] + qw_s[c] - fc);
                }
            #pragma unroll
            for (int o = 4; o <= 16; o <<= 1)
                cs += __shfl_xor_sync(0xFFFFFFFFu, cs, o);
            if ((lane >> 2) == 0) colred2[wn * 256 + c] = cs;
        }
    }
    __syncthreads();

    if (wn == 0 && (lane >> 2) == 0) {
        #pragma unroll
        for (int j = 0; j < 8; j++)
            #pragma unroll
            for (int e2 = 0; e2 < 2; e2++) {
                int c = cbase + j * 8 + e2;
                float fm2 = colred[c], ps = colred2[c];
                #pragma unroll
                for (int q = 1; q < 4; q++) {
                    fm2 = fmaxf(fm2, colred[q * 256 + c]);
                    ps += colred2[q * 256 + c];
                }
                g_pmax[b][blockIdx.x][c] = fm2;
                g_psum[b][blockIdx.x][c] = ps;
            }
    }
}

// -------------------- k_bm2: combine partials, write Bm (fp32) -------------------
__global__ void __launch_bounds__(256) k_bm2() {
    int b = blockIdx.z, ns = blockIdx.y;
    int lane = threadIdx.x & 31, p = threadIdx.x >> 5;
    int m = blockIdx.x * 32 + lane;
    int clen = g_clen[b];

    __shared__ float fmv[32], invv[32];
    if (threadIdx.x < 32) {
        float fm = -1e30f;
        #pragma unroll
        for (int q = 0; q < NSPLIT; q++) fm = fmaxf(fm, g_pmax[b][q][m]);
        float fs = 0.f;
        #pragma unroll
        for (int q = 0; q < NSPLIT; q++) {
            float pm = g_pmax[b][q][m];
            if (pm > -1e29f) fs += g_psum[b][q][m] * __expf(pm - fm);
        }
        fmv[threadIdx.x] = fm;
        invv[threadIdx.x] = 1.f / fs;
    }
    __syncthreads();

    float fm = fmv[lane], inv = invv[lane];
    const float* Sc = g_S  + (size_t)b * NN * MM + m;
    float*       Bc = g_Bm + (size_t)b * NN * MM + m;
    #pragma unroll
    for (int it = 0; it < 16; it++) {
        int n = ns * 128 + p + it * 8;
        float v = (n < clen) ? __expf(Sc[(size_t)n * MM] - fm) * inv : 0.f;
        Bc[(size_t)n * MM] = v;
    }
}

// ============ k_mid_f: midT[d][m] = (Bm^T @ ctx)^T, tf32 mma, fp16 output ========
#define M_STGF 12800
#define M_STGB (M_STGF * 4)
#define M_BOFF (32 * 264)
__global__ void __launch_bounds__(512, 1) k_mid_f(const float* __restrict__ ctx) {
    extern __shared__ float sm[];
    int b = blockIdx.y, d0 = blockIdx.x * 128;
    int tid = threadIdx.x, lane = tid & 31, warp = tid >> 5;
    int wm = warp & 3, wd = warp >> 2;
    uint32_t smb = s2u(sm);

    const float* Bmb  = g_Bm + (size_t)b * NN * MM;
    const float* ctxb = ctx  + (size_t)b * NN * DD;

    float acc[4][4][4] = {};
    const int KT = NN / 32;

    #define MF_LOAD(kt, s) do { \
        uint32_t base = smb + (s) * M_STGB; \
        _Pragma("unroll") \
        for (int r2 = 0; r2 < 4; r2++) { \
            int idx = tid + 512 * r2; int kr = idx >> 6, c4 = idx & 63; \
            cp16(base + (kr * 264 + c4 * 4) * 4, Bmb + (size_t)((kt) * 32 + kr) * MM + c4 * 4); \
        } \
        _Pragma("unroll") \
        for (int r2 = 0; r2 < 2; r2++) { \
            int idx = tid + 512 * r2; int kr = idx >> 5, c4 = idx & 31; \
            cp16(base + (M_BOFF + kr * 136 + c4 * 4) * 4, ctxb + (size_t)((kt) * 32 + kr) * DD + d0 + c4 * 4); \
        } \
    } while (0)

    MF_LOAD(0, 0); cp_commit();
    MF_LOAD(1, 1); cp_commit();

    for (int kt = 0; kt < KT; kt++) {
        cp_wait1();
        __syncthreads();
        if (kt + 2 < KT) { MF_LOAD(kt + 2, (kt + 2) % 3); }
        cp_commit();
        const float* As = sm + (kt % 3) * M_STGF;
        const float* Bs = As + M_BOFF;
        #pragma unroll
        for (int kk = 0; kk < 4; kk++) {
            int kb = kk * 8;
            uint32_t a[4][4];
            #pragma unroll
            for (int i = 0; i < 4; i++) {
                int r = wm * 64 + i * 16 + (lane >> 2);
                a[i][0] = __float_as_uint(As[(kb + (lane & 3)) * 264 + r]);
                a[i][1] = __float_as_uint(As[(kb + (lane & 3)) * 264 + r + 8]);
                a[i][2] = __float_as_uint(As[(kb + 4 + (lane & 3)) * 264 + r]);
                a[i][3] = __float_as_uint(As[(kb + 4 + (lane & 3)) * 264 + r + 8]);
            }
            #pragma unroll
            for (int j = 0; j < 4; j++) {
                int c = wd * 32 + j * 8 + (lane >> 2);
                uint32_t bf[2];
                bf[0] = __float_as_uint(Bs[(kb + (lane & 3)) * 136 + c]);
                bf[1] = __float_as_uint(Bs[(kb + 4 + (lane & 3)) * 136 + c]);
                #pragma unroll
                for (int i = 0; i < 4; i++) mma8(acc[i][j], a[i], bf);
            }
        }
    }
    #undef MF_LOAD

    // epilogue: stage [d][m] fp32 in smem, convert + coalesced fp16 store
    __syncthreads();
    float* ot = sm;
    #pragma unroll
    for (int i = 0; i < 4; i++) {
        int m_r = wm * 64 + i * 16 + (lane >> 2);
        #pragma unroll
        for (int j = 0; j < 4; j++) {
            int c = wd * 32 + j * 8 + 2 * (lane & 3);
            ot[(size_t)c * 260 + m_r]           = acc[i][j][0];
            ot[(size_t)(c + 1) * 260 + m_r]     = acc[i][j][1];
            ot[(size_t)c * 260 + m_r + 8]       = acc[i][j][2];
            ot[(size_t)(c + 1) * 260 + m_r + 8] = acc[i][j][3];
        }
    }
    __syncthreads();
    #pragma unroll
    for (int rep = 0; rep < 16; rep++) {
        int idx = tid + rep * 512;
        int d = idx >> 6, m4 = (idx & 63) * 4;
        float4 v = *(float4*)(ot + (size_t)d * 260 + m4);
        __half2* dp = (__half2*)(g_midT + ((size_t)b * DD + d0 + d) * MM + m4);
        dp[0] = __floats2half2_rn(v.x, v.y);
        dp[1] = __floats2half2_rn(v.z, v.w);
    }
}

// ============ k_out_f: c2q = A@qT^T, q2c = A@midT^T, fp16 MMA, 128n x 128d =======
// 512 thr, 16 warps (wn 4x32n, wd 4x32d), BK=64 halfs, 3 stages.
#define O_STGB 55296
#define O_QOFFB 18432
#define O_MOFFB 36864
__global__ void __launch_bounds__(512, 1) k_out_f(const float* __restrict__ ctx,
                                                  float* __restrict__ out) {
    extern __shared__ float sm[];
    int b = blockIdx.z, d0 = blockIdx.x * 128, n0 = blockIdx.y * 128;
    int tid = threadIdx.x, lane = tid & 31, warp = tid >> 5;
    int wn = warp & 3, wd = warp >> 2;
    uint32_t smb = s2u(sm);

    const __half* Ab  = g_A    + ((size_t)b * NN + n0) * MM;
    const __half* qTb = g_qT   + ((size_t)b * DD + d0) * MM;
    const __half* mTb = g_midT + ((size_t)b * DD + d0) * MM;

    uint32_t aLd[2], bqLd[2], bmLd[2];
    #pragma unroll
    for (int i = 0; i < 2; i++)
        aLd[i] = smb + (wn * 32 + i * 16 + (lane & 15)) * 144 + (lane >> 4) * 16;
    #pragma unroll
    for (int jj = 0; jj < 2; jj++) {
        bqLd[jj] = smb + O_QOFFB + (wd * 32 + jj * 16 + (lane & 15)) * 144 + (lane >> 4) * 16;
        bmLd[jj] = smb + O_MOFFB + (wd * 32 + jj * 16 + (lane & 15)) * 144 + (lane >> 4) * 16;
    }

    float accq[2][4][4] = {};
    float accm[2][4][4] = {};
    const int KT = MM / 64;  // 4

    #define OF_LOAD(kt, s) do { \
        uint32_t base = smb + (s) * O_STGB; \
        _Pragma("unroll") \
        for (int r2 = 0; r2 < 2; r2++) { \
            int idx = tid + 512 * r2; int row = idx >> 3, c = idx & 7; \
            uint32_t o = row * 144 + c * 16; \
            cp16(base + o,           Ab  + (size_t)row * MM + (kt) * 64 + c * 8); \
            cp16(base + O_QOFFB + o, qTb + (size_t)row * MM + (kt) * 64 + c * 8); \
            cp16(base + O_MOFFB + o, mTb + (size_t)row * MM + (kt) * 64 + c * 8); \
        } \
    } while (0)

    OF_LOAD(0, 0); cp_commit();
    OF_LOAD(1, 1); cp_commit();

    for (int kt = 0; kt < KT; kt++) {
        cp_wait1();
        __syncthreads();
        if (kt + 2 < KT) { OF_LOAD(kt + 2, (kt + 2) % 3); }
        cp_commit();
        uint32_t boff = (kt % 3) * O_STGB;
        #pragma unroll
        for (int kk = 0; kk < 4; kk++) {
            uint32_t ko = boff + kk * 32;
            uint32_t a0[4], a1[4];
            ldsm4(a0, aLd[0] + ko);
            ldsm4(a1, aLd[1] + ko);
            #pragma unroll
            for (int jj = 0; jj < 2; jj++) {
                uint32_t bq[4], bm[4];
                ldsm4(bq, bqLd[jj] + ko);
                mma16(accq[0][jj * 2],     a0, bq[0], bq[2]);
                mma16(accq[0][jj * 2 + 1], a0, bq[1], bq[3]);
                mma16(accq[1][jj * 2],     a1, bq[0], bq[2]);
                mma16(accq[1][jj * 2 + 1], a1, bq[1], bq[3]);
                ldsm4(bm, bmLd[jj] + ko);
                mma16(accm[0][jj * 2],     a0, bm[0], bm[2]);
                mma16(accm[0][jj * 2 + 1], a0, bm[1], bm[3]);
                mma16(accm[1][jj * 2],     a1, bm[0], bm[2]);
                mma16(accm[1][jj * 2 + 1], a1, bm[1], bm[3]);
            }
        }
    }
    #undef OF_LOAD

    // epilogue: out = [ctx, c2q, ctx*c2q, ctx*q2c]
    #pragma unroll
    for (int i = 0; i < 2; i++) {
        #pragma unroll
        for (int half = 0; half < 2; half++) {
            int n = n0 + wn * 32 + i * 16 + (lane >> 2) + half * 8;
            const float* crow = ctx + ((size_t)b * NN + n) * DD;
            float* orow = out + ((size_t)b * NN + n) * (4 * DD);
            #pragma unroll
            for (int jj = 0; jj < 2; jj++) {
                #pragma unroll
                for (int hc = 0; hc < 2; hc++) {
                    int d = d0 + wd * 32 + jj * 16 + hc * 8 + 2 * (lane & 3);
                    int ai = jj * 2 + hc;
                    float2 cv = *(const float2*)(crow + d);
                    float c2q0 = accq[i][ai][half * 2], c2q1 = accq[i][ai][half * 2 + 1];
                    float q2c0 = accm[i][ai][half * 2], q2c1 = accm[i][ai][half * 2 + 1];
                    *(float2*)(orow + d)          = cv;
                    *(float2*)(orow + DD + d)     = make_float2(c2q0, c2q1);
                    *(float2*)(orow + 2 * DD + d) = make_float2(cv.x * c2q0, cv.y * c2q1);
                    *(float2*)(orow + 3 * DD + d) = make_float2(cv.x * q2c0, cv.y * q2c1);
                }
            }
        }
    }
}

// -------------------- launch --------------------
extern "C" void kernel_launch(void* const* d_in, const int* in_sizes, int n_in,
                              void* d_out, int out_size) {
    const float* ctx = (const float*)d_in[0];
    const float* qry = (const float*)d_in[1];
    const unsigned char* cm = (const unsigned char*)d_in[2];
    const unsigned char* qm = (const unsigned char*)d_in[3];
    const float* w = (const float*)d_in[4];
    float* out = (float*)d_out;

    const int SMEM_S   = 3 * S_STGB + 2944 * 4;  // 177664
    const int SMEM_MID = 3 * M_STGB;             // 153600
    const int SMEM_OUT = 3 * O_STGB;             // 165888

    cudaFuncSetAttribute(k_S_f,   cudaFuncAttributeMaxDynamicSharedMemorySize, SMEM_S);
    cudaFuncSetAttribute(k_mid_f, cudaFuncAttributeMaxDynamicSharedMemorySize, SMEM_MID);
    cudaFuncSetAttribute(k_out_f, cudaFuncAttributeMaxDynamicSharedMemorySize, SMEM_OUT);

    k_lens<<<1, 64>>>(cm, qm);
    k_rowdots<<<(BB * NN + BB * MM) / 8, 256>>>(ctx, qry, w);
    k_scale<<<(BB * MM * DD) / (4 * 256), 256>>>(qry, w);
    k_cvtctx<<<(int)(((size_t)BB * NN * DD) / (4 * 512)), 512>>>(ctx);
    k_tq<<<dim3(MM / 32, DD / 32, BB), dim3(32, 8)>>>(qry);
    k_S_f<<<dim3(NN / 128, BB), 512, SMEM_S>>>(ctx);
    k_bm2<<<dim3(MM / 32, NSPLIT, BB), 256>>>();
    k_mid_f<<<dim3(DD / 128, BB), 512, SMEM_MID>>>(ctx);
    k_out_f<<<dim3(DD / 128, NN / 128, BB), 512, SMEM_OUT>>>(ctx, out);
}

// round 9
// speedup vs baseline: 2.9411x; 1.1188x over previous
#include <cuda_runtime.h>
#include <cuda_fp16.h>
#include <cstdint>
#include <cstddef>

#define BB 32
#define NN 1024
#define MM 256
#define DD 512
#define NSPLIT 8

// -------------------- device scratch --------------------
__device__ __align__(128) float  g_S  [(size_t)BB * NN * MM];
__device__ __align__(128) __half g_A  [(size_t)BB * NN * MM];
__device__ __align__(128) __half g_Bmh[(size_t)BB * NN * MM];   // Bm fp16 [n][m]
__device__ __align__(128) __half g_midT[(size_t)BB * DD * MM];  // mid^T [d][m] fp16
__device__ __align__(128) __half g_qs [(size_t)BB * MM * DD];   // (query*w_m) fp16
__device__ __align__(128) __half g_qT [(size_t)BB * DD * MM];   // query^T [d][m] fp16
__device__ __align__(128) __half g_ctxh[(size_t)BB * NN * DD];  // ctx fp16
__device__ float g_pmax[BB][NSPLIT][MM];
__device__ float g_psum[BB][NSPLIT][MM];
__device__ float g_cw[BB * NN];
__device__ float g_qw[BB * MM];
__device__ int   g_clen[BB];
__device__ int   g_qlen[BB];

// -------------------- helpers --------------------
__device__ __forceinline__ void mma16(float* c, const uint32_t* a, uint32_t b0, uint32_t b1) {
    asm volatile(
        "mma.sync.aligned.m16n8k16.row.col.f32.f16.f16.f32 "
        "{%0,%1,%2,%3}, {%4,%5,%6,%7}, {%8,%9}, {%0,%1,%2,%3};"
        : "+f"(c[0]), "+f"(c[1]), "+f"(c[2]), "+f"(c[3])
        : "r"(a[0]), "r"(a[1]), "r"(a[2]), "r"(a[3]), "r"(b0), "r"(b1));
}

__device__ __forceinline__ void ldsm4(uint32_t* r, uint32_t addr) {
    asm volatile("ldmatrix.sync.aligned.m8n8.x4.shared.b16 {%0,%1,%2,%3}, [%4];"
                 : "=r"(r[0]), "=r"(r[1]), "=r"(r[2]), "=r"(r[3]) : "r"(addr));
}
__device__ __forceinline__ void ldsm4t(uint32_t* r, uint32_t addr) {
    asm volatile("ldmatrix.sync.aligned.m8n8.x4.trans.shared.b16 {%0,%1,%2,%3}, [%4];"
                 : "=r"(r[0]), "=r"(r[1]), "=r"(r[2]), "=r"(r[3]) : "r"(addr));
}

__device__ __forceinline__ uint32_t s2u(const void* p) {
    return (uint32_t)__cvta_generic_to_shared(p);
}
__device__ __forceinline__ void cp16(uint32_t dst, const void* src) {
    asm volatile("cp.async.cg.shared.global [%0], [%1], 16;" :: "r"(dst), "l"(src));
}
__device__ __forceinline__ void cp_commit() { asm volatile("cp.async.commit_group;"); }
__device__ __forceinline__ void cp_wait1()  { asm volatile("cp.async.wait_group 1;"); }

// -------------------- mask length detection --------------------
__device__ __forceinline__ int count_prefix(const unsigned char* p, int length,
                                            int esize, unsigned val) {
    int c = 0;
    for (int i = 0; i < length; i++) {
        unsigned v;
        if (esize == 1)      v = p[i];
        else if (esize == 2) v = ((const unsigned short*)p)[i];
        else                 v = ((const unsigned*)p)[i];
        if (v != val) break;
        c++;
    }
    return c;
}

__device__ void detect_fmt(const unsigned char* p, int length, int minlen,
                           int* esize, unsigned* val) {
    const int es[4]      = {1, 2, 4, 4};
    const unsigned vv[4] = {1u, 0x3F80u, 1u, 0x3F800000u};
    for (int k = 0; k < 4; k++) {
        if (count_prefix(p, length, es[k], vv[k]) >= minlen) {
            *esize = es[k]; *val = vv[k]; return;
        }
    }
    *esize = 4; *val = 1u;
}

__global__ void k_lens(const unsigned char* __restrict__ cm,
                       const unsigned char* __restrict__ qm) {
    __shared__ int es_c, es_q;
    __shared__ unsigned v_c, v_q;
    int t = threadIdx.x;
    if (t == 0) detect_fmt(cm, NN, NN / 4, &es_c, &v_c);
    if (t == 1) detect_fmt(qm, MM, MM / 4, &es_q, &v_q);
    __syncthreads();
    if (t < BB) {
        g_clen[t] = count_prefix(cm + (size_t)t * NN * es_c, NN, es_c, v_c);
    } else if (t < 2 * BB) {
        int b = t - BB;
        g_qlen[b] = count_prefix(qm + (size_t)b * MM * es_q, MM, es_q, v_q);
    }
}

// ------------- cw = ctx @ w_c (also emits ctx fp16), qw = query @ w_q ------------
__global__ void __launch_bounds__(256) k_rowdots(const float* __restrict__ ctx,
                                                 const float* __restrict__ qry,
                                                 const float* __restrict__ w) {
    int warp = threadIdx.x >> 5, lane = threadIdx.x & 31;
    int row = blockIdx.x * 8 + warp;
    if (row < BB * NN) {
        const float* src = ctx + (size_t)row * DD;
        const float* wp  = w + DD;
        __half* hdst = g_ctxh + (size_t)row * DD;
        float s = 0.f;
        #pragma unroll
        for (int d = lane * 4; d < DD; d += 128) {
            float4 v  = *(const float4*)(src + d);
            float4 wv = *(const float4*)(wp + d);
            s += v.x * wv.x + v.y * wv.y + v.z * wv.z + v.w * wv.w;
            __half2* hp = (__half2*)(hdst + d);
            hp[0] = __floats2half2_rn(v.x, v.y);
            hp[1] = __floats2half2_rn(v.z, v.w);
        }
        #pragma unroll
        for (int o = 16; o; o >>= 1) s += __shfl_xor_sync(0xFFFFFFFFu, s, o);
        if (lane == 0) g_cw[row] = s;
    } else {
        int r = row - BB * NN;
        const float* src = qry + (size_t)r * DD;
        float s = 0.f;
        #pragma unroll
        for (int d = lane * 4; d < DD; d += 128) {
            float4 v  = *(const float4*)(src + d);
            float4 wv = *(const float4*)(w + d);
            s += v.x * wv.x + v.y * wv.y + v.z * wv.z + v.w * wv.w;
        }
        #pragma unroll
        for (int o = 16; o; o >>= 1) s += __shfl_xor_sync(0xFFFFFFFFu, s, o);
        if (lane == 0) g_qw[r] = s;
    }
}

// -------------------- qs = (query * w_m) fp16 --------------------
__global__ void __launch_bounds__(256) k_scale(const float* __restrict__ qry,
                                               const float* __restrict__ w) {
    int i4 = blockIdx.x * 256 + threadIdx.x;
    int d4 = i4 & (DD / 4 - 1);
    float4 v  = *(const float4*)(qry + (size_t)i4 * 4);
    float4 wm = *(const float4*)(w + 2 * DD + d4 * 4);
    __half2* dst = (__half2*)(g_qs + (size_t)i4 * 4);
    dst[0] = __floats2half2_rn(v.x * wm.x, v.y * wm.y);
    dst[1] = __floats2half2_rn(v.z * wm.z, v.w * wm.w);
}

// -------------------- qT[b][d][m] = fp16(qry[b][m][d]) --------------------
__global__ void k_tq(const float* __restrict__ qry) {
    __shared__ float t[32][33];
    int b = blockIdx.z, m0 = blockIdx.x * 32, d0 = blockIdx.y * 32;
    int tx = threadIdx.x, ty = threadIdx.y;
    const float* src = qry + ((size_t)b * MM + m0) * DD + d0;
    #pragma unroll
    for (int i = 0; i < 4; i++) t[ty + 8 * i][tx] = src[(size_t)(ty + 8 * i) * DD + tx];
    __syncthreads();
    __half* dst = g_qT + ((size_t)b * DD + d0) * MM + m0;
    #pragma unroll
    for (int i = 0; i < 4; i++)
        dst[(size_t)(ty + 8 * i) * MM + tx] = __float2half_rn(t[tx][ty + 8 * i]);
}

// ============ k_S_f: S = ctx.qs^T (128n x 256m) fp16 MMA, fused softmax ==========
#define S_STGB 55296
#define S_BOFFB 18432
#define S_REDF (3 * S_STGB / 4)
__global__ void __launch_bounds__(512, 1) k_S_f(const float* __restrict__ ctx) {
    extern __shared__ float sm[];
    float* rowred  = sm + S_REDF;
    float* colred  = rowred + 512;
    float* colred2 = colred + 1024;
    float* cw_s    = colred2 + 1024;
    float* qw_s    = cw_s + 128;

    int b = blockIdx.y, n0 = blockIdx.x * 128;
    int tid = threadIdx.x, lane = tid & 31, warp = tid >> 5;
    int wn = warp & 3, wm = warp >> 2;
    uint32_t smb = s2u(sm);

    if (tid < 128) cw_s[tid] = g_cw[b * NN + n0 + tid];
    else if (tid < 384) qw_s[tid - 128] = g_qw[b * MM + (tid - 128)];

    const __half* ctxb = g_ctxh + ((size_t)b * NN + n0) * DD;
    const __half* qsb  = g_qs   + (size_t)b * MM * DD;

    uint32_t aLd[2], bLd[4];
    #pragma unroll
    for (int i = 0; i < 2; i++)
        aLd[i] = smb + (wn * 32 + i * 16 + (lane & 15)) * 144 + (lane >> 4) * 16;
    #pragma unroll
    for (int jj = 0; jj < 4; jj++)
        bLd[jj] = smb + S_BOFFB + (wm * 64 + jj * 16 + (lane & 15)) * 144 + (lane >> 4) * 16;

    float acc[2][8][4] = {};
    const int KT = DD / 64;  // 8

    #define SF_LOAD(kt, s) do { \
        uint32_t base = smb + (s) * S_STGB; \
        _Pragma("unroll") \
        for (int r2 = 0; r2 < 2; r2++) { \
            int idx = tid + 512 * r2; int row = idx >> 3, c = idx & 7; \
            cp16(base + row * 144 + c * 16, ctxb + (size_t)row * DD + (kt) * 64 + c * 8); \
        } \
        _Pragma("unroll") \
        for (int r2 = 0; r2 < 4; r2++) { \
            int idx = tid + 512 * r2; int row = idx >> 3, c = idx & 7; \
            cp16(base + S_BOFFB + row * 144 + c * 16, qsb + (size_t)row * DD + (kt) * 64 + c * 8); \
        } \
    } while (0)

    SF_LOAD(0, 0); cp_commit();
    SF_LOAD(1, 1); cp_commit();

    for (int kt = 0; kt < KT; kt++) {
        cp_wait1();
        __syncthreads();
        if (kt + 2 < KT) { SF_LOAD(kt + 2, (kt + 2) % 3); }
        cp_commit();
        uint32_t boff = (kt % 3) * S_STGB;
        #pragma unroll
        for (int kk = 0; kk < 4; kk++) {
            uint32_t ko = boff + kk * 32;
            uint32_t a0[4], a1[4];
            ldsm4(a0, aLd[0] + ko);
            ldsm4(a1, aLd[1] + ko);
            #pragma unroll
            for (int jj = 0; jj < 4; jj++) {
                uint32_t bb[4];
                ldsm4(bb, bLd[jj] + ko);
                mma16(acc[0][2 * jj],     a0, bb[0], bb[2]);
                mma16(acc[0][2 * jj + 1], a0, bb[1], bb[3]);
                mma16(acc[1][2 * jj],     a1, bb[0], bb[2]);
                mma16(acc[1][2 * jj + 1], a1, bb[1], bb[3]);
            }
        }
    }
    #undef SF_LOAD

    // ======== fused epilogue ========
    int qlen = g_qlen[b], clen = g_clen[b];
    int rbase = wn * 32 + (lane >> 2);
    int cbase = wm * 64 + 2 * (lane & 3);

    float rmax[2][2] = {{-1e30f, -1e30f}, {-1e30f, -1e30f}};
    #pragma unroll
    for (int i = 0; i < 2; i++) {
        #pragma unroll
        for (int h = 0; h < 2; h++) {
            int r = rbase + i * 16 + h * 8;
            float cwv = cw_s[r];
            float* Srow = g_S + ((size_t)b * NN + n0 + r) * MM;
            #pragma unroll
            for (int j = 0; j < 8; j++) {
                int c = cbase + j * 8;
                float s0 = acc[i][j][h * 2]     + cwv + qw_s[c];
                float s1 = acc[i][j][h * 2 + 1] + cwv + qw_s[c + 1];
                *(float2*)(Srow + c) = make_float2(s0, s1);
                if (c < qlen)     rmax[i][h] = fmaxf(rmax[i][h], s0);
                if (c + 1 < qlen) rmax[i][h] = fmaxf(rmax[i][h], s1);
            }
        }
    }
    #pragma unroll
    for (int i = 0; i < 2; i++)
        #pragma unroll
        for (int h = 0; h < 2; h++) {
            #pragma unroll
            for (int o = 1; o <= 2; o <<= 1)
                rmax[i][h] = fmaxf(rmax[i][h], __shfl_xor_sync(0xFFFFFFFFu, rmax[i][h], o));
        }
    if ((lane & 3) == 0) {
        #pragma unroll
        for (int i = 0; i < 2; i++)
            #pragma unroll
            for (int h = 0; h < 2; h++)
                rowred[wm * 128 + rbase + i * 16 + h * 8] = rmax[i][h];
    }
    __syncthreads();
    float frmax[2][2];
    #pragma unroll
    for (int i = 0; i < 2; i++)
        #pragma unroll
        for (int h = 0; h < 2; h++) {
            int r = rbase + i * 16 + h * 8;
            float m = rowred[r];
            #pragma unroll
            for (int q = 1; q < 4; q++) m = fmaxf(m, rowred[q * 128 + r]);
            frmax[i][h] = m;
        }
    __syncthreads();

    float rsum[2][2] = {};
    #pragma unroll
    for (int i = 0; i < 2; i++)
        #pragma unroll
        for (int h = 0; h < 2; h++) {
            int r = rbase + i * 16 + h * 8;
            float cwv = cw_s[r];
            #pragma unroll
            for (int j = 0; j < 8; j++) {
                int c = cbase + j * 8;
                if (c < qlen)     rsum[i][h] += __expf(acc[i][j][h * 2]     + cwv + qw_s[c]     - frmax[i][h]);
                if (c + 1 < qlen) rsum[i][h] += __expf(acc[i][j][h * 2 + 1] + cwv + qw_s[c + 1] - frmax[i][h]);
            }
            #pragma unroll
            for (int o = 1; o <= 2; o <<= 1)
                rsum[i][h] += __shfl_xor_sync(0xFFFFFFFFu, rsum[i][h], o);
        }
    if ((lane & 3) == 0) {
        #pragma unroll
        for (int i = 0; i < 2; i++)
            #pragma unroll
            for (int h = 0; h < 2; h++)
                rowred[wm * 128 + rbase + i * 16 + h * 8] = rsum[i][h];
    }
    __syncthreads();
    float rinv[2][2];
    #pragma unroll
    for (int i = 0; i < 2; i++)
        #pragma unroll
        for (int h = 0; h < 2; h++) {
            int r = rbase + i * 16 + h * 8;
            float t = 0.f;
            #pragma unroll
            for (int q = 0; q < 4; q++) t += rowred[q * 128 + r];
            rinv[i][h] = 1.f / t;
        }

    #pragma unroll
    for (int i = 0; i < 2; i++)
        #pragma unroll
        for (int h = 0; h < 2; h++) {
            int r = rbase + i * 16 + h * 8;
            float cwv = cw_s[r];
            __half* Arow = g_A + ((size_t)b * NN + n0 + r) * MM;
            #pragma unroll
            for (int j = 0; j < 8; j++) {
                int c = cbase + j * 8;
                float e0 = (c < qlen)
                    ? __expf(acc[i][j][h * 2] + cwv + qw_s[c] - frmax[i][h]) * rinv[i][h] : 0.f;
                float e1 = (c + 1 < qlen)
                    ? __expf(acc[i][j][h * 2 + 1] + cwv + qw_s[c + 1] - frmax[i][h]) * rinv[i][h] : 0.f;
                *(__half2*)(Arow + c) = __floats2half2_rn(e0, e1);
            }
        }

    #pragma unroll
    for (int j = 0; j < 8; j++) {
        #pragma unroll
        for (int e2 = 0; e2 < 2; e2++) {
            int c = cbase + j * 8 + e2;
            float cm = -1e30f;
            #pragma unroll
            for (int i = 0; i < 2; i++)
                #pragma unroll
                for (int h = 0; h < 2; h++) {
                    int r = rbase + i * 16 + h * 8;
                    if (n0 + r < clen)
                        cm = fmaxf(cm, acc[i][j][h * 2 + e2] + cw_s[r] + qw_s[c]);
                }
            #pragma unroll
            for (int o = 4; o <= 16; o <<= 1)
                cm = fmaxf(cm, __shfl_xor_sync(0xFFFFFFFFu, cm, o));
            if ((lane >> 2) == 0) colred[wn * 256 + c] = cm;
        }
    }
    __syncthreads();

    #pragma unroll
    for (int j = 0; j < 8; j++) {
        #pragma unroll
        for (int e2 = 0; e2 < 2; e2++) {
            int c = cbase + j * 8 + e2;
            float fc = colred[c];
            #pragma unroll
            for (int q = 1; q < 4; q++) fc = fmaxf(fc, colred[q * 256 + c]);
            float cs = 0.f;
            #pragma unroll
            for (int i = 0; i < 2; i++)
                #pragma unroll
                for (int h = 0; h < 2; h++) {
                    int r = rbase + i * 16 + h * 8;
                    if (n0 + r < clen)
                        cs += __expf(acc[i][j][h * 2 + e2] + cw_s[r] + qw_s[c] - fc);
                }
            #pragma unroll
            for (int o = 4; o <= 16; o <<= 1)
                cs += __shfl_xor_sync(0xFFFFFFFFu, cs, o);
            if ((lane >> 2) == 0) colred2[wn * 256 + c] = cs;
        }
    }
    __syncthreads();

    if (wn == 0 && (lane >> 2) == 0) {
        #pragma unroll
        for (int j = 0; j < 8; j++)
            #pragma unroll
            for (int e2 = 0; e2 < 2; e2++) {
                int c = cbase + j * 8 + e2;
                float fm2 = colred[c], ps = colred2[c];
                #pragma unroll
                for (int q = 1; q < 4; q++) {
                    fm2 = fmaxf(fm2, colred[q * 256 + c]);
                    ps += colred2[q * 256 + c];
                }
                g_pmax[b][blockIdx.x][c] = fm2;
                g_psum[b][blockIdx.x][c] = ps;
            }
    }
}

// -------------------- k_bm2: combine partials, write Bm (fp16) -------------------
__global__ void __launch_bounds__(256) k_bm2() {
    int b = blockIdx.z, ns = blockIdx.y;
    int lane = threadIdx.x & 31, p = threadIdx.x >> 5;
    int m = blockIdx.x * 32 + lane;
    int clen = g_clen[b];

    __shared__ float fmv[32], invv[32];
    if (threadIdx.x < 32) {
        float fm = -1e30f;
        #pragma unroll
        for (int q = 0; q < NSPLIT; q++) fm = fmaxf(fm, g_pmax[b][q][m]);
        float fs = 0.f;
        #pragma unroll
        for (int q = 0; q < NSPLIT; q++) {
            float pm = g_pmax[b][q][m];
            if (pm > -1e29f) fs += g_psum[b][q][m] * __expf(pm - fm);
        }
        fmv[threadIdx.x] = fm;
        invv[threadIdx.x] = 1.f / fs;
    }
    __syncthreads();

    float fm = fmv[lane], inv = invv[lane];
    const float* Sc = g_S   + (size_t)b * NN * MM + m;
    __half*      Bc = g_Bmh + (size_t)b * NN * MM + m;
    #pragma unroll
    for (int it = 0; it < 16; it++) {
        int n = ns * 128 + p + it * 8;
        float v = (n < clen) ? __expf(Sc[(size_t)n * MM] - fm) * inv : 0.f;
        Bc[(size_t)n * MM] = __float2half_rn(v);
    }
}

// ============ k_mid_f: midT[d][m] = (Bm^T @ ctx)^T, fp16 MMA (ldmatrix.trans) ====
// 512 thr, 16 warps (wm 4x64m, wd 4x32d), tile 256m x 128d, BK=32(n), 3 stages.
// A tile: Bm [k=32][256m] fp16, row 512B + 16 pad = 528B.
// B tile: ctx [k=32][128d] fp16, row 256B + 16 pad = 272B.
#define M_STGB 25600
#define M_BOFFB 16896
__global__ void __launch_bounds__(512, 1) k_mid_f() {
    extern __shared__ float sm[];
    int b = blockIdx.y, d0 = blockIdx.x * 128;
    int tid = threadIdx.x, lane = tid & 31, warp = tid >> 5;
    int wm = warp & 3, wd = warp >> 2;
    uint32_t smb = s2u(sm);

    const __half* Bmb  = g_Bmh  + (size_t)b * NN * MM;
    const __half* ctxb = g_ctxh + (size_t)b * NN * DD;

    // ldmatrix.trans bases. lr = lane&7, g = lane>>3.
    // A block i (m16): g0=(k0-7, m), g1=(k0-7, m+8), g2=(k8-15, m), g3=(k8-15, m+8)
    // B block j (d16): g0=(k0-7, d), g1=(k8-15, d), g2=(k0-7, d+8), g3=(k8-15, d+8)
    int lr = lane & 7, g = lane >> 3;
    uint32_t aLd[4], bLd[2];
    #pragma unroll
    for (int i = 0; i < 4; i++)
        aLd[i] = smb + (lr + (g >> 1) * 8) * 528 + (wm * 64 + i * 16 + (g & 1) * 8) * 2;
    #pragma unroll
    for (int j = 0; j < 2; j++)
        bLd[j] = smb + M_BOFFB + (lr + (g & 1) * 8) * 272 + (wd * 32 + j * 16 + (g >> 1) * 8) * 2;

    float acc[4][4][4] = {};
    const int KT = NN / 32;  // 32

    #define MF_LOAD(kt, s) do { \
        uint32_t base = smb + (s) * M_STGB; \
        _Pragma("unroll") \
        for (int r2 = 0; r2 < 2; r2++) { \
            int idx = tid + 512 * r2; int row = idx >> 5, c = idx & 31; \
            cp16(base + row * 528 + c * 16, Bmb + (size_t)((kt) * 32 + row) * MM + c * 8); \
        } \
        { \
            int row = tid >> 4, c = tid & 15; \
            cp16(base + M_BOFFB + row * 272 + c * 16, ctxb + (size_t)((kt) * 32 + row) * DD + d0 + c * 8); \
        } \
    } while (0)

    MF_LOAD(0, 0); cp_commit();
    MF_LOAD(1, 1); cp_commit();

    for (int kt = 0; kt < KT; kt++) {
        cp_wait1();
        __syncthreads();
        if (kt + 2 < KT) { MF_LOAD(kt + 2, (kt + 2) % 3); }
        cp_commit();
        uint32_t base = (kt % 3) * M_STGB;
        #pragma unroll
        for (int step = 0; step < 2; step++) {
            uint32_t koA = base + step * 16 * 528;
            uint32_t koB = base + step * 16 * 272;
            uint32_t a[4][4];
            #pragma unroll
            for (int i = 0; i < 4; i++) ldsm4t(a[i], aLd[i] + koA);
            #pragma unroll
            for (int j = 0; j < 2; j++) {
                uint32_t bb[4];
                ldsm4t(bb, bLd[j] + koB);
                #pragma unroll
                for (int i = 0; i < 4; i++) {
                    mma16(acc[i][j * 2],     a[i], bb[0], bb[1]);
                    mma16(acc[i][j * 2 + 1], a[i], bb[2], bb[3]);
                }
            }
        }
    }
    #undef MF_LOAD

    // epilogue: stage fp16 [d][m] in smem (stride 264 halfs), coalesced store
    __syncthreads();
    __half* ot = (__half*)sm;
    #pragma unroll
    for (int i = 0; i < 4; i++) {
        int m_r = wm * 64 + i * 16 + (lane >> 2);
        #pragma unroll
        for (int j = 0; j < 4; j++) {
            int c = wd * 32 + j * 8 + 2 * (lane & 3);
            ot[(size_t)c * 264 + m_r]           = __float2half_rn(acc[i][j][0]);
            ot[(size_t)(c + 1) * 264 + m_r]     = __float2half_rn(acc[i][j][1]);
            ot[(size_t)c * 264 + m_r + 8]       = __float2half_rn(acc[i][j][2]);
            ot[(size_t)(c + 1) * 264 + m_r + 8] = __float2half_rn(acc[i][j][3]);
        }
    }
    __syncthreads();
    #pragma unroll
    for (int rep = 0; rep < 8; rep++) {
        int idx = tid + rep * 512;
        int d = idx >> 5, c16 = idx & 31;
        uint4 v = *(uint4*)(ot + (size_t)d * 264 + c16 * 8);
        *(uint4*)(g_midT + ((size_t)b * DD + d0 + d) * MM + c16 * 8) = v;
    }
}

// ============ k_out_f: c2q = A@qT^T, q2c = A@midT^T, fp16 MMA, 128n x 128d =======
#define O_STGB 55296
#define O_QOFFB 18432
#define O_MOFFB 36864
__global__ void __launch_bounds__(512, 1) k_out_f(const float* __restrict__ ctx,
                                                  float* __restrict__ out) {
    extern __shared__ float sm[];
    int b = blockIdx.z, d0 = blockIdx.x * 128, n0 = blockIdx.y * 128;
    int tid = threadIdx.x, lane = tid & 31, warp = tid >> 5;
    int wn = warp & 3, wd = warp >> 2;
    uint32_t smb = s2u(sm);

    const __half* Ab  = g_A    + ((size_t)b * NN + n0) * MM;
    const __half* qTb = g_qT   + ((size_t)b * DD + d0) * MM;
    const __half* mTb = g_midT + ((size_t)b * DD + d0) * MM;

    uint32_t aLd[2], bqLd[2], bmLd[2];
    #pragma unroll
    for (int i = 0; i < 2; i++)
        aLd[i] = smb + (wn * 32 + i * 16 + (lane & 15)) * 144 + (lane >> 4) * 16;
    #pragma unroll
    for (int jj = 0; jj < 2; jj++) {
        bqLd[jj] = smb + O_QOFFB + (wd * 32 + jj * 16 + (lane & 15)) * 144 + (lane >> 4) * 16;
        bmLd[jj] = smb + O_MOFFB + (wd * 32 + jj * 16 + (lane & 15)) * 144 + (lane >> 4) * 16;
    }

    float accq[2][4][4] = {};
    float accm[2][4][4] = {};
    const int KT = MM / 64;  // 4

    #define OF_LOAD(kt, s) do { \
        uint32_t base = smb + (s) * O_STGB; \
        _Pragma("unroll") \
        for (int r2 = 0; r2 < 2; r2++) { \
            int idx = tid + 512 * r2; int row = idx >> 3, c = idx & 7; \
            uint32_t o = row * 144 + c * 16; \
            cp16(base + o,           Ab  + (size_t)row * MM + (kt) * 64 + c * 8); \
            cp16(base + O_QOFFB + o, qTb + (size_t)row * MM + (kt) * 64 + c * 8); \
            cp16(base + O_MOFFB + o, mTb + (size_t)row * MM + (kt) * 64 + c * 8); \
        } \
    } while (0)

    OF_LOAD(0, 0); cp_commit();
    OF_LOAD(1, 1); cp_commit();

    for (int kt = 0; kt < KT; kt++) {
        cp_wait1();
        __syncthreads();
        if (kt + 2 < KT) { OF_LOAD(kt + 2, (kt + 2) % 3); }
        cp_commit();
        uint32_t boff = (kt % 3) * O_STGB;
        #pragma unroll
        for (int kk = 0; kk < 4; kk++) {
            uint32_t ko = boff + kk * 32;
            uint32_t a0[4], a1[4];
            ldsm4(a0, aLd[0] + ko);
            ldsm4(a1, aLd[1] + ko);
            #pragma unroll
            for (int jj = 0; jj < 2; jj++) {
                uint32_t bq[4], bm[4];
                ldsm4(bq, bqLd[jj] + ko);
                mma16(accq[0][jj * 2],     a0, bq[0], bq[2]);
                mma16(accq[0][jj * 2 + 1], a0, bq[1], bq[3]);
                mma16(accq[1][jj * 2],     a1, bq[0], bq[2]);
                mma16(accq[1][jj * 2 + 1], a1, bq[1], bq[3]);
                ldsm4(bm, bmLd[jj] + ko);
                mma16(accm[0][jj * 2],     a0, bm[0], bm[2]);
                mma16(accm[0][jj * 2 + 1], a0, bm[1], bm[3]);
                mma16(accm[1][jj * 2],     a1, bm[0], bm[2]);
                mma16(accm[1][jj * 2 + 1], a1, bm[1], bm[3]);
            }
        }
    }
    #undef OF_LOAD

    // epilogue: out = [ctx, c2q, ctx*c2q, ctx*q2c]
    #pragma unroll
    for (int i = 0; i < 2; i++) {
        #pragma unroll
        for (int half = 0; half < 2; half++) {
            int n = n0 + wn * 32 + i * 16 + (lane >> 2) + half * 8;
            const float* crow = ctx + ((size_t)b * NN + n) * DD;
            float* orow = out + ((size_t)b * NN + n) * (4 * DD);
            #pragma unroll
            for (int jj = 0; jj < 2; jj++) {
                #pragma unroll
                for (int hc = 0; hc < 2; hc++) {
                    int d = d0 + wd * 32 + jj * 16 + hc * 8 + 2 * (lane & 3);
                    int ai = jj * 2 + hc;
                    float2 cv = *(const float2*)(crow + d);
                    float c2q0 = accq[i][ai][half * 2], c2q1 = accq[i][ai][half * 2 + 1];
                    float q2c0 = accm[i][ai][half * 2], q2c1 = accm[i][ai][half * 2 + 1];
                    *(float2*)(orow + d)          = cv;
                    *(float2*)(orow + DD + d)     = make_float2(c2q0, c2q1);
                    *(float2*)(orow + 2 * DD + d) = make_float2(cv.x * c2q0, cv.y * c2q1);
                    *(float2*)(orow + 3 * DD + d) = make_float2(cv.x * q2c0, cv.y * q2c1);
                }
            }
        }
    }
}

// -------------------- launch --------------------
extern "C" void kernel_launch(void* const* d_in, const int* in_sizes, int n_in,
                              void* d_out, int out_size) {
    const float* ctx = (const float*)d_in[0];
    const float* qry = (const float*)d_in[1];
    const unsigned char* cm = (const unsigned char*)d_in[2];
    const unsigned char* qm = (const unsigned char*)d_in[3];
    const float* w = (const float*)d_in[4];
    float* out = (float*)d_out;

    const int SMEM_S   = 3 * S_STGB + 2944 * 4;  // 177664
    const int SMEM_MID = 3 * M_STGB;             // 76800
    const int SMEM_OUT = 3 * O_STGB;             // 165888

    cudaFuncSetAttribute(k_S_f,   cudaFuncAttributeMaxDynamicSharedMemorySize, SMEM_S);
    cudaFuncSetAttribute(k_mid_f, cudaFuncAttributeMaxDynamicSharedMemorySize, SMEM_MID);
    cudaFuncSetAttribute(k_out_f, cudaFuncAttributeMaxDynamicSharedMemorySize, SMEM_OUT);

    k_lens<<<1, 64>>>(cm, qm);
    k_rowdots<<<(BB * NN + BB * MM) / 8, 256>>>(ctx, qry, w);
    k_scale<<<(BB * MM * DD) / (4 * 256), 256>>>(qry, w);
    k_tq<<<dim3(MM / 32, DD / 32, BB), dim3(32, 8)>>>(qry);
    k_S_f<<<dim3(NN / 128, BB), 512, SMEM_S>>>(ctx);
    k_bm2<<<dim3(MM / 32, NSPLIT, BB), 256>>>();
    k_mid_f<<<dim3(DD / 128, BB), 512, SMEM_MID>>>();
    k_out_f<<<dim3(DD / 128, NN / 128, BB), 512, SMEM_OUT>>>(ctx, out);
}

// round 10
// speedup vs baseline: 3.0214x; 1.0273x over previous
#include <cuda_runtime.h>
#include <cuda_fp16.h>
#include <cstdint>
#include <cstddef>

#define BB 32
#define NN 1024
#define MM 256
#define DD 512
#define NSPLIT 8

// -------------------- device scratch --------------------
__device__ __align__(128) __half g_E  [(size_t)BB * NN * MM];   // exp(S - colmax_blk) fp16
__device__ __align__(128) __half g_A  [(size_t)BB * NN * MM];
__device__ __align__(128) __half g_Bmh[(size_t)BB * NN * MM];   // Bm fp16 [n][m]
__device__ __align__(128) __half g_midT[(size_t)BB * DD * MM];  // mid^T [d][m] fp16
__device__ __align__(128) __half g_qs [(size_t)BB * MM * DD];   // (query*w_m) fp16
__device__ __align__(128) __half g_qT [(size_t)BB * DD * MM];   // query^T [d][m] fp16
__device__ __align__(128) __half g_ctxh[(size_t)BB * NN * DD];  // ctx fp16
__device__ float g_pmax[BB][NSPLIT][MM];
__device__ float g_psum[BB][NSPLIT][MM];
__device__ float g_cw[BB * NN];
__device__ float g_qw[BB * MM];
__device__ int   g_clen[BB];
__device__ int   g_qlen[BB];

// -------------------- helpers --------------------
__device__ __forceinline__ void mma16(float* c, const uint32_t* a, uint32_t b0, uint32_t b1) {
    asm volatile(
        "mma.sync.aligned.m16n8k16.row.col.f32.f16.f16.f32 "
        "{%0,%1,%2,%3}, {%4,%5,%6,%7}, {%8,%9}, {%0,%1,%2,%3};"
        : "+f"(c[0]), "+f"(c[1]), "+f"(c[2]), "+f"(c[3])
        : "r"(a[0]), "r"(a[1]), "r"(a[2]), "r"(a[3]), "r"(b0), "r"(b1));
}

__device__ __forceinline__ void ldsm4(uint32_t* r, uint32_t addr) {
    asm volatile("ldmatrix.sync.aligned.m8n8.x4.shared.b16 {%0,%1,%2,%3}, [%4];"
                 : "=r"(r[0]), "=r"(r[1]), "=r"(r[2]), "=r"(r[3]) : "r"(addr));
}
__device__ __forceinline__ void ldsm4t(uint32_t* r, uint32_t addr) {
    asm volatile("ldmatrix.sync.aligned.m8n8.x4.trans.shared.b16 {%0,%1,%2,%3}, [%4];"
                 : "=r"(r[0]), "=r"(r[1]), "=r"(r[2]), "=r"(r[3]) : "r"(addr));
}

__device__ __forceinline__ uint32_t s2u(const void* p) {
    return (uint32_t)__cvta_generic_to_shared(p);
}
__device__ __forceinline__ void cp16(uint32_t dst, const void* src) {
    asm volatile("cp.async.cg.shared.global [%0], [%1], 16;" :: "r"(dst), "l"(src));
}
__device__ __forceinline__ void cp_commit() { asm volatile("cp.async.commit_group;"); }
__device__ __forceinline__ void cp_wait1()  { asm volatile("cp.async.wait_group 1;"); }

// -------------------- mask length detection --------------------
__device__ __forceinline__ int count_prefix(const unsigned char* p, int length,
                                            int esize, unsigned val) {
    int c = 0;
    for (int i = 0; i < length; i++) {
        unsigned v;
        if (esize == 1)      v = p[i];
        else if (esize == 2) v = ((const unsigned short*)p)[i];
        else                 v = ((const unsigned*)p)[i];
        if (v != val) break;
        c++;
    }
    return c;
}

__device__ void detect_fmt(const unsigned char* p, int length, int minlen,
                           int* esize, unsigned* val) {
    const int es[4]      = {1, 2, 4, 4};
    const unsigned vv[4] = {1u, 0x3F80u, 1u, 0x3F800000u};
    for (int k = 0; k < 4; k++) {
        if (count_prefix(p, length, es[k], vv[k]) >= minlen) {
            *esize = es[k]; *val = vv[k]; return;
        }
    }
    *esize = 4; *val = 1u;
}

__global__ void k_lens(const unsigned char* __restrict__ cm,
                       const unsigned char* __restrict__ qm) {
    __shared__ int es_c, es_q;
    __shared__ unsigned v_c, v_q;
    int t = threadIdx.x;
    if (t == 0) detect_fmt(cm, NN, NN / 4, &es_c, &v_c);
    if (t == 1) detect_fmt(qm, MM, MM / 4, &es_q, &v_q);
    __syncthreads();
    if (t < BB) {
        g_clen[t] = count_prefix(cm + (size_t)t * NN * es_c, NN, es_c, v_c);
    } else if (t < 2 * BB) {
        int b = t - BB;
        g_qlen[b] = count_prefix(qm + (size_t)b * MM * es_q, MM, es_q, v_q);
    }
}

// ------------- cw = ctx @ w_c (also emits ctx fp16), qw = query @ w_q ------------
__global__ void __launch_bounds__(256) k_rowdots(const float* __restrict__ ctx,
                                                 const float* __restrict__ qry,
                                                 const float* __restrict__ w) {
    int warp = threadIdx.x >> 5, lane = threadIdx.x & 31;
    int row = blockIdx.x * 8 + warp;
    if (row < BB * NN) {
        const float* src = ctx + (size_t)row * DD;
        const float* wp  = w + DD;
        __half* hdst = g_ctxh + (size_t)row * DD;
        float s = 0.f;
        #pragma unroll
        for (int d = lane * 4; d < DD; d += 128) {
            float4 v  = *(const float4*)(src + d);
            float4 wv = *(const float4*)(wp + d);
            s += v.x * wv.x + v.y * wv.y + v.z * wv.z + v.w * wv.w;
            __half2* hp = (__half2*)(hdst + d);
            hp[0] = __floats2half2_rn(v.x, v.y);
            hp[1] = __floats2half2_rn(v.z, v.w);
        }
        #pragma unroll
        for (int o = 16; o; o >>= 1) s += __shfl_xor_sync(0xFFFFFFFFu, s, o);
        if (lane == 0) g_cw[row] = s;
    } else {
        int r = row - BB * NN;
        const float* src = qry + (size_t)r * DD;
        float s = 0.f;
        #pragma unroll
        for (int d = lane * 4; d < DD; d += 128) {
            float4 v  = *(const float4*)(src + d);
            float4 wv = *(const float4*)(w + d);
            s += v.x * wv.x + v.y * wv.y + v.z * wv.z + v.w * wv.w;
        }
        #pragma unroll
        for (int o = 16; o; o >>= 1) s += __shfl_xor_sync(0xFFFFFFFFu, s, o);
        if (lane == 0) g_qw[r] = s;
    }
}

// ----- k_q: one pass over qry -> qT[d][m] fp16 (transposed) + qs[m][d] fp16 ------
__global__ void k_q(const float* __restrict__ qry, const float* __restrict__ w) {
    __shared__ float t[32][33];
    int b = blockIdx.z, m0 = blockIdx.x * 32, d0 = blockIdx.y * 32;
    int tx = threadIdx.x, ty = threadIdx.y;
    const float* src = qry + ((size_t)b * MM + m0) * DD + d0;
    float wmv = w[2 * DD + d0 + tx];
    #pragma unroll
    for (int i = 0; i < 4; i++) {
        float v = src[(size_t)(ty + 8 * i) * DD + tx];
        t[ty + 8 * i][tx] = v;
        g_qs[((size_t)b * MM + m0 + ty + 8 * i) * DD + d0 + tx] = __float2half_rn(v * wmv);
    }
    __syncthreads();
    __half* dst = g_qT + ((size_t)b * DD + d0) * MM + m0;
    #pragma unroll
    for (int i = 0; i < 4; i++)
        dst[(size_t)(ty + 8 * i) * MM + tx] = __float2half_rn(t[tx][ty + 8 * i]);
}

// ============ k_S_f: S = ctx.qs^T (128n x 256m) fp16 MMA, fused softmax ==========
// Writes E = exp(S - colmax_blk) fp16 instead of S fp32, A fp16, col partials.
#define S_STGB 55296
#define S_BOFFB 18432
#define S_REDF (3 * S_STGB / 4)
__global__ void __launch_bounds__(512, 1) k_S_f() {
    extern __shared__ float sm[];
    float* rowred  = sm + S_REDF;
    float* colred  = rowred + 512;
    float* colred2 = colred + 1024;
    float* cw_s    = colred2 + 1024;
    float* qw_s    = cw_s + 128;

    int b = blockIdx.y, n0 = blockIdx.x * 128;
    int tid = threadIdx.x, lane = tid & 31, warp = tid >> 5;
    int wn = warp & 3, wm = warp >> 2;
    uint32_t smb = s2u(sm);

    if (tid < 128) cw_s[tid] = g_cw[b * NN + n0 + tid];
    else if (tid < 384) qw_s[tid - 128] = g_qw[b * MM + (tid - 128)];

    const __half* ctxb = g_ctxh + ((size_t)b * NN + n0) * DD;
    const __half* qsb  = g_qs   + (size_t)b * MM * DD;

    uint32_t aLd[2], bLd[4];
    #pragma unroll
    for (int i = 0; i < 2; i++)
        aLd[i] = smb + (wn * 32 + i * 16 + (lane & 15)) * 144 + (lane >> 4) * 16;
    #pragma unroll
    for (int jj = 0; jj < 4; jj++)
        bLd[jj] = smb + S_BOFFB + (wm * 64 + jj * 16 + (lane & 15)) * 144 + (lane >> 4) * 16;

    float acc[2][8][4] = {};
    const int KT = DD / 64;  // 8

    #define SF_LOAD(kt, s) do { \
        uint32_t base = smb + (s) * S_STGB; \
        _Pragma("unroll") \
        for (int r2 = 0; r2 < 2; r2++) { \
            int idx = tid + 512 * r2; int row = idx >> 3, c = idx & 7; \
            cp16(base + row * 144 + c * 16, ctxb + (size_t)row * DD + (kt) * 64 + c * 8); \
        } \
        _Pragma("unroll") \
        for (int r2 = 0; r2 < 4; r2++) { \
            int idx = tid + 512 * r2; int row = idx >> 3, c = idx & 7; \
            cp16(base + S_BOFFB + row * 144 + c * 16, qsb + (size_t)row * DD + (kt) * 64 + c * 8); \
        } \
    } while (0)

    SF_LOAD(0, 0); cp_commit();
    SF_LOAD(1, 1); cp_commit();

    for (int kt = 0; kt < KT; kt++) {
        cp_wait1();
        __syncthreads();
        if (kt + 2 < KT) { SF_LOAD(kt + 2, (kt + 2) % 3); }
        cp_commit();
        uint32_t boff = (kt % 3) * S_STGB;
        #pragma unroll
        for (int kk = 0; kk < 4; kk++) {
            uint32_t ko = boff + kk * 32;
            uint32_t a0[4], a1[4];
            ldsm4(a0, aLd[0] + ko);
            ldsm4(a1, aLd[1] + ko);
            #pragma unroll
            for (int jj = 0; jj < 4; jj++) {
                uint32_t bb[4];
                ldsm4(bb, bLd[jj] + ko);
                mma16(acc[0][2 * jj],     a0, bb[0], bb[2]);
                mma16(acc[0][2 * jj + 1], a0, bb[1], bb[3]);
                mma16(acc[1][2 * jj],     a1, bb[0], bb[2]);
                mma16(acc[1][2 * jj + 1], a1, bb[1], bb[3]);
            }
        }
    }
    #undef SF_LOAD

    // ======== fused epilogue ========
    int qlen = g_qlen[b], clen = g_clen[b];
    int rbase = wn * 32 + (lane >> 2);
    int cbase = wm * 64 + 2 * (lane & 3);

    // -- col pass 1: per-warp-group column max over this block's valid rows --
    #pragma unroll
    for (int j = 0; j < 8; j++) {
        #pragma unroll
        for (int e2 = 0; e2 < 2; e2++) {
            int c = cbase + j * 8 + e2;
            float cm = -1e30f;
            #pragma unroll
            for (int i = 0; i < 2; i++)
                #pragma unroll
                for (int h = 0; h < 2; h++) {
                    int r = rbase + i * 16 + h * 8;
                    if (n0 + r < clen)
                        cm = fmaxf(cm, acc[i][j][h * 2 + e2] + cw_s[r] + qw_s[c]);
                }
            #pragma unroll
            for (int o = 4; o <= 16; o <<= 1)
                cm = fmaxf(cm, __shfl_xor_sync(0xFFFFFFFFu, cm, o));
            if ((lane >> 2) == 0) colred[wn * 256 + c] = cm;
        }
    }
    __syncthreads();

    // -- col pass 2: final block colmax fc, write E = exp(s - fc), col sums --
    #pragma unroll
    for (int j = 0; j < 8; j++) {
        int c = cbase + j * 8;
        float fc0 = colred[c],     fc1 = colred[c + 1];
        #pragma unroll
        for (int q = 1; q < 4; q++) {
            fc0 = fmaxf(fc0, colred[q * 256 + c]);
            fc1 = fmaxf(fc1, colred[q * 256 + c + 1]);
        }
        float cs0 = 0.f, cs1 = 0.f;
        #pragma unroll
        for (int i = 0; i < 2; i++)
            #pragma unroll
            for (int h = 0; h < 2; h++) {
                int r = rbase + i * 16 + h * 8;
                float cwv = cw_s[r];
                float e0 = __expf(fminf(acc[i][j][h * 2]     + cwv + qw_s[c]     - fc0, 11.f));
                float e1 = __expf(fminf(acc[i][j][h * 2 + 1] + cwv + qw_s[c + 1] - fc1, 11.f));
                __half* Erow = g_E + ((size_t)b * NN + n0 + r) * MM;
                *(__half2*)(Erow + c) = __floats2half2_rn(e0, e1);
                if (n0 + r < clen) { cs0 += e0; cs1 += e1; }
            }
        #pragma unroll
        for (int o = 4; o <= 16; o <<= 1) {
            cs0 += __shfl_xor_sync(0xFFFFFFFFu, cs0, o);
            cs1 += __shfl_xor_sync(0xFFFFFFFFu, cs1, o);
        }
        if ((lane >> 2) == 0) {
            colred2[wn * 256 + c]     = cs0;
            colred2[wn * 256 + c + 1] = cs1;
        }
    }
    __syncthreads();

    if (wn == 0 && (lane >> 2) == 0) {
        #pragma unroll
        for (int j = 0; j < 8; j++)
            #pragma unroll
            for (int e2 = 0; e2 < 2; e2++) {
                int c = cbase + j * 8 + e2;
                float fm2 = colred[c], ps = colred2[c];
                #pragma unroll
                for (int q = 1; q < 4; q++) {
                    fm2 = fmaxf(fm2, colred[q * 256 + c]);
                    ps += colred2[q * 256 + c];
                }
                g_pmax[b][blockIdx.x][c] = fm2;
                g_psum[b][blockIdx.x][c] = ps;
            }
    }

    // -- row softmax (register-resident) --
    float rmax[2][2] = {{-1e30f, -1e30f}, {-1e30f, -1e30f}};
    #pragma unroll
    for (int i = 0; i < 2; i++)
        #pragma unroll
        for (int h = 0; h < 2; h++) {
            int r = rbase + i * 16 + h * 8;
            float cwv = cw_s[r];
            #pragma unroll
            for (int j = 0; j < 8; j++) {
                int c = cbase + j * 8;
                if (c < qlen)     rmax[i][h] = fmaxf(rmax[i][h], acc[i][j][h * 2]     + cwv + qw_s[c]);
                if (c + 1 < qlen) rmax[i][h] = fmaxf(rmax[i][h], acc[i][j][h * 2 + 1] + cwv + qw_s[c + 1]);
            }
            #pragma unroll
            for (int o = 1; o <= 2; o <<= 1)
                rmax[i][h] = fmaxf(rmax[i][h], __shfl_xor_sync(0xFFFFFFFFu, rmax[i][h], o));
        }
    if ((lane & 3) == 0) {
        #pragma unroll
        for (int i = 0; i < 2; i++)
            #pragma unroll
            for (int h = 0; h < 2; h++)
                rowred[wm * 128 + rbase + i * 16 + h * 8] = rmax[i][h];
    }
    __syncthreads();
    float frmax[2][2];
    #pragma unroll
    for (int i = 0; i < 2; i++)
        #pragma unroll
        for (int h = 0; h < 2; h++) {
            int r = rbase + i * 16 + h * 8;
            float m = rowred[r];
            #pragma unroll
            for (int q = 1; q < 4; q++) m = fmaxf(m, rowred[q * 128 + r]);
            frmax[i][h] = m;
        }
    __syncthreads();

    float rsum[2][2] = {};
    #pragma unroll
    for (int i = 0; i < 2; i++)
        #pragma unroll
        for (int h = 0; h < 2; h++) {
            int r = rbase + i * 16 + h * 8;
            float cwv = cw_s[r];
            #pragma unroll
            for (int j = 0; j < 8; j++) {
                int c = cbase + j * 8;
                if (c < qlen)     rsum[i][h] += __expf(acc[i][j][h * 2]     + cwv + qw_s[c]     - frmax[i][h]);
                if (c + 1 < qlen) rsum[i][h] += __expf(acc[i][j][h * 2 + 1] + cwv + qw_s[c + 1] - frmax[i][h]);
            }
            #pragma unroll
            for (int o = 1; o <= 2; o <<= 1)
                rsum[i][h] += __shfl_xor_sync(0xFFFFFFFFu, rsum[i][h], o);
        }
    if ((lane & 3) == 0) {
        #pragma unroll
        for (int i = 0; i < 2; i++)
            #pragma unroll
            for (int h = 0; h < 2; h++)
                rowred[wm * 128 + rbase + i * 16 + h * 8] = rsum[i][h];
    }
    __syncthreads();
    float rinv[2][2];
    #pragma unroll
    for (int i = 0; i < 2; i++)
        #pragma unroll
        for (int h = 0; h < 2; h++) {
            int r = rbase + i * 16 + h * 8;
            float t = 0.f;
            #pragma unroll
            for (int q = 0; q < 4; q++) t += rowred[q * 128 + r];
            rinv[i][h] = 1.f / t;
        }

    #pragma unroll
    for (int i = 0; i < 2; i++)
        #pragma unroll
        for (int h = 0; h < 2; h++) {
            int r = rbase + i * 16 + h * 8;
            float cwv = cw_s[r];
            __half* Arow = g_A + ((size_t)b * NN + n0 + r) * MM;
            #pragma unroll
            for (int j = 0; j < 8; j++) {
                int c = cbase + j * 8;
                float e0 = (c < qlen)
                    ? __expf(acc[i][j][h * 2] + cwv + qw_s[c] - frmax[i][h]) * rinv[i][h] : 0.f;
                float e1 = (c + 1 < qlen)
                    ? __expf(acc[i][j][h * 2 + 1] + cwv + qw_s[c + 1] - frmax[i][h]) * rinv[i][h] : 0.f;
                *(__half2*)(Arow + c) = __floats2half2_rn(e0, e1);
            }
        }
}

// ------- k_bm2: Bm = E * exp(pmax_blk - fm) * inv, fp16 in / fp16 out ------------
__global__ void __launch_bounds__(256) k_bm2() {
    int b = blockIdx.z, ns = blockIdx.y;
    int lane = threadIdx.x & 31, p = threadIdx.x >> 5;
    int m = blockIdx.x * 32 + lane;
    int clen = g_clen[b];

    __shared__ float scv[32];
    if (threadIdx.x < 32) {
        float fm = -1e30f;
        #pragma unroll
        for (int q = 0; q < NSPLIT; q++) fm = fmaxf(fm, g_pmax[b][q][m]);
        float fs = 0.f;
        #pragma unroll
        for (int q = 0; q < NSPLIT; q++) {
            float pm = g_pmax[b][q][m];
            if (pm > -1e29f) fs += g_psum[b][q][m] * __expf(pm - fm);
        }
        float pmn = g_pmax[b][ns][m];
        scv[threadIdx.x] = (pmn > -1e29f) ? __expf(pmn - fm) / fs : 0.f;
    }
    __syncthreads();

    float sc = scv[lane];
    const __half* Ec = g_E   + (size_t)b * NN * MM + m;
    __half*       Bc = g_Bmh + (size_t)b * NN * MM + m;
    #pragma unroll
    for (int it = 0; it < 16; it++) {
        int n = ns * 128 + p + it * 8;
        float v = (n < clen) ? __half2float(Ec[(size_t)n * MM]) * sc : 0.f;
        Bc[(size_t)n * MM] = __float2half_rn(v);
    }
}

// ============ k_mid_f: midT[d][m] = (Bm^T @ ctx)^T, fp16 MMA (ldmatrix.trans) ====
#define M_STGB 25600
#define M_BOFFB 16896
__global__ void __launch_bounds__(512, 1) k_mid_f() {
    extern __shared__ float sm[];
    int b = blockIdx.y, d0 = blockIdx.x * 128;
    int tid = threadIdx.x, lane = tid & 31, warp = tid >> 5;
    int wm = warp & 3, wd = warp >> 2;
    uint32_t smb = s2u(sm);

    const __half* Bmb  = g_Bmh  + (size_t)b * NN * MM;
    const __half* ctxb = g_ctxh + (size_t)b * NN * DD;

    int lr = lane & 7, g = lane >> 3;
    uint32_t aLd[4], bLd[2];
    #pragma unroll
    for (int i = 0; i < 4; i++)
        aLd[i] = smb + (lr + (g >> 1) * 8) * 528 + (wm * 64 + i * 16 + (g & 1) * 8) * 2;
    #pragma unroll
    for (int j = 0; j < 2; j++)
        bLd[j] = smb + M_BOFFB + (lr + (g & 1) * 8) * 272 + (wd * 32 + j * 16 + (g >> 1) * 8) * 2;

    float acc[4][4][4] = {};
    const int KT = NN / 32;  // 32

    #define MF_LOAD(kt, s) do { \
        uint32_t base = smb + (s) * M_STGB; \
        _Pragma("unroll") \
        for (int r2 = 0; r2 < 2; r2++) { \
            int idx = tid + 512 * r2; int row = idx >> 5, c = idx & 31; \
            cp16(base + row * 528 + c * 16, Bmb + (size_t)((kt) * 32 + row) * MM + c * 8); \
        } \
        { \
            int row = tid >> 4, c = tid & 15; \
            cp16(base + M_BOFFB + row * 272 + c * 16, ctxb + (size_t)((kt) * 32 + row) * DD + d0 + c * 8); \
        } \
    } while (0)

    MF_LOAD(0, 0); cp_commit();
    MF_LOAD(1, 1); cp_commit();

    for (int kt = 0; kt < KT; kt++) {
        cp_wait1();
        __syncthreads();
        if (kt + 2 < KT) { MF_LOAD(kt + 2, (kt + 2) % 3); }
        cp_commit();
        uint32_t base = (kt % 3) * M_STGB;
        #pragma unroll
        for (int step = 0; step < 2; step++) {
            uint32_t koA = base + step * 16 * 528;
            uint32_t koB = base + step * 16 * 272;
            uint32_t a[4][4];
            #pragma unroll
            for (int i = 0; i < 4; i++) ldsm4t(a[i], aLd[i] + koA);
            #pragma unroll
            for (int j = 0; j < 2; j++) {
                uint32_t bb[4];
                ldsm4t(bb, bLd[j] + koB);
                #pragma unroll
                for (int i = 0; i < 4; i++) {
                    mma16(acc[i][j * 2],     a[i], bb[0], bb[1]);
                    mma16(acc[i][j * 2 + 1], a[i], bb[2], bb[3]);
                }
            }
        }
    }
    #undef MF_LOAD

    __syncthreads();
    __half* ot = (__half*)sm;
    #pragma unroll
    for (int i = 0; i < 4; i++) {
        int m_r = wm * 64 + i * 16 + (lane >> 2);
        #pragma unroll
        for (int j = 0; j < 4; j++) {
            int c = wd * 32 + j * 8 + 2 * (lane & 3);
            ot[(size_t)c * 264 + m_r]           = __float2half_rn(acc[i][j][0]);
            ot[(size_t)(c + 1) * 264 + m_r]     = __float2half_rn(acc[i][j][1]);
            ot[(size_t)c * 264 + m_r + 8]       = __float2half_rn(acc[i][j][2]);
            ot[(size_t)(c + 1) * 264 + m_r + 8] = __float2half_rn(acc[i][j][3]);
        }
    }
    __syncthreads();
    #pragma unroll
    for (int rep = 0; rep < 8; rep++) {
        int idx = tid + rep * 512;
        int d = idx >> 5, c16 = idx & 31;
        uint4 v = *(uint4*)(ot + (size_t)d * 264 + c16 * 8);
        *(uint4*)(g_midT + ((size_t)b * DD + d0 + d) * MM + c16 * 8) = v;
    }
}

// ============ k_out_f: c2q = A@qT^T, q2c = A@midT^T, fp16 MMA, 128n x 128d =======
#define O_STGB 55296
#define O_QOFFB 18432
#define O_MOFFB 36864
__global__ void __launch_bounds__(512, 1) k_out_f(const float* __restrict__ ctx,
                                                  float* __restrict__ out) {
    extern __shared__ float sm[];
    int b = blockIdx.z, d0 = blockIdx.x * 128, n0 = blockIdx.y * 128;
    int tid = threadIdx.x, lane = tid & 31, warp = tid >> 5;
    int wn = warp & 3, wd = warp >> 2;
    uint32_t smb = s2u(sm);

    const __half* Ab  = g_A    + ((size_t)b * NN + n0) * MM;
    const __half* qTb = g_qT   + ((size_t)b * DD + d0) * MM;
    const __half* mTb = g_midT + ((size_t)b * DD + d0) * MM;

    uint32_t aLd[2], bqLd[2], bmLd[2];
    #pragma unroll
    for (int i = 0; i < 2; i++)
        aLd[i] = smb + (wn * 32 + i * 16 + (lane & 15)) * 144 + (lane >> 4) * 16;
    #pragma unroll
    for (int jj = 0; jj < 2; jj++) {
        bqLd[jj] = smb + O_QOFFB + (wd * 32 + jj * 16 + (lane & 15)) * 144 + (lane >> 4) * 16;
        bmLd[jj] = smb + O_MOFFB + (wd * 32 + jj * 16 + (lane & 15)) * 144 + (lane >> 4) * 16;
    }

    float accq[2][4][4] = {};
    float accm[2][4][4] = {};
    const int KT = MM / 64;  // 4

    #define OF_LOAD(kt, s) do { \
        uint32_t base = smb + (s) * O_STGB; \
        _Pragma("unroll") \
        for (int r2 = 0; r2 < 2; r2++) { \
            int idx = tid + 512 * r2; int row = idx >> 3, c = idx & 7; \
            uint32_t o = row * 144 + c * 16; \
            cp16(base + o,           Ab  + (size_t)row * MM + (kt) * 64 + c * 8); \
            cp16(base + O_QOFFB + o, qTb + (size_t)row * MM + (kt) * 64 + c * 8); \
            cp16(base + O_MOFFB + o, mTb + (size_t)row * MM + (kt) * 64 + c * 8); \
        } \
    } while (0)

    OF_LOAD(0, 0); cp_commit();
    OF_LOAD(1, 1); cp_commit();

    for (int kt = 0; kt < KT; kt++) {
        cp_wait1();
        __syncthreads();
        if (kt + 2 < KT) { OF_LOAD(kt + 2, (kt + 2) % 3); }
        cp_commit();
        uint32_t boff = (kt % 3) * O_STGB;
        #pragma unroll
        for (int kk = 0; kk < 4; kk++) {
            uint32_t ko = boff + kk * 32;
            uint32_t a0[4], a1[4];
            ldsm4(a0, aLd[0] + ko);
            ldsm4(a1, aLd[1] + ko);
            #pragma unroll
            for (int jj = 0; jj < 2; jj++) {
                uint32_t bq[4], bm[4];
                ldsm4(bq, bqLd[jj] + ko);
                mma16(accq[0][jj * 2],     a0, bq[0], bq[2]);
                mma16(accq[0][jj * 2 + 1], a0, bq[1], bq[3]);
                mma16(accq[1][jj * 2],     a1, bq[0], bq[2]);
                mma16(accq[1][jj * 2 + 1], a1, bq[1], bq[3]);
                ldsm4(bm, bmLd[jj] + ko);
                mma16(accm[0][jj * 2],     a0, bm[0], bm[2]);
                mma16(accm[0][jj * 2 + 1], a0, bm[1], bm[3]);
                mma16(accm[1][jj * 2],     a1, bm[0], bm[2]);
                mma16(accm[1][jj * 2 + 1], a1, bm[1], bm[3]);
            }
        }
    }
    #undef OF_LOAD

    // epilogue: out = [ctx, c2q, ctx*c2q, ctx*q2c]
    #pragma unroll
    for (int i = 0; i < 2; i++) {
        #pragma unroll
        for (int half = 0; half < 2; half++) {
            int n = n0 + wn * 32 + i * 16 + (lane >> 2) + half * 8;
            const float* crow = ctx + ((size_t)b * NN + n) * DD;
            float* orow = out + ((size_t)b * NN + n) * (4 * DD);
            #pragma unroll
            for (int jj = 0; jj < 2; jj++) {
                #pragma unroll
                for (int hc = 0; hc < 2; hc++) {
                    int d = d0 + wd * 32 + jj * 16 + hc * 8 + 2 * (lane & 3);
                    int ai = jj * 2 + hc;
                    float2 cv = *(const float2*)(crow + d);
                    float c2q0 = accq[i][ai][half * 2], c2q1 = accq[i][ai][half * 2 + 1];
                    float q2c0 = accm[i][ai][half * 2], q2c1 = accm[i][ai][half * 2 + 1];
                    *(float2*)(orow + d)          = cv;
                    *(float2*)(orow + DD + d)     = make_float2(c2q0, c2q1);
                    *(float2*)(orow + 2 * DD + d) = make_float2(cv.x * c2q0, cv.y * c2q1);
                    *(float2*)(orow + 3 * DD + d) = make_float2(cv.x * q2c0, cv.y * q2c1);
                }
            }
        }
    }
}

// -------------------- launch --------------------
extern "C" void kernel_launch(void* const* d_in, const int* in_sizes, int n_in,
                              void* d_out, int out_size) {
    const float* ctx = (const float*)d_in[0];
    const float* qry = (const float*)d_in[1];
    const unsigned char* cm = (const unsigned char*)d_in[2];
    const unsigned char* qm = (const unsigned char*)d_in[3];
    const float* w = (const float*)d_in[4];
    float* out = (float*)d_out;

    const int SMEM_S   = 3 * S_STGB + 2944 * 4;  // 177664
    const int SMEM_MID = 3 * M_STGB;             // 76800
    const int SMEM_OUT = 3 * O_STGB;             // 165888

    cudaFuncSetAttribute(k_S_f,   cudaFuncAttributeMaxDynamicSharedMemorySize, SMEM_S);
    cudaFuncSetAttribute(k_mid_f, cudaFuncAttributeMaxDynamicSharedMemorySize, SMEM_MID);
    cudaFuncSetAttribute(k_out_f, cudaFuncAttributeMaxDynamicSharedMemorySize, SMEM_OUT);

    k_lens<<<1, 64>>>(cm, qm);
    k_rowdots<<<(BB * NN + BB * MM) / 8, 256>>>(ctx, qry, w);
    k_q<<<dim3(MM / 32, DD / 32, BB), dim3(32, 8)>>>(qry, w);
    k_S_f<<<dim3(NN / 128, BB), 512, SMEM_S>>>();
    k_bm2<<<dim3(MM / 32, NSPLIT, BB), 256>>>();
    k_mid_f<<<dim3(DD / 128, BB), 512, SMEM_MID>>>();
    k_out_f<<<dim3(DD / 128, NN / 128, BB), 512, SMEM_OUT>>>(ctx, out);
}